// round 1
// baseline (speedup 1.0000x reference)
#include <cuda_runtime.h>
#include <cuda_bf16.h>
#include <math.h>

#define B_SZ     2
#define SEQ      2048
#define D_MODEL  1024
#define D_INNER  2048
#define D_STATE  16
#define DT_RANK  64
#define D_CONV   4
#define NROWS    (B_SZ * SEQ)          // 4096
#define XPROJ_N  (DT_RANK + 2 * D_STATE)  // 96

// ---------------- scratch (static device globals; no allocation allowed) ---
__device__ float g_xz[(size_t)NROWS * (2 * D_INNER)];   // [4096, 4096]
__device__ float g_xconv[(size_t)NROWS * D_INNER];      // [4096, 2048]
__device__ float g_xdbc[(size_t)NROWS * XPROJ_N];       // [4096, 96]
__device__ float g_dt[(size_t)NROWS * D_INNER];         // [4096, 2048]
__device__ float g_y[(size_t)NROWS * D_INNER];          // [4096, 2048]

// ---------------- generic 128x128x8 SGEMM, row-major A[M,K] * B[K,N] -------
// act: 0 = none, 1 = softplus(v + bias)
__global__ __launch_bounds__(256)
void sgemm_kernel(const float* __restrict__ A, const float* __restrict__ B,
                  float* __restrict__ C, int M, int N, int K,
                  int lda, int ldb, int ldc,
                  const float* __restrict__ bias, int act)
{
    __shared__ float As[8][128];
    __shared__ float Bs[8][128];

    const int tid  = threadIdx.x;
    const int row0 = blockIdx.y * 128;
    const int col0 = blockIdx.x * 128;
    const int ty   = tid >> 4;     // 0..15
    const int tx   = tid & 15;     // 0..15

    float acc[8][8];
#pragma unroll
    for (int i = 0; i < 8; i++)
#pragma unroll
        for (int j = 0; j < 8; j++) acc[i][j] = 0.f;

    for (int k0 = 0; k0 < K; k0 += 8) {
        // load A tile (128 x 8) transposed into As[k][m]
#pragma unroll
        for (int i = 0; i < 4; i++) {
            int idx = tid * 4 + i;            // 0..1023
            int m   = idx >> 3;
            int kk  = idx & 7;
            int gr  = row0 + m;
            int gk  = k0 + kk;
            As[kk][m] = (gr < M && gk < K) ? A[(size_t)gr * lda + gk] : 0.f;
        }
        // load B tile (8 x 128)
#pragma unroll
        for (int i = 0; i < 4; i++) {
            int idx = tid * 4 + i;
            int kk  = idx >> 7;
            int n   = idx & 127;
            int gk  = k0 + kk;
            int gc  = col0 + n;
            Bs[kk][n] = (gk < K && gc < N) ? B[(size_t)gk * ldb + gc] : 0.f;
        }
        __syncthreads();

#pragma unroll
        for (int kk = 0; kk < 8; kk++) {
            float ra[8], rb[8];
            // vectorized smem reads
            float4 a0 = *reinterpret_cast<const float4*>(&As[kk][ty * 8]);
            float4 a1 = *reinterpret_cast<const float4*>(&As[kk][ty * 8 + 4]);
            float4 b0 = *reinterpret_cast<const float4*>(&Bs[kk][tx * 8]);
            float4 b1 = *reinterpret_cast<const float4*>(&Bs[kk][tx * 8 + 4]);
            ra[0]=a0.x; ra[1]=a0.y; ra[2]=a0.z; ra[3]=a0.w;
            ra[4]=a1.x; ra[5]=a1.y; ra[6]=a1.z; ra[7]=a1.w;
            rb[0]=b0.x; rb[1]=b0.y; rb[2]=b0.z; rb[3]=b0.w;
            rb[4]=b1.x; rb[5]=b1.y; rb[6]=b1.z; rb[7]=b1.w;
#pragma unroll
            for (int i = 0; i < 8; i++)
#pragma unroll
                for (int j = 0; j < 8; j++)
                    acc[i][j] = fmaf(ra[i], rb[j], acc[i][j]);
        }
        __syncthreads();
    }

#pragma unroll
    for (int i = 0; i < 8; i++) {
        int r = row0 + ty * 8 + i;
        if (r >= M) continue;
#pragma unroll
        for (int j = 0; j < 8; j++) {
            int c = col0 + tx * 8 + j;
            if (c >= N) continue;
            float v = acc[i][j];
            if (bias) v += bias[c];
            if (act == 1) {
                // softplus, numerically stable
                v = (v > 20.f) ? v : log1pf(expf(v));
            }
            C[(size_t)r * ldc + c] = v;
        }
    }
}

// ---------------- causal depthwise conv (width 4) + SiLU -------------------
__global__ void conv_silu_kernel(const float* __restrict__ xz,
                                 const float* __restrict__ w_conv,
                                 const float* __restrict__ b_conv,
                                 float* __restrict__ xconv)
{
    int idx = blockIdx.x * blockDim.x + threadIdx.x;   // over B*L*D_INNER
    if (idx >= NROWS * D_INNER) return;
    int d = idx % D_INNER;
    int l = (idx / D_INNER) % SEQ;
    int b = idx / (D_INNER * SEQ);

    float acc = b_conv[d];
    const float* wc = w_conv + d * D_CONV;
#pragma unroll
    for (int k = 0; k < D_CONV; k++) {
        int ls = l - (D_CONV - 1) + k;
        if (ls >= 0)
            acc += xz[((size_t)(b * SEQ + ls)) * (2 * D_INNER) + d] * wc[k];
    }
    float s = 1.f / (1.f + __expf(-acc));
    xconv[idx] = acc * s;
}

// ---------------- selective scan: 16 lanes per channel ---------------------
__global__ __launch_bounds__(256)
void scan_kernel(const float* __restrict__ xconv,  // [B*L, 2048]
                 const float* __restrict__ xdbc,   // [B*L, 96] (dt|B|C)
                 const float* __restrict__ dtbuf,  // [B*L, 2048]
                 const float* __restrict__ xz,     // [B*L, 4096] (z = cols 2048+)
                 const float* __restrict__ A_log,  // [2048, 16]
                 const float* __restrict__ Dv,     // [2048]
                 float* __restrict__ y)            // [B*L, 2048]
{
    int t = blockIdx.x * 256 + threadIdx.x;        // 65536 threads total
    int n = t & 15;                                // state index
    int c = t >> 4;                                // channel 0..4095
    int d = c & (D_INNER - 1);
    int b = c >> 11;                               // c / D_INNER

    float An = -expf(A_log[d * D_STATE + n]);
    float Dd = Dv[d];
    float h = 0.f;

    const float* dtp = dtbuf + (size_t)b * SEQ * D_INNER + d;
    const float* xp  = xconv + (size_t)b * SEQ * D_INNER + d;
    const float* zp  = xz    + (size_t)b * SEQ * (2 * D_INNER) + D_INNER + d;
    const float* bcp = xdbc  + (size_t)b * SEQ * XPROJ_N;
    float*       yp  = y     + (size_t)b * SEQ * D_INNER + d;

    for (int l = 0; l < SEQ; l++) {
        float dt = dtp[0];
        float xv = xp[0];
        float Bn = bcp[DT_RANK + n];
        float Cn = bcp[DT_RANK + D_STATE + n];
        float ab = __expf(dt * An);
        h = fmaf(ab, h, (dt * xv) * Bn);
        float part = Cn * h;
        part += __shfl_xor_sync(0xffffffffu, part, 1);
        part += __shfl_xor_sync(0xffffffffu, part, 2);
        part += __shfl_xor_sync(0xffffffffu, part, 4);
        part += __shfl_xor_sync(0xffffffffu, part, 8);
        if (n == 0) {
            float z   = zp[0];
            float sig = 1.f / (1.f + __expf(-z));
            yp[0] = (part + xv * Dd) * (z * sig);
        }
        dtp += D_INNER; xp += D_INNER; zp += 2 * D_INNER; bcp += XPROJ_N; yp += D_INNER;
    }
}

// ---------------- launcher -------------------------------------------------
extern "C" void kernel_launch(void* const* d_in, const int* in_sizes, int n_in,
                              void* d_out, int out_size)
{
    const float* x       = (const float*)d_in[0];   // [2,2048,1024]
    const float* w_in    = (const float*)d_in[1];   // [1024,4096]
    const float* w_conv  = (const float*)d_in[2];   // [2048,4]
    const float* b_conv  = (const float*)d_in[3];   // [2048]
    const float* w_xproj = (const float*)d_in[4];   // [2048,96]
    const float* w_dt    = (const float*)d_in[5];   // [64,2048]
    const float* b_dt    = (const float*)d_in[6];   // [2048]
    const float* A_log   = (const float*)d_in[7];   // [2048,16]
    const float* Dv      = (const float*)d_in[8];   // [2048]
    const float* w_out   = (const float*)d_in[9];   // [2048,1024]
    float* out = (float*)d_out;                     // [2,2048,1024]

    float *xz, *xconv, *xdbc, *dtb, *yb;
    cudaGetSymbolAddress((void**)&xz,    g_xz);
    cudaGetSymbolAddress((void**)&xconv, g_xconv);
    cudaGetSymbolAddress((void**)&xdbc,  g_xdbc);
    cudaGetSymbolAddress((void**)&dtb,   g_dt);
    cudaGetSymbolAddress((void**)&yb,    g_y);

    // 1) xz = x @ w_in        [4096,1024]x[1024,4096]
    {
        dim3 grid((2 * D_INNER) / 128, NROWS / 128);
        sgemm_kernel<<<grid, 256>>>(x, w_in, xz, NROWS, 2 * D_INNER, D_MODEL,
                                    D_MODEL, 2 * D_INNER, 2 * D_INNER, nullptr, 0);
    }
    // 2) causal conv + silu
    {
        int total = NROWS * D_INNER;
        conv_silu_kernel<<<(total + 255) / 256, 256>>>(xz, w_conv, b_conv, xconv);
    }
    // 3) xdbc = xconv @ w_xproj   [4096,2048]x[2048,96]
    {
        dim3 grid((XPROJ_N + 127) / 128, NROWS / 128);
        sgemm_kernel<<<grid, 256>>>(xconv, w_xproj, xdbc, NROWS, XPROJ_N, D_INNER,
                                    D_INNER, XPROJ_N, XPROJ_N, nullptr, 0);
    }
    // 4) dt = softplus(xdbc[:, :64] @ w_dt + b_dt)   [4096,64]x[64,2048]
    {
        dim3 grid(D_INNER / 128, NROWS / 128);
        sgemm_kernel<<<grid, 256>>>(xdbc, w_dt, dtb, NROWS, D_INNER, DT_RANK,
                                    XPROJ_N, D_INNER, D_INNER, b_dt, 1);
    }
    // 5) selective scan (fused gating epilogue)
    {
        int threads = B_SZ * D_INNER * D_STATE;    // 65536
        scan_kernel<<<threads / 256, 256>>>(xconv, xdbc, dtb, xz, A_log, Dv, yb);
    }
    // 6) out = y @ w_out   [4096,2048]x[2048,1024]
    {
        dim3 grid(D_MODEL / 128, NROWS / 128);
        sgemm_kernel<<<grid, 256>>>(yb, w_out, out, NROWS, D_MODEL, D_INNER,
                                    D_INNER, D_MODEL, D_MODEL, nullptr, 0);
    }
}

// round 4
// speedup vs baseline: 1.4203x; 1.4203x over previous
#include <cuda_runtime.h>
#include <cuda_bf16.h>
#include <math.h>
#include <cstdint>

#define B_SZ     2
#define SEQ      2048
#define D_MODEL  1024
#define D_INNER  2048
#define D_STATE  16
#define DT_RANK  64
#define D_CONV   4
#define NROWS    (B_SZ * SEQ)             // 4096
#define XPROJ_N  (DT_RANK + 2 * D_STATE)  // 96
#define XPROJ_NPAD 128

typedef __nv_bfloat16 bf16;

// ---------------- scratch (static device globals; no allocation allowed) ---
__device__ __align__(256) float g_xz[(size_t)NROWS * (2 * D_INNER)];
__device__ __align__(256) float g_xconv[(size_t)NROWS * D_INNER];
__device__ __align__(256) float g_xdbc[(size_t)NROWS * XPROJ_N];
__device__ __align__(256) float g_dt[(size_t)NROWS * D_INNER];
// bf16 split activations
__device__ __align__(256) bf16 g_xh[(size_t)NROWS * D_MODEL];
__device__ __align__(256) bf16 g_xl[(size_t)NROWS * D_MODEL];
__device__ __align__(256) bf16 g_xconvh[(size_t)NROWS * D_INNER];
__device__ __align__(256) bf16 g_xconvl[(size_t)NROWS * D_INNER];
__device__ __align__(256) bf16 g_xdbch[(size_t)NROWS * DT_RANK];
__device__ __align__(256) bf16 g_xdbcl[(size_t)NROWS * DT_RANK];
__device__ __align__(256) bf16 g_yh[(size_t)NROWS * D_INNER];
__device__ __align__(256) bf16 g_yl[(size_t)NROWS * D_INNER];
// bf16 split transposed weights [N, K]
__device__ __align__(256) bf16 g_winT_h[(size_t)(2 * D_INNER) * D_MODEL];
__device__ __align__(256) bf16 g_winT_l[(size_t)(2 * D_INNER) * D_MODEL];
__device__ __align__(256) bf16 g_woutT_h[(size_t)D_MODEL * D_INNER];
__device__ __align__(256) bf16 g_woutT_l[(size_t)D_MODEL * D_INNER];
__device__ __align__(256) bf16 g_wxT_h[(size_t)XPROJ_NPAD * D_INNER];
__device__ __align__(256) bf16 g_wxT_l[(size_t)XPROJ_NPAD * D_INNER];
__device__ __align__(256) bf16 g_wdtT_h[(size_t)D_INNER * DT_RANK];
__device__ __align__(256) bf16 g_wdtT_l[(size_t)D_INNER * DT_RANK];

// ======================= helpers ===========================================
__device__ __forceinline__ uint32_t smem_u32(const void* p) {
    uint32_t a;
    asm("{ .reg .u64 t; cvta.to.shared.u64 t, %1; cvt.u32.u64 %0, t; }"
        : "=r"(a) : "l"(p));
    return a;
}
__device__ __forceinline__ void cp_async16(uint32_t dst, const void* src) {
    asm volatile("cp.async.cg.shared.global [%0], [%1], 16;"
                 :: "r"(dst), "l"(src));
}
#define CP_COMMIT() asm volatile("cp.async.commit_group;")
#define CP_WAIT1()  asm volatile("cp.async.wait_group 1;")

__device__ __forceinline__ void mma16816(float* c, const uint32_t* a,
                                         const uint32_t* b) {
    asm volatile(
        "mma.sync.aligned.m16n8k16.row.col.f32.bf16.bf16.f32 "
        "{%0,%1,%2,%3}, {%4,%5,%6,%7}, {%8,%9}, {%0,%1,%2,%3};\n"
        : "+f"(c[0]), "+f"(c[1]), "+f"(c[2]), "+f"(c[3])
        : "r"(a[0]), "r"(a[1]), "r"(a[2]), "r"(a[3]),
          "r"(b[0]), "r"(b[1]));
}

__device__ __forceinline__ void split_bf16(float v, bf16& h, bf16& l) {
    h = __float2bfloat16_rn(v);
    l = __float2bfloat16_rn(v - __bfloat162float(h));
}

// ===================== GEMM: C[M,N] = A * B^T, 3x bf16 split ==============
// A stored split (Ah, Al) [M,K] bf16; B stored split (Bh, Bl) [N,K] bf16.
// Virtual k-loop over 3 passes: Ah*Bh, Ah*Bl, Al*Bh.
// CTA 128x128, 256 thr, warp tile 64x32, K_tile=32, 2-stage cp.async.
// smem row stride = 80B (20 u32): 16B-aligned rows, conflict-free frags.
#define ROW_U32 20
#define ROW_BYTES 80u
#define TILE_B  (128u * ROW_BYTES)   // 10240
#define STAGE_B (2u * TILE_B)        // 20480
#define SMEM_TOT (2u * STAGE_B)      // 40960

__global__ void __launch_bounds__(256)
gemm3x(const bf16* __restrict__ Ah, const bf16* __restrict__ Al,
       const bf16* __restrict__ Bh, const bf16* __restrict__ Bl,
       float* __restrict__ C, int Nc, int K, int ldc,
       const float* __restrict__ bias, int act,
       bf16* __restrict__ Sh, bf16* __restrict__ Sl)   // optional split-out (cols<64)
{
    __shared__ __align__(16) char smem_raw[SMEM_TOT];
    const uint32_t sb = smem_u32(smem_raw);

    const int tid = threadIdx.x;
    const int wid = tid >> 5, lane = tid & 31;
    const int gr = lane >> 2, q = lane & 3;
    const int row0 = blockIdx.y * 128, col0 = blockIdx.x * 128;
    const int warp_m = (wid & 1) * 64, warp_n = (wid >> 1) * 32;

    const int kchunks = K >> 5;
    const int nch = 3 * kchunks;

    float acc[4][4][4];
#pragma unroll
    for (int i = 0; i < 4; i++)
#pragma unroll
        for (int j = 0; j < 4; j++)
#pragma unroll
            for (int r = 0; r < 4; r++) acc[i][j][r] = 0.f;

    auto load_stage = [&](int c, int s) {
        int p = c / kchunks;
        int koff = (c - p * kchunks) << 5;
        const bf16* Ab = ((p == 2) ? Al : Ah) + (size_t)row0 * K + koff;
        const bf16* Bb = ((p == 1) ? Bl : Bh) + (size_t)col0 * K + koff;
#pragma unroll
        for (int i = 0; i < 4; i++) {
            int seg = tid + 256 * i;          // 0..1023
            int buf = seg >> 9;               // 0 = A, 1 = B
            int w   = seg & 511;
            int row = w >> 2, s4 = w & 3;
            const bf16* g = (buf ? Bb : Ab) + (size_t)row * K + s4 * 8;
            uint32_t dst = sb + (uint32_t)s * STAGE_B + (uint32_t)buf * TILE_B
                         + (uint32_t)row * ROW_BYTES + (uint32_t)s4 * 16u;
            cp_async16(dst, g);
        }
    };

    load_stage(0, 0);
    CP_COMMIT();

    for (int c = 0; c < nch; c++) {
        if (c + 1 < nch) load_stage(c + 1, (c + 1) & 1);
        CP_COMMIT();
        CP_WAIT1();
        __syncthreads();

        const uint32_t* A32 = reinterpret_cast<const uint32_t*>(
            smem_raw + (size_t)(c & 1) * STAGE_B);
        const uint32_t* B32 = reinterpret_cast<const uint32_t*>(
            smem_raw + (size_t)(c & 1) * STAGE_B + TILE_B);

#pragma unroll
        for (int kc = 0; kc < 2; kc++) {
            uint32_t a[4][4], b[4][2];
#pragma unroll
            for (int mt = 0; mt < 4; mt++) {
                int r = warp_m + mt * 16 + gr;
                a[mt][0] = A32[r * ROW_U32 + kc * 8 + q];
                a[mt][1] = A32[(r + 8) * ROW_U32 + kc * 8 + q];
                a[mt][2] = A32[r * ROW_U32 + kc * 8 + 4 + q];
                a[mt][3] = A32[(r + 8) * ROW_U32 + kc * 8 + 4 + q];
            }
#pragma unroll
            for (int nt = 0; nt < 4; nt++) {
                int n = warp_n + nt * 8 + gr;
                b[nt][0] = B32[n * ROW_U32 + kc * 8 + q];
                b[nt][1] = B32[n * ROW_U32 + kc * 8 + 4 + q];
            }
#pragma unroll
            for (int mt = 0; mt < 4; mt++)
#pragma unroll
                for (int nt = 0; nt < 4; nt++)
                    mma16816(acc[mt][nt], a[mt], b[nt]);
        }
        __syncthreads();
    }

    // ---------------- epilogue ----------------
#pragma unroll
    for (int mt = 0; mt < 4; mt++) {
#pragma unroll
        for (int nt = 0; nt < 4; nt++) {
            int rg = row0 + warp_m + mt * 16 + gr;
            int cg = col0 + warp_n + nt * 8 + 2 * q;
            float* cc = acc[mt][nt];
#pragma unroll
            for (int half = 0; half < 2; half++) {
                int r = rg + half * 8;
                float v0 = cc[half * 2 + 0];
                float v1 = cc[half * 2 + 1];
                if (bias) { v0 += bias[cg]; v1 += bias[cg + 1]; }
                if (act == 1) {
                    v0 = (v0 > 20.f) ? v0 : log1pf(expf(v0));
                    v1 = (v1 > 20.f) ? v1 : log1pf(expf(v1));
                }
                if (cg + 1 < Nc) {
                    *reinterpret_cast<float2*>(&C[(size_t)r * ldc + cg]) =
                        make_float2(v0, v1);
                } else if (cg < Nc) {
                    C[(size_t)r * ldc + cg] = v0;
                }
                if (Sh && cg < DT_RANK) {
                    bf16 h0, l0, h1, l1;
                    split_bf16(v0, h0, l0);
                    split_bf16(v1, h1, l1);
                    Sh[(size_t)r * DT_RANK + cg] = h0;
                    Sl[(size_t)r * DT_RANK + cg] = l0;
                    Sh[(size_t)r * DT_RANK + cg + 1] = h1;
                    Sl[(size_t)r * DT_RANK + cg + 1] = l1;
                }
            }
        }
    }
}

// ===================== weight transpose + bf16 split =======================
// W [K, N] -> Th/Tl [Npad, K] bf16 (rows >= N zero-filled)
__global__ void wsplit_kernel(const float* __restrict__ W,
                              bf16* __restrict__ Th, bf16* __restrict__ Tl,
                              int K, int N, int Npad)
{
    __shared__ float tile[32][33];
    int kb = blockIdx.y * 32, nb = blockIdx.x * 32;
    int tx = threadIdx.x, ty = threadIdx.y;
#pragma unroll
    for (int i = ty; i < 32; i += 8) {
        int k = kb + i, n = nb + tx;
        tile[i][tx] = (k < K && n < N) ? W[(size_t)k * N + n] : 0.f;
    }
    __syncthreads();
#pragma unroll
    for (int i = ty; i < 32; i += 8) {
        int n = nb + i, k = kb + tx;
        if (n < Npad && k < K) {
            bf16 h, l;
            split_bf16(tile[tx][i], h, l);
            Th[(size_t)n * K + k] = h;
            Tl[(size_t)n * K + k] = l;
        }
    }
}

// ---------------- elementwise fp32 -> bf16 hi/lo split ---------------------
__global__ void fsplit_kernel(const float* __restrict__ X,
                              bf16* __restrict__ H, bf16* __restrict__ L,
                              int n)
{
    int i = blockIdx.x * blockDim.x + threadIdx.x;
    if (i >= n) return;
    bf16 h, l;
    split_bf16(X[i], h, l);
    H[i] = h; L[i] = l;
}

// ---------------- causal depthwise conv (width 4) + SiLU + split -----------
__global__ void conv_silu_kernel(const float* __restrict__ xz,
                                 const float* __restrict__ w_conv,
                                 const float* __restrict__ b_conv,
                                 float* __restrict__ xconv,
                                 bf16* __restrict__ xch, bf16* __restrict__ xcl)
{
    int idx = blockIdx.x * blockDim.x + threadIdx.x;
    if (idx >= NROWS * D_INNER) return;
    int d = idx % D_INNER;
    int l = (idx / D_INNER) % SEQ;
    int b = idx / (D_INNER * SEQ);

    float acc = b_conv[d];
    const float* wc = w_conv + d * D_CONV;
#pragma unroll
    for (int k = 0; k < D_CONV; k++) {
        int ls = l - (D_CONV - 1) + k;
        if (ls >= 0)
            acc += xz[((size_t)(b * SEQ + ls)) * (2 * D_INNER) + d] * wc[k];
    }
    float s = 1.f / (1.f + __expf(-acc));
    float v = acc * s;
    xconv[idx] = v;
    bf16 h, lo;
    split_bf16(v, h, lo);
    xch[idx] = h; xcl[idx] = lo;
}

// ---------------- selective scan: 16 lanes per channel ---------------------
__global__ void __launch_bounds__(256)
scan_kernel(const float* __restrict__ xconv,
            const float* __restrict__ xdbc,
            const float* __restrict__ dtbuf,
            const float* __restrict__ xz,
            const float* __restrict__ A_log,
            const float* __restrict__ Dv,
            bf16* __restrict__ yh, bf16* __restrict__ yl)
{
    int t = blockIdx.x * 256 + threadIdx.x;
    int n = t & 15;
    int c = t >> 4;
    int d = c & (D_INNER - 1);
    int b = c >> 11;

    float An = -expf(A_log[d * D_STATE + n]);
    float Dd = Dv[d];
    float h = 0.f;

    const float* dtp = dtbuf + (size_t)b * SEQ * D_INNER + d;
    const float* xp  = xconv + (size_t)b * SEQ * D_INNER + d;
    const float* zp  = xz    + (size_t)b * SEQ * (2 * D_INNER) + D_INNER + d;
    const float* bcp = xdbc  + (size_t)b * SEQ * XPROJ_N;
    size_t yi = (size_t)b * SEQ * D_INNER + d;

    for (int l = 0; l < SEQ; l++) {
        float dt = dtp[0];
        float xv = xp[0];
        float Bn = bcp[DT_RANK + n];
        float Cn = bcp[DT_RANK + D_STATE + n];
        float ab = __expf(dt * An);
        h = fmaf(ab, h, (dt * xv) * Bn);
        float part = Cn * h;
        part += __shfl_xor_sync(0xffffffffu, part, 1);
        part += __shfl_xor_sync(0xffffffffu, part, 2);
        part += __shfl_xor_sync(0xffffffffu, part, 4);
        part += __shfl_xor_sync(0xffffffffu, part, 8);
        if (n == 0) {
            float z   = zp[0];
            float sig = 1.f / (1.f + __expf(-z));
            float yv = (part + xv * Dd) * (z * sig);
            bf16 hh, ll;
            split_bf16(yv, hh, ll);
            yh[yi] = hh; yl[yi] = ll;
        }
        dtp += D_INNER; xp += D_INNER; zp += 2 * D_INNER; bcp += XPROJ_N;
        yi += D_INNER;
    }
}

// ---------------- launcher -------------------------------------------------
extern "C" void kernel_launch(void* const* d_in, const int* in_sizes, int n_in,
                              void* d_out, int out_size)
{
    const float* x       = (const float*)d_in[0];
    const float* w_in    = (const float*)d_in[1];
    const float* w_conv  = (const float*)d_in[2];
    const float* b_conv  = (const float*)d_in[3];
    const float* w_xproj = (const float*)d_in[4];
    const float* w_dt    = (const float*)d_in[5];
    const float* b_dt    = (const float*)d_in[6];
    const float* A_log   = (const float*)d_in[7];
    const float* Dv      = (const float*)d_in[8];
    const float* w_out   = (const float*)d_in[9];
    float* out = (float*)d_out;

    float *xz, *xconv, *xdbc, *dtb;
    bf16 *xh, *xl, *xch, *xcl, *xdh, *xdl, *yh, *yl;
    bf16 *winT_h, *winT_l, *woutT_h, *woutT_l, *wxT_h, *wxT_l, *wdtT_h, *wdtT_l;
    cudaGetSymbolAddress((void**)&xz,      g_xz);
    cudaGetSymbolAddress((void**)&xconv,   g_xconv);
    cudaGetSymbolAddress((void**)&xdbc,    g_xdbc);
    cudaGetSymbolAddress((void**)&dtb,     g_dt);
    cudaGetSymbolAddress((void**)&xh,      g_xh);
    cudaGetSymbolAddress((void**)&xl,      g_xl);
    cudaGetSymbolAddress((void**)&xch,     g_xconvh);
    cudaGetSymbolAddress((void**)&xcl,     g_xconvl);
    cudaGetSymbolAddress((void**)&xdh,     g_xdbch);
    cudaGetSymbolAddress((void**)&xdl,     g_xdbcl);
    cudaGetSymbolAddress((void**)&yh,      g_yh);
    cudaGetSymbolAddress((void**)&yl,      g_yl);
    cudaGetSymbolAddress((void**)&winT_h,  g_winT_h);
    cudaGetSymbolAddress((void**)&winT_l,  g_winT_l);
    cudaGetSymbolAddress((void**)&woutT_h, g_woutT_h);
    cudaGetSymbolAddress((void**)&woutT_l, g_woutT_l);
    cudaGetSymbolAddress((void**)&wxT_h,   g_wxT_h);
    cudaGetSymbolAddress((void**)&wxT_l,   g_wxT_l);
    cudaGetSymbolAddress((void**)&wdtT_h,  g_wdtT_h);
    cudaGetSymbolAddress((void**)&wdtT_l,  g_wdtT_l);

    dim3 tb(32, 8);
    // input + weight splits
    fsplit_kernel<<<(NROWS * D_MODEL + 255) / 256, 256>>>(x, xh, xl, NROWS * D_MODEL);
    wsplit_kernel<<<dim3(4096 / 32, 1024 / 32), tb>>>(w_in, winT_h, winT_l,
                                                      D_MODEL, 2 * D_INNER, 2 * D_INNER);
    wsplit_kernel<<<dim3(XPROJ_NPAD / 32, 2048 / 32), tb>>>(w_xproj, wxT_h, wxT_l,
                                                            D_INNER, XPROJ_N, XPROJ_NPAD);
    wsplit_kernel<<<dim3(2048 / 32, 64 / 32), tb>>>(w_dt, wdtT_h, wdtT_l,
                                                    DT_RANK, D_INNER, D_INNER);
    wsplit_kernel<<<dim3(1024 / 32, 2048 / 32), tb>>>(w_out, woutT_h, woutT_l,
                                                      D_INNER, D_MODEL, D_MODEL);

    // 1) xz = x @ w_in                 M=4096 N=4096 K=1024
    gemm3x<<<dim3(32, 32), 256>>>(xh, xl, winT_h, winT_l, xz,
                                  2 * D_INNER, D_MODEL, 2 * D_INNER,
                                  nullptr, 0, nullptr, nullptr);
    // 2) causal conv + silu (+ bf16 split)
    conv_silu_kernel<<<(NROWS * D_INNER + 255) / 256, 256>>>(
        xz, w_conv, b_conv, xconv, xch, xcl);
    // 3) xdbc = xconv @ w_xproj        M=4096 N=96 K=2048 (+ dt-rank split out)
    gemm3x<<<dim3(1, 32), 256>>>(xch, xcl, wxT_h, wxT_l, xdbc,
                                 XPROJ_N, D_INNER, XPROJ_N,
                                 nullptr, 0, xdh, xdl);
    // 4) dt = softplus(xdbc[:, :64] @ w_dt + b_dt)   M=4096 N=2048 K=64
    gemm3x<<<dim3(16, 32), 256>>>(xdh, xdl, wdtT_h, wdtT_l, dtb,
                                  D_INNER, DT_RANK, D_INNER,
                                  b_dt, 1, nullptr, nullptr);
    // 5) selective scan (fused gating + y split)
    scan_kernel<<<(B_SZ * D_INNER * D_STATE) / 256, 256>>>(
        xconv, xdbc, dtb, xz, A_log, Dv, yh, yl);
    // 6) out = y @ w_out               M=4096 N=1024 K=2048
    gemm3x<<<dim3(8, 32), 256>>>(yh, yl, woutT_h, woutT_l, out,
                                 D_MODEL, D_INNER, D_MODEL,
                                 nullptr, 0, nullptr, nullptr);
}

// round 5
// speedup vs baseline: 1.5753x; 1.1091x over previous
#include <cuda_runtime.h>
#include <cuda_bf16.h>
#include <math.h>
#include <cstdint>

#define B_SZ     2
#define SEQ      2048
#define D_MODEL  1024
#define D_INNER  2048
#define D_STATE  16
#define DT_RANK  64
#define D_CONV   4
#define NROWS    (B_SZ * SEQ)             // 4096
#define XPROJ_N  (DT_RANK + 2 * D_STATE)  // 96
#define XPROJ_NPAD 128
#define KSPLIT3  4

typedef __nv_bfloat16 bf16;

// ---------------- scratch (static device globals; no allocation allowed) ---
__device__ __align__(256) float g_xz[(size_t)NROWS * (2 * D_INNER)];
__device__ __align__(256) float g_xconv[(size_t)NROWS * D_INNER];
__device__ __align__(256) float g_xdbc[(size_t)NROWS * XPROJ_N];
__device__ __align__(256) float g_dt[(size_t)NROWS * D_INNER];
__device__ __align__(256) float g_part[(size_t)KSPLIT3 * NROWS * XPROJ_NPAD];
// bf16 split activations
__device__ __align__(256) bf16 g_xh[(size_t)NROWS * D_MODEL];
__device__ __align__(256) bf16 g_xl[(size_t)NROWS * D_MODEL];
__device__ __align__(256) bf16 g_xconvh[(size_t)NROWS * D_INNER];
__device__ __align__(256) bf16 g_xconvl[(size_t)NROWS * D_INNER];
__device__ __align__(256) bf16 g_xdbch[(size_t)NROWS * DT_RANK];
__device__ __align__(256) bf16 g_xdbcl[(size_t)NROWS * DT_RANK];
__device__ __align__(256) bf16 g_yh[(size_t)NROWS * D_INNER];
__device__ __align__(256) bf16 g_yl[(size_t)NROWS * D_INNER];
// bf16 split transposed weights [N, K]
__device__ __align__(256) bf16 g_winT_h[(size_t)(2 * D_INNER) * D_MODEL];
__device__ __align__(256) bf16 g_winT_l[(size_t)(2 * D_INNER) * D_MODEL];
__device__ __align__(256) bf16 g_woutT_h[(size_t)D_MODEL * D_INNER];
__device__ __align__(256) bf16 g_woutT_l[(size_t)D_MODEL * D_INNER];
__device__ __align__(256) bf16 g_wxT_h[(size_t)XPROJ_NPAD * D_INNER];
__device__ __align__(256) bf16 g_wxT_l[(size_t)XPROJ_NPAD * D_INNER];
__device__ __align__(256) bf16 g_wdtT_h[(size_t)D_INNER * DT_RANK];
__device__ __align__(256) bf16 g_wdtT_l[(size_t)D_INNER * DT_RANK];

// ======================= helpers ===========================================
__device__ __forceinline__ uint32_t smem_u32(const void* p) {
    uint32_t a;
    asm("{ .reg .u64 t; cvta.to.shared.u64 t, %1; cvt.u32.u64 %0, t; }"
        : "=r"(a) : "l"(p));
    return a;
}
__device__ __forceinline__ void cp_async16(uint32_t dst, const void* src) {
    asm volatile("cp.async.cg.shared.global [%0], [%1], 16;"
                 :: "r"(dst), "l"(src));
}
#define CP_COMMIT() asm volatile("cp.async.commit_group;")
#define CP_WAIT0()  asm volatile("cp.async.wait_group 0;")

__device__ __forceinline__ void ldsm_x4(uint32_t* r, uint32_t addr) {
    asm volatile("ldmatrix.sync.aligned.m8n8.x4.shared.b16 {%0,%1,%2,%3}, [%4];"
                 : "=r"(r[0]), "=r"(r[1]), "=r"(r[2]), "=r"(r[3]) : "r"(addr));
}

__device__ __forceinline__ void mma16816(float* c, const uint32_t* a,
                                         const uint32_t* b) {
    asm volatile(
        "mma.sync.aligned.m16n8k16.row.col.f32.bf16.bf16.f32 "
        "{%0,%1,%2,%3}, {%4,%5,%6,%7}, {%8,%9}, {%0,%1,%2,%3};\n"
        : "+f"(c[0]), "+f"(c[1]), "+f"(c[2]), "+f"(c[3])
        : "r"(a[0]), "r"(a[1]), "r"(a[2]), "r"(a[3]),
          "r"(b[0]), "r"(b[1]));
}

__device__ __forceinline__ void split_bf16(float v, bf16& h, bf16& l) {
    h = __float2bfloat16_rn(v);
    l = __float2bfloat16_rn(v - __bfloat162float(h));
}

// ===================== GEMM: C[M,N] = A * B^T, 3x bf16 split ==============
#define ROW_BYTES 80u
#define TILE_B    (128u * ROW_BYTES)    // 10240
#define STAGE_B   (4u * TILE_B)         // 40960 (Ah|Al|Bh|Bl)
#define SMEM_TOT  (2u * STAGE_B)        // 81920

__global__ void __launch_bounds__(256)
gemm3x(const bf16* __restrict__ Ah, const bf16* __restrict__ Al,
       const bf16* __restrict__ Bh, const bf16* __restrict__ Bl,
       float* __restrict__ C, int Nc, int K, int kstart_ch, int kch, int ldc,
       const float* __restrict__ bias, int act, size_t partStride)
{
    extern __shared__ __align__(16) char smem_raw[];
    const uint32_t sb = smem_u32(smem_raw);

    kstart_ch += blockIdx.z * kch;          // split-K slice

    const int tid = threadIdx.x;
    const int wid = tid >> 5, lane = tid & 31;
    const int gr = lane >> 2, q = lane & 3;
    const int row0 = blockIdx.y * 128, col0 = blockIdx.x * 128;
    const int warp_m = (wid & 1) * 64, warp_n = (wid >> 1) * 32;

    float* Cout = C + (size_t)blockIdx.z * partStride;

    const bf16* tb0 = Ah + (size_t)row0 * K;
    const bf16* tb1 = Al + (size_t)row0 * K;
    const bf16* tb2 = Bh + (size_t)col0 * K;
    const bf16* tb3 = Bl + (size_t)col0 * K;

    float acc[4][4][4];
#pragma unroll
    for (int i = 0; i < 4; i++)
#pragma unroll
        for (int j = 0; j < 4; j++)
#pragma unroll
            for (int r = 0; r < 4; r++) acc[i][j][r] = 0.f;

    auto load_stage = [&](int c, int s) {
        int koff = (kstart_ch + c) << 5;
#pragma unroll
        for (int i = 0; i < 8; i++) {
            int seg = tid + 256 * i;            // 0..2047
            int buf = seg >> 9;                 // tile id 0..3
            int w   = seg & 511;
            int row = w >> 2, s4 = w & 3;
            const bf16* base = (buf == 0) ? tb0 : (buf == 1) ? tb1
                             : (buf == 2) ? tb2 : tb3;
            const bf16* g = base + (size_t)row * K + koff + s4 * 8;
            uint32_t dst = sb + (uint32_t)s * STAGE_B + (uint32_t)buf * TILE_B
                         + (uint32_t)row * ROW_BYTES + (uint32_t)s4 * 16u;
            cp_async16(dst, g);
        }
    };

    const uint32_t a_row  = (uint32_t)(lane & 15);
    const uint32_t a_koff = (uint32_t)(lane >> 4) * 16u;
    const uint32_t b_row  = (uint32_t)(((lane >> 4) << 3) + (lane & 7));
    const uint32_t b_koff = (uint32_t)((lane >> 3) & 1) * 16u;

    load_stage(0, 0);
    CP_COMMIT();

    for (int c = 0; c < kch; c++) {
        CP_WAIT0();
        __syncthreads();
        if (c + 1 < kch) { load_stage(c + 1, (c + 1) & 1); CP_COMMIT(); }

        const uint32_t st = sb + (uint32_t)(c & 1) * STAGE_B;
        const uint32_t sAh = st;
        const uint32_t sAl = st + TILE_B;
        const uint32_t sBh = st + 2 * TILE_B;
        const uint32_t sBl = st + 3 * TILE_B;

#pragma unroll
        for (int kc = 0; kc < 2; kc++) {
            uint32_t aH[4][4], aL[4][4], bH[8], bL[8];
#pragma unroll
            for (int mt = 0; mt < 4; mt++) {
                uint32_t roff = ((uint32_t)(warp_m + mt * 16) + a_row) * ROW_BYTES
                              + kc * 32u + a_koff;
                ldsm_x4(aH[mt], sAh + roff);
                ldsm_x4(aL[mt], sAl + roff);
            }
            {
                uint32_t r0 = ((uint32_t)warp_n + b_row) * ROW_BYTES
                            + kc * 32u + b_koff;
                uint32_t r1 = r0 + 16u * ROW_BYTES;
                ldsm_x4(bH + 0, sBh + r0);
                ldsm_x4(bH + 4, sBh + r1);
                ldsm_x4(bL + 0, sBl + r0);
                ldsm_x4(bL + 4, sBl + r1);
            }
#pragma unroll
            for (int mt = 0; mt < 4; mt++)
#pragma unroll
                for (int nt = 0; nt < 4; nt++)
                    mma16816(acc[mt][nt], aH[mt], bH + nt * 2);
#pragma unroll
            for (int mt = 0; mt < 4; mt++)
#pragma unroll
                for (int nt = 0; nt < 4; nt++)
                    mma16816(acc[mt][nt], aH[mt], bL + nt * 2);
#pragma unroll
            for (int mt = 0; mt < 4; mt++)
#pragma unroll
                for (int nt = 0; nt < 4; nt++)
                    mma16816(acc[mt][nt], aL[mt], bH + nt * 2);
        }
        __syncthreads();
    }

    // ---------------- epilogue ----------------
#pragma unroll
    for (int mt = 0; mt < 4; mt++) {
#pragma unroll
        for (int nt = 0; nt < 4; nt++) {
            int rg = row0 + warp_m + mt * 16 + gr;
            int cg = col0 + warp_n + nt * 8 + 2 * q;
            float* cc = acc[mt][nt];
#pragma unroll
            for (int half = 0; half < 2; half++) {
                int r = rg + half * 8;
                float v0 = cc[half * 2 + 0];
                float v1 = cc[half * 2 + 1];
                if (bias) { v0 += bias[cg]; v1 += bias[cg + 1]; }
                if (act == 1) {
                    v0 = (v0 > 20.f) ? v0 : log1pf(expf(v0));
                    v1 = (v1 > 20.f) ? v1 : log1pf(expf(v1));
                }
                if (cg + 1 < Nc) {
                    *reinterpret_cast<float2*>(&Cout[(size_t)r * ldc + cg]) =
                        make_float2(v0, v1);
                } else if (cg < Nc) {
                    Cout[(size_t)r * ldc + cg] = v0;
                }
            }
        }
    }
}

// -------- split-K reduce for xproj GEMM: sum partials, write xdbc + dt split
__global__ void reduce3_kernel(const float* __restrict__ part,
                               float* __restrict__ xdbc,
                               bf16* __restrict__ xdh, bf16* __restrict__ xdl)
{
    int i = blockIdx.x * 256 + threadIdx.x;
    if (i >= NROWS * XPROJ_N) return;
    int r = i / XPROJ_N, c = i - r * XPROJ_N;
    const size_t ps = (size_t)NROWS * XPROJ_NPAD;
    float v = 0.f;
#pragma unroll
    for (int p = 0; p < KSPLIT3; p++)
        v += part[p * ps + (size_t)r * XPROJ_NPAD + c];
    xdbc[(size_t)r * XPROJ_N + c] = v;
    if (c < DT_RANK) {
        bf16 h, l;
        split_bf16(v, h, l);
        xdh[(size_t)r * DT_RANK + c] = h;
        xdl[(size_t)r * DT_RANK + c] = l;
    }
}

// ===================== weight transpose + bf16 split =======================
__global__ void wsplit_kernel(const float* __restrict__ W,
                              bf16* __restrict__ Th, bf16* __restrict__ Tl,
                              int K, int N, int Npad)
{
    __shared__ float tile[32][33];
    int kb = blockIdx.y * 32, nb = blockIdx.x * 32;
    int tx = threadIdx.x, ty = threadIdx.y;
#pragma unroll
    for (int i = ty; i < 32; i += 8) {
        int k = kb + i, n = nb + tx;
        tile[i][tx] = (k < K && n < N) ? W[(size_t)k * N + n] : 0.f;
    }
    __syncthreads();
#pragma unroll
    for (int i = ty; i < 32; i += 8) {
        int n = nb + i, k = kb + tx;
        if (n < Npad && k < K) {
            bf16 h, l;
            split_bf16(tile[tx][i], h, l);
            Th[(size_t)n * K + k] = h;
            Tl[(size_t)n * K + k] = l;
        }
    }
}

// ---------------- elementwise fp32 -> bf16 hi/lo split ---------------------
__global__ void fsplit_kernel(const float* __restrict__ X,
                              bf16* __restrict__ H, bf16* __restrict__ L,
                              int n)
{
    int i = blockIdx.x * blockDim.x + threadIdx.x;
    if (i >= n) return;
    bf16 h, l;
    split_bf16(X[i], h, l);
    H[i] = h; L[i] = l;
}

// ---------------- causal depthwise conv (width 4) + SiLU + split -----------
__global__ void conv_silu_kernel(const float* __restrict__ xz,
                                 const float* __restrict__ w_conv,
                                 const float* __restrict__ b_conv,
                                 float* __restrict__ xconv,
                                 bf16* __restrict__ xch, bf16* __restrict__ xcl)
{
    int idx = blockIdx.x * blockDim.x + threadIdx.x;
    if (idx >= NROWS * D_INNER) return;
    int d = idx % D_INNER;
    int l = (idx / D_INNER) % SEQ;
    int b = idx / (D_INNER * SEQ);

    float acc = b_conv[d];
    const float* wc = w_conv + d * D_CONV;
#pragma unroll
    for (int k = 0; k < D_CONV; k++) {
        int ls = l - (D_CONV - 1) + k;
        if (ls >= 0)
            acc += xz[((size_t)(b * SEQ + ls)) * (2 * D_INNER) + d] * wc[k];
    }
    float s = 1.f / (1.f + __expf(-acc));
    float v = acc * s;
    xconv[idx] = v;
    bf16 h, lo;
    split_bf16(v, h, lo);
    xch[idx] = h; xcl[idx] = lo;
}

// ---------------- selective scan: 16 lanes per channel ---------------------
__global__ void __launch_bounds__(256)
scan_kernel(const float* __restrict__ xconv,
            const float* __restrict__ xdbc,
            const float* __restrict__ dtbuf,
            const float* __restrict__ xz,
            const float* __restrict__ A_log,
            const float* __restrict__ Dv,
            bf16* __restrict__ yh, bf16* __restrict__ yl)
{
    int t = blockIdx.x * 256 + threadIdx.x;
    int n = t & 15;
    int c = t >> 4;
    int d = c & (D_INNER - 1);
    int b = c >> 11;

    float An = -expf(A_log[d * D_STATE + n]);
    float Dd = Dv[d];
    float h = 0.f;

    const float* dtp = dtbuf + (size_t)b * SEQ * D_INNER + d;
    const float* xp  = xconv + (size_t)b * SEQ * D_INNER + d;
    const float* zp  = xz    + (size_t)b * SEQ * (2 * D_INNER) + D_INNER + d;
    const float* bcp = xdbc  + (size_t)b * SEQ * XPROJ_N;
    size_t yi = (size_t)b * SEQ * D_INNER + d;

    for (int l = 0; l < SEQ; l++) {
        float dt = dtp[0];
        float xv = xp[0];
        float Bn = bcp[DT_RANK + n];
        float Cn = bcp[DT_RANK + D_STATE + n];
        float ab = __expf(dt * An);
        h = fmaf(ab, h, (dt * xv) * Bn);
        float part = Cn * h;
        part += __shfl_xor_sync(0xffffffffu, part, 1);
        part += __shfl_xor_sync(0xffffffffu, part, 2);
        part += __shfl_xor_sync(0xffffffffu, part, 4);
        part += __shfl_xor_sync(0xffffffffu, part, 8);
        if (n == 0) {
            float z   = zp[0];
            float sig = 1.f / (1.f + __expf(-z));
            float yv = (part + xv * Dd) * (z * sig);
            bf16 hh, ll;
            split_bf16(yv, hh, ll);
            yh[yi] = hh; yl[yi] = ll;
        }
        dtp += D_INNER; xp += D_INNER; zp += 2 * D_INNER; bcp += XPROJ_N;
        yi += D_INNER;
    }
}

// ---------------- launcher -------------------------------------------------
extern "C" void kernel_launch(void* const* d_in, const int* in_sizes, int n_in,
                              void* d_out, int out_size)
{
    const float* x       = (const float*)d_in[0];
    const float* w_in    = (const float*)d_in[1];
    const float* w_conv  = (const float*)d_in[2];
    const float* b_conv  = (const float*)d_in[3];
    const float* w_xproj = (const float*)d_in[4];
    const float* w_dt    = (const float*)d_in[5];
    const float* b_dt    = (const float*)d_in[6];
    const float* A_log   = (const float*)d_in[7];
    const float* Dv      = (const float*)d_in[8];
    const float* w_out   = (const float*)d_in[9];
    float* out = (float*)d_out;

    float *xz, *xconv, *xdbc, *dtb, *part;
    bf16 *xh, *xl, *xch, *xcl, *xdh, *xdl, *yh, *yl;
    bf16 *winT_h, *winT_l, *woutT_h, *woutT_l, *wxT_h, *wxT_l, *wdtT_h, *wdtT_l;
    cudaGetSymbolAddress((void**)&xz,      g_xz);
    cudaGetSymbolAddress((void**)&xconv,   g_xconv);
    cudaGetSymbolAddress((void**)&xdbc,    g_xdbc);
    cudaGetSymbolAddress((void**)&dtb,     g_dt);
    cudaGetSymbolAddress((void**)&part,    g_part);
    cudaGetSymbolAddress((void**)&xh,      g_xh);
    cudaGetSymbolAddress((void**)&xl,      g_xl);
    cudaGetSymbolAddress((void**)&xch,     g_xconvh);
    cudaGetSymbolAddress((void**)&xcl,     g_xconvl);
    cudaGetSymbolAddress((void**)&xdh,     g_xdbch);
    cudaGetSymbolAddress((void**)&xdl,     g_xdbcl);
    cudaGetSymbolAddress((void**)&yh,      g_yh);
    cudaGetSymbolAddress((void**)&yl,      g_yl);
    cudaGetSymbolAddress((void**)&winT_h,  g_winT_h);
    cudaGetSymbolAddress((void**)&winT_l,  g_winT_l);
    cudaGetSymbolAddress((void**)&woutT_h, g_woutT_h);
    cudaGetSymbolAddress((void**)&woutT_l, g_woutT_l);
    cudaGetSymbolAddress((void**)&wxT_h,   g_wxT_h);
    cudaGetSymbolAddress((void**)&wxT_l,   g_wxT_l);
    cudaGetSymbolAddress((void**)&wdtT_h,  g_wdtT_h);
    cudaGetSymbolAddress((void**)&wdtT_l,  g_wdtT_l);

    cudaFuncSetAttribute(gemm3x, cudaFuncAttributeMaxDynamicSharedMemorySize,
                         SMEM_TOT);

    dim3 tb(32, 8);
    fsplit_kernel<<<(NROWS * D_MODEL + 255) / 256, 256>>>(x, xh, xl, NROWS * D_MODEL);
    wsplit_kernel<<<dim3(4096 / 32, 1024 / 32), tb>>>(w_in, winT_h, winT_l,
                                                      D_MODEL, 2 * D_INNER, 2 * D_INNER);
    wsplit_kernel<<<dim3(XPROJ_NPAD / 32, 2048 / 32), tb>>>(w_xproj, wxT_h, wxT_l,
                                                            D_INNER, XPROJ_N, XPROJ_NPAD);
    wsplit_kernel<<<dim3(2048 / 32, 64 / 32), tb>>>(w_dt, wdtT_h, wdtT_l,
                                                    DT_RANK, D_INNER, D_INNER);
    wsplit_kernel<<<dim3(1024 / 32, 2048 / 32), tb>>>(w_out, woutT_h, woutT_l,
                                                      D_INNER, D_MODEL, D_MODEL);

    // 1) xz = x @ w_in                 M=4096 N=4096 K=1024
    gemm3x<<<dim3(32, 32, 1), 256, SMEM_TOT>>>(xh, xl, winT_h, winT_l, xz,
                                               2 * D_INNER, D_MODEL, 0,
                                               D_MODEL / 32, 2 * D_INNER,
                                               nullptr, 0, 0);
    // 2) causal conv + silu (+ bf16 split)
    conv_silu_kernel<<<(NROWS * D_INNER + 255) / 256, 256>>>(
        xz, w_conv, b_conv, xconv, xch, xcl);
    // 3) xproj: split-K=4 into partials, then reduce (+ dt split)
    gemm3x<<<dim3(1, 32, KSPLIT3), 256, SMEM_TOT>>>(
        xch, xcl, wxT_h, wxT_l, part,
        XPROJ_NPAD, D_INNER, 0, (D_INNER / 32) / KSPLIT3, XPROJ_NPAD,
        nullptr, 0, (size_t)NROWS * XPROJ_NPAD);
    reduce3_kernel<<<(NROWS * XPROJ_N + 255) / 256, 256>>>(part, xdbc, xdh, xdl);
    // 4) dt = softplus(xdbc[:, :64] @ w_dt + b_dt)   M=4096 N=2048 K=64
    gemm3x<<<dim3(16, 32, 1), 256, SMEM_TOT>>>(xdh, xdl, wdtT_h, wdtT_l, dtb,
                                               D_INNER, DT_RANK, 0,
                                               DT_RANK / 32, D_INNER,
                                               b_dt, 1, 0);
    // 5) selective scan (fused gating + y split)
    scan_kernel<<<(B_SZ * D_INNER * D_STATE) / 256, 256>>>(
        xconv, xdbc, dtb, xz, A_log, Dv, yh, yl);
    // 6) out = y @ w_out               M=4096 N=1024 K=2048
    gemm3x<<<dim3(8, 32, 1), 256, SMEM_TOT>>>(yh, yl, woutT_h, woutT_l, out,
                                              D_MODEL, D_INNER, 0,
                                              D_INNER / 32, D_MODEL,
                                              nullptr, 0, 0);
}

// round 6
// speedup vs baseline: 4.4117x; 2.8005x over previous
#include <cuda_runtime.h>
#include <cuda_bf16.h>
#include <math.h>
#include <cstdint>

#define B_SZ     2
#define SEQ      2048
#define D_MODEL  1024
#define D_INNER  2048
#define D_STATE  16
#define DT_RANK  64
#define D_CONV   4
#define NROWS    (B_SZ * SEQ)             // 4096
#define XPROJ_N  (DT_RANK + 2 * D_STATE)  // 96
#define XPROJ_NPAD 128
#define KSPLIT3  4
#define NCH      16                        // scan chunks
#define CHT      (SEQ / NCH)               // 128 steps per chunk

typedef __nv_bfloat16 bf16;

// ---------------- scratch (static device globals; no allocation allowed) ---
__device__ __align__(256) float g_xz[(size_t)NROWS * (2 * D_INNER)];
__device__ __align__(256) float g_xconv[(size_t)NROWS * D_INNER];
__device__ __align__(256) float g_xdbc[(size_t)NROWS * XPROJ_N];
__device__ __align__(256) float g_dt[(size_t)NROWS * D_INNER];
__device__ __align__(256) float g_part[(size_t)KSPLIT3 * NROWS * XPROJ_NPAD];
// transposed [B, D, L] scan inputs
__device__ __align__(256) float g_dtT[(size_t)B_SZ * D_INNER * SEQ];
__device__ __align__(256) float g_xcT[(size_t)B_SZ * D_INNER * SEQ];
__device__ __align__(256) float g_zT[(size_t)B_SZ * D_INNER * SEQ];
// chunked-scan intermediates [B, D, NCH, 16]
__device__ __align__(256) float g_P[(size_t)B_SZ * D_INNER * NCH * D_STATE];
__device__ __align__(256) float g_S[(size_t)B_SZ * D_INNER * NCH * D_STATE];
__device__ __align__(256) float g_H[(size_t)B_SZ * D_INNER * NCH * D_STATE];
// bf16 split activations
__device__ __align__(256) bf16 g_xh[(size_t)NROWS * D_MODEL];
__device__ __align__(256) bf16 g_xl[(size_t)NROWS * D_MODEL];
__device__ __align__(256) bf16 g_xconvh[(size_t)NROWS * D_INNER];
__device__ __align__(256) bf16 g_xconvl[(size_t)NROWS * D_INNER];
__device__ __align__(256) bf16 g_xdbch[(size_t)NROWS * DT_RANK];
__device__ __align__(256) bf16 g_xdbcl[(size_t)NROWS * DT_RANK];
__device__ __align__(256) bf16 g_yh[(size_t)NROWS * D_INNER];
__device__ __align__(256) bf16 g_yl[(size_t)NROWS * D_INNER];
// bf16 split transposed weights [N, K]
__device__ __align__(256) bf16 g_winT_h[(size_t)(2 * D_INNER) * D_MODEL];
__device__ __align__(256) bf16 g_winT_l[(size_t)(2 * D_INNER) * D_MODEL];
__device__ __align__(256) bf16 g_woutT_h[(size_t)D_MODEL * D_INNER];
__device__ __align__(256) bf16 g_woutT_l[(size_t)D_MODEL * D_INNER];
__device__ __align__(256) bf16 g_wxT_h[(size_t)XPROJ_NPAD * D_INNER];
__device__ __align__(256) bf16 g_wxT_l[(size_t)XPROJ_NPAD * D_INNER];
__device__ __align__(256) bf16 g_wdtT_h[(size_t)D_INNER * DT_RANK];
__device__ __align__(256) bf16 g_wdtT_l[(size_t)D_INNER * DT_RANK];

// ======================= helpers ===========================================
__device__ __forceinline__ uint32_t smem_u32(const void* p) {
    uint32_t a;
    asm("{ .reg .u64 t; cvta.to.shared.u64 t, %1; cvt.u32.u64 %0, t; }"
        : "=r"(a) : "l"(p));
    return a;
}
__device__ __forceinline__ void cp_async16(uint32_t dst, const void* src) {
    asm volatile("cp.async.cg.shared.global [%0], [%1], 16;"
                 :: "r"(dst), "l"(src));
}
#define CP_COMMIT() asm volatile("cp.async.commit_group;")
#define CP_WAIT0()  asm volatile("cp.async.wait_group 0;")

__device__ __forceinline__ void ldsm_x4(uint32_t* r, uint32_t addr) {
    asm volatile("ldmatrix.sync.aligned.m8n8.x4.shared.b16 {%0,%1,%2,%3}, [%4];"
                 : "=r"(r[0]), "=r"(r[1]), "=r"(r[2]), "=r"(r[3]) : "r"(addr));
}

__device__ __forceinline__ void mma16816(float* c, const uint32_t* a,
                                         const uint32_t* b) {
    asm volatile(
        "mma.sync.aligned.m16n8k16.row.col.f32.bf16.bf16.f32 "
        "{%0,%1,%2,%3}, {%4,%5,%6,%7}, {%8,%9}, {%0,%1,%2,%3};\n"
        : "+f"(c[0]), "+f"(c[1]), "+f"(c[2]), "+f"(c[3])
        : "r"(a[0]), "r"(a[1]), "r"(a[2]), "r"(a[3]),
          "r"(b[0]), "r"(b[1]));
}

__device__ __forceinline__ void split_bf16(float v, bf16& h, bf16& l) {
    h = __float2bfloat16_rn(v);
    l = __float2bfloat16_rn(v - __bfloat162float(h));
}

// ===================== GEMM: C[M,N] = A * B^T, 3x bf16 split ==============
#define ROW_BYTES 80u
#define TILE_B    (128u * ROW_BYTES)    // 10240
#define STAGE_B   (4u * TILE_B)         // 40960 (Ah|Al|Bh|Bl)
#define SMEM_TOT  (2u * STAGE_B)        // 81920

__global__ void __launch_bounds__(256)
gemm3x(const bf16* __restrict__ Ah, const bf16* __restrict__ Al,
       const bf16* __restrict__ Bh, const bf16* __restrict__ Bl,
       float* __restrict__ C, int Nc, int K, int kstart_ch, int kch, int ldc,
       const float* __restrict__ bias, int act, size_t partStride)
{
    extern __shared__ __align__(16) char smem_raw[];
    const uint32_t sb = smem_u32(smem_raw);

    kstart_ch += blockIdx.z * kch;          // split-K slice

    const int tid = threadIdx.x;
    const int wid = tid >> 5, lane = tid & 31;
    const int gr = lane >> 2, q = lane & 3;
    const int row0 = blockIdx.y * 128, col0 = blockIdx.x * 128;
    const int warp_m = (wid & 1) * 64, warp_n = (wid >> 1) * 32;

    float* Cout = C + (size_t)blockIdx.z * partStride;

    const bf16* tb0 = Ah + (size_t)row0 * K;
    const bf16* tb1 = Al + (size_t)row0 * K;
    const bf16* tb2 = Bh + (size_t)col0 * K;
    const bf16* tb3 = Bl + (size_t)col0 * K;

    float acc[4][4][4];
#pragma unroll
    for (int i = 0; i < 4; i++)
#pragma unroll
        for (int j = 0; j < 4; j++)
#pragma unroll
            for (int r = 0; r < 4; r++) acc[i][j][r] = 0.f;

    auto load_stage = [&](int c, int s) {
        int koff = (kstart_ch + c) << 5;
#pragma unroll
        for (int i = 0; i < 8; i++) {
            int seg = tid + 256 * i;            // 0..2047
            int buf = seg >> 9;                 // tile id 0..3
            int w   = seg & 511;
            int row = w >> 2, s4 = w & 3;
            const bf16* base = (buf == 0) ? tb0 : (buf == 1) ? tb1
                             : (buf == 2) ? tb2 : tb3;
            const bf16* g = base + (size_t)row * K + koff + s4 * 8;
            uint32_t dst = sb + (uint32_t)s * STAGE_B + (uint32_t)buf * TILE_B
                         + (uint32_t)row * ROW_BYTES + (uint32_t)s4 * 16u;
            cp_async16(dst, g);
        }
    };

    const uint32_t a_row  = (uint32_t)(lane & 15);
    const uint32_t a_koff = (uint32_t)(lane >> 4) * 16u;
    const uint32_t b_row  = (uint32_t)(((lane >> 4) << 3) + (lane & 7));
    const uint32_t b_koff = (uint32_t)((lane >> 3) & 1) * 16u;

    load_stage(0, 0);
    CP_COMMIT();

    for (int c = 0; c < kch; c++) {
        CP_WAIT0();
        __syncthreads();
        if (c + 1 < kch) { load_stage(c + 1, (c + 1) & 1); CP_COMMIT(); }

        const uint32_t st = sb + (uint32_t)(c & 1) * STAGE_B;
        const uint32_t sAh = st;
        const uint32_t sAl = st + TILE_B;
        const uint32_t sBh = st + 2 * TILE_B;
        const uint32_t sBl = st + 3 * TILE_B;

#pragma unroll
        for (int kc = 0; kc < 2; kc++) {
            uint32_t aH[4][4], aL[4][4], bH[8], bL[8];
#pragma unroll
            for (int mt = 0; mt < 4; mt++) {
                uint32_t roff = ((uint32_t)(warp_m + mt * 16) + a_row) * ROW_BYTES
                              + kc * 32u + a_koff;
                ldsm_x4(aH[mt], sAh + roff);
                ldsm_x4(aL[mt], sAl + roff);
            }
            {
                uint32_t r0 = ((uint32_t)warp_n + b_row) * ROW_BYTES
                            + kc * 32u + b_koff;
                uint32_t r1 = r0 + 16u * ROW_BYTES;
                ldsm_x4(bH + 0, sBh + r0);
                ldsm_x4(bH + 4, sBh + r1);
                ldsm_x4(bL + 0, sBl + r0);
                ldsm_x4(bL + 4, sBl + r1);
            }
#pragma unroll
            for (int mt = 0; mt < 4; mt++)
#pragma unroll
                for (int nt = 0; nt < 4; nt++)
                    mma16816(acc[mt][nt], aH[mt], bH + nt * 2);
#pragma unroll
            for (int mt = 0; mt < 4; mt++)
#pragma unroll
                for (int nt = 0; nt < 4; nt++)
                    mma16816(acc[mt][nt], aH[mt], bL + nt * 2);
#pragma unroll
            for (int mt = 0; mt < 4; mt++)
#pragma unroll
                for (int nt = 0; nt < 4; nt++)
                    mma16816(acc[mt][nt], aL[mt], bH + nt * 2);
        }
        __syncthreads();
    }

    // ---------------- epilogue ----------------
#pragma unroll
    for (int mt = 0; mt < 4; mt++) {
#pragma unroll
        for (int nt = 0; nt < 4; nt++) {
            int rg = row0 + warp_m + mt * 16 + gr;
            int cg = col0 + warp_n + nt * 8 + 2 * q;
            float* cc = acc[mt][nt];
#pragma unroll
            for (int half = 0; half < 2; half++) {
                int r = rg + half * 8;
                float v0 = cc[half * 2 + 0];
                float v1 = cc[half * 2 + 1];
                if (bias) { v0 += bias[cg]; v1 += bias[cg + 1]; }
                if (act == 1) {
                    v0 = (v0 > 20.f) ? v0 : log1pf(expf(v0));
                    v1 = (v1 > 20.f) ? v1 : log1pf(expf(v1));
                }
                if (cg + 1 < Nc) {
                    *reinterpret_cast<float2*>(&Cout[(size_t)r * ldc + cg]) =
                        make_float2(v0, v1);
                } else if (cg < Nc) {
                    Cout[(size_t)r * ldc + cg] = v0;
                }
            }
        }
    }
}

// -------- split-K reduce for xproj GEMM: sum partials, write xdbc + dt split
__global__ void reduce3_kernel(const float* __restrict__ part,
                               float* __restrict__ xdbc,
                               bf16* __restrict__ xdh, bf16* __restrict__ xdl)
{
    int i = blockIdx.x * 256 + threadIdx.x;
    if (i >= NROWS * XPROJ_N) return;
    int r = i / XPROJ_N, c = i - r * XPROJ_N;
    const size_t ps = (size_t)NROWS * XPROJ_NPAD;
    float v = 0.f;
#pragma unroll
    for (int p = 0; p < KSPLIT3; p++)
        v += part[p * ps + (size_t)r * XPROJ_NPAD + c];
    xdbc[(size_t)r * XPROJ_N + c] = v;
    if (c < DT_RANK) {
        bf16 h, l;
        split_bf16(v, h, l);
        xdh[(size_t)r * DT_RANK + c] = h;
        xdl[(size_t)r * DT_RANK + c] = l;
    }
}

// ===================== weight transpose + bf16 split =======================
__global__ void wsplit_kernel(const float* __restrict__ W,
                              bf16* __restrict__ Th, bf16* __restrict__ Tl,
                              int K, int N, int Npad)
{
    __shared__ float tile[32][33];
    int kb = blockIdx.y * 32, nb = blockIdx.x * 32;
    int tx = threadIdx.x, ty = threadIdx.y;
#pragma unroll
    for (int i = ty; i < 32; i += 8) {
        int k = kb + i, n = nb + tx;
        tile[i][tx] = (k < K && n < N) ? W[(size_t)k * N + n] : 0.f;
    }
    __syncthreads();
#pragma unroll
    for (int i = ty; i < 32; i += 8) {
        int n = nb + i, k = kb + tx;
        if (n < Npad && k < K) {
            bf16 h, l;
            split_bf16(tile[tx][i], h, l);
            Th[(size_t)n * K + k] = h;
            Tl[(size_t)n * K + k] = l;
        }
    }
}

// ---------------- elementwise fp32 -> bf16 hi/lo split ---------------------
__global__ void fsplit_kernel(const float* __restrict__ X,
                              bf16* __restrict__ H, bf16* __restrict__ L,
                              int n)
{
    int i = blockIdx.x * blockDim.x + threadIdx.x;
    if (i >= n) return;
    bf16 h, l;
    split_bf16(X[i], h, l);
    H[i] = h; L[i] = l;
}

// ---------------- [B*L, stride] column slice -> [B, D, L] transpose --------
__global__ void transpose_kernel(const float* __restrict__ src, int srcStride,
                                 int coloff, float* __restrict__ dst)
{
    __shared__ float tile[32][33];
    int b  = blockIdx.z;
    int l0 = blockIdx.x * 32, d0 = blockIdx.y * 32;
    int tx = threadIdx.x, ty = threadIdx.y;
#pragma unroll
    for (int i = ty; i < 32; i += 8)
        tile[i][tx] = src[(size_t)(b * SEQ + l0 + i) * srcStride + coloff + d0 + tx];
    __syncthreads();
#pragma unroll
    for (int i = ty; i < 32; i += 8)
        dst[(size_t)(b * D_INNER + d0 + i) * SEQ + l0 + tx] = tile[tx][i];
}

// ---------------- causal depthwise conv (width 4) + SiLU + split -----------
__global__ void conv_silu_kernel(const float* __restrict__ xz,
                                 const float* __restrict__ w_conv,
                                 const float* __restrict__ b_conv,
                                 float* __restrict__ xconv,
                                 bf16* __restrict__ xch, bf16* __restrict__ xcl)
{
    int idx = blockIdx.x * blockDim.x + threadIdx.x;
    if (idx >= NROWS * D_INNER) return;
    int d = idx % D_INNER;
    int l = (idx / D_INNER) % SEQ;
    int b = idx / (D_INNER * SEQ);

    float acc = b_conv[d];
    const float* wc = w_conv + d * D_CONV;
#pragma unroll
    for (int k = 0; k < D_CONV; k++) {
        int ls = l - (D_CONV - 1) + k;
        if (ls >= 0)
            acc += xz[((size_t)(b * SEQ + ls)) * (2 * D_INNER) + d] * wc[k];
    }
    float s = 1.f / (1.f + __expf(-acc));
    float v = acc * s;
    xconv[idx] = v;
    bf16 h, lo;
    split_bf16(v, h, lo);
    xch[idx] = h; xcl[idx] = lo;
}

// ========================= chunked selective scan ==========================
// thread id bits: n = t&15, chunk c = (t>>4)&15, d = (t>>8)&2047, b = t>>19
// Phase A: per-chunk affine coefficients  h_out = P*h_in + S
__global__ void __launch_bounds__(256)
scanA_kernel(const float* __restrict__ dtT, const float* __restrict__ xcT,
             const float* __restrict__ xdbc, const float* __restrict__ A_log,
             float* __restrict__ gP, float* __restrict__ gS)
{
    int t = blockIdx.x * 256 + threadIdx.x;
    int n = t & 15, c = (t >> 4) & 15, d = (t >> 8) & 2047, b = t >> 19;

    float An = -expf(A_log[d * D_STATE + n]);
    const float* dtp = dtT + ((size_t)(b * D_INNER + d)) * SEQ + c * CHT;
    const float* xcp = xcT + ((size_t)(b * D_INNER + d)) * SEQ + c * CHT;
    const float* bc  = xdbc + ((size_t)(b * SEQ + c * CHT)) * XPROJ_N;

    float P = 1.f, S = 0.f;
    for (int l0 = 0; l0 < CHT; l0 += 4) {
        float4 dt4 = *reinterpret_cast<const float4*>(dtp + l0);
        float4 xv4 = *reinterpret_cast<const float4*>(xcp + l0);
        float dtv[4] = {dt4.x, dt4.y, dt4.z, dt4.w};
        float xvv[4] = {xv4.x, xv4.y, xv4.z, xv4.w};
#pragma unroll
        for (int j = 0; j < 4; j++) {
            float Bn = bc[DT_RANK + n];
            float a  = __expf(dtv[j] * An);
            S = fmaf(a, S, dtv[j] * xvv[j] * Bn);
            P *= a;
            bc += XPROJ_N;
        }
    }
    gP[t] = P; gS[t] = S;
}

// Phase B: scan chunk boundaries (16 steps) -> initial h per chunk
__global__ void scanB_kernel(const float* __restrict__ gP,
                             const float* __restrict__ gS,
                             float* __restrict__ gH)
{
    int t = blockIdx.x * 256 + threadIdx.x;   // 65536 = B*D*16
    int n = t & 15, d = (t >> 4) & 2047, b = t >> 15;
    size_t base = ((size_t)(b * D_INNER + d)) * (NCH * D_STATE) + n;
    float h = 0.f;
#pragma unroll
    for (int c = 0; c < NCH; c++) {
        gH[base + c * D_STATE] = h;
        h = fmaf(gP[base + c * D_STATE], h, gS[base + c * D_STATE]);
    }
}

// Phase C: replay chunks with correct h_in, reduce y, gate, split-store
__global__ void __launch_bounds__(256)
scanC_kernel(const float* __restrict__ dtT, const float* __restrict__ xcT,
             const float* __restrict__ zT,  const float* __restrict__ xdbc,
             const float* __restrict__ A_log, const float* __restrict__ Dv,
             const float* __restrict__ gH,
             bf16* __restrict__ yh, bf16* __restrict__ yl)
{
    int t = blockIdx.x * 256 + threadIdx.x;
    int n = t & 15, c = (t >> 4) & 15, d = (t >> 8) & 2047, b = t >> 19;

    float An = -expf(A_log[d * D_STATE + n]);
    float Dd = Dv[d];
    const size_t chan = (size_t)(b * D_INNER + d);
    const float* dtp = dtT + chan * SEQ + c * CHT;
    const float* xcp = xcT + chan * SEQ + c * CHT;
    const float* zp  = zT  + chan * SEQ + c * CHT;
    const float* bc  = xdbc + ((size_t)(b * SEQ + c * CHT)) * XPROJ_N;

    float h = gH[t];
    size_t yrow = (size_t)(b * SEQ + c * CHT) * D_INNER + d;

    for (int l0 = 0; l0 < CHT; l0 += 4) {
        float4 dt4 = *reinterpret_cast<const float4*>(dtp + l0);
        float4 xv4 = *reinterpret_cast<const float4*>(xcp + l0);
        float4 z4  = *reinterpret_cast<const float4*>(zp + l0);
        float dtv[4] = {dt4.x, dt4.y, dt4.z, dt4.w};
        float xvv[4] = {xv4.x, xv4.y, xv4.z, xv4.w};
        float zvv[4] = {z4.x, z4.y, z4.z, z4.w};
#pragma unroll
        for (int j = 0; j < 4; j++) {
            float Bn = bc[DT_RANK + n];
            float Cn = bc[DT_RANK + D_STATE + n];
            float a  = __expf(dtv[j] * An);
            h = fmaf(a, h, dtv[j] * xvv[j] * Bn);
            float part = Cn * h;
            part += __shfl_xor_sync(0xffffffffu, part, 1);
            part += __shfl_xor_sync(0xffffffffu, part, 2);
            part += __shfl_xor_sync(0xffffffffu, part, 4);
            part += __shfl_xor_sync(0xffffffffu, part, 8);
            if (n == 0) {
                float z   = zvv[j];
                float sig = 1.f / (1.f + __expf(-z));
                float yv  = (part + xvv[j] * Dd) * (z * sig);
                bf16 hh, ll;
                split_bf16(yv, hh, ll);
                yh[yrow] = hh; yl[yrow] = ll;
            }
            bc += XPROJ_N;
            yrow += D_INNER;
        }
    }
}

// ---------------- launcher -------------------------------------------------
extern "C" void kernel_launch(void* const* d_in, const int* in_sizes, int n_in,
                              void* d_out, int out_size)
{
    const float* x       = (const float*)d_in[0];
    const float* w_in    = (const float*)d_in[1];
    const float* w_conv  = (const float*)d_in[2];
    const float* b_conv  = (const float*)d_in[3];
    const float* w_xproj = (const float*)d_in[4];
    const float* w_dt    = (const float*)d_in[5];
    const float* b_dt    = (const float*)d_in[6];
    const float* A_log   = (const float*)d_in[7];
    const float* Dv      = (const float*)d_in[8];
    const float* w_out   = (const float*)d_in[9];
    float* out = (float*)d_out;

    float *xz, *xconv, *xdbc, *dtb, *part, *dtT, *xcT, *zT, *gP, *gS, *gH;
    bf16 *xh, *xl, *xch, *xcl, *xdh, *xdl, *yh, *yl;
    bf16 *winT_h, *winT_l, *woutT_h, *woutT_l, *wxT_h, *wxT_l, *wdtT_h, *wdtT_l;
    cudaGetSymbolAddress((void**)&xz,      g_xz);
    cudaGetSymbolAddress((void**)&xconv,   g_xconv);
    cudaGetSymbolAddress((void**)&xdbc,    g_xdbc);
    cudaGetSymbolAddress((void**)&dtb,     g_dt);
    cudaGetSymbolAddress((void**)&part,    g_part);
    cudaGetSymbolAddress((void**)&dtT,     g_dtT);
    cudaGetSymbolAddress((void**)&xcT,     g_xcT);
    cudaGetSymbolAddress((void**)&zT,      g_zT);
    cudaGetSymbolAddress((void**)&gP,      g_P);
    cudaGetSymbolAddress((void**)&gS,      g_S);
    cudaGetSymbolAddress((void**)&gH,      g_H);
    cudaGetSymbolAddress((void**)&xh,      g_xh);
    cudaGetSymbolAddress((void**)&xl,      g_xl);
    cudaGetSymbolAddress((void**)&xch,     g_xconvh);
    cudaGetSymbolAddress((void**)&xcl,     g_xconvl);
    cudaGetSymbolAddress((void**)&xdh,     g_xdbch);
    cudaGetSymbolAddress((void**)&xdl,     g_xdbcl);
    cudaGetSymbolAddress((void**)&yh,      g_yh);
    cudaGetSymbolAddress((void**)&yl,      g_yl);
    cudaGetSymbolAddress((void**)&winT_h,  g_winT_h);
    cudaGetSymbolAddress((void**)&winT_l,  g_winT_l);
    cudaGetSymbolAddress((void**)&woutT_h, g_woutT_h);
    cudaGetSymbolAddress((void**)&woutT_l, g_woutT_l);
    cudaGetSymbolAddress((void**)&wxT_h,   g_wxT_h);
    cudaGetSymbolAddress((void**)&wxT_l,   g_wxT_l);
    cudaGetSymbolAddress((void**)&wdtT_h,  g_wdtT_h);
    cudaGetSymbolAddress((void**)&wdtT_l,  g_wdtT_l);

    cudaFuncSetAttribute(gemm3x, cudaFuncAttributeMaxDynamicSharedMemorySize,
                         SMEM_TOT);

    dim3 tb(32, 8);
    fsplit_kernel<<<(NROWS * D_MODEL + 255) / 256, 256>>>(x, xh, xl, NROWS * D_MODEL);
    wsplit_kernel<<<dim3(4096 / 32, 1024 / 32), tb>>>(w_in, winT_h, winT_l,
                                                      D_MODEL, 2 * D_INNER, 2 * D_INNER);
    wsplit_kernel<<<dim3(XPROJ_NPAD / 32, 2048 / 32), tb>>>(w_xproj, wxT_h, wxT_l,
                                                            D_INNER, XPROJ_N, XPROJ_NPAD);
    wsplit_kernel<<<dim3(2048 / 32, 64 / 32), tb>>>(w_dt, wdtT_h, wdtT_l,
                                                    DT_RANK, D_INNER, D_INNER);
    wsplit_kernel<<<dim3(1024 / 32, 2048 / 32), tb>>>(w_out, woutT_h, woutT_l,
                                                      D_INNER, D_MODEL, D_MODEL);

    // 1) xz = x @ w_in                 M=4096 N=4096 K=1024
    gemm3x<<<dim3(32, 32, 1), 256, SMEM_TOT>>>(xh, xl, winT_h, winT_l, xz,
                                               2 * D_INNER, D_MODEL, 0,
                                               D_MODEL / 32, 2 * D_INNER,
                                               nullptr, 0, 0);
    // 2) causal conv + silu (+ bf16 split)
    conv_silu_kernel<<<(NROWS * D_INNER + 255) / 256, 256>>>(
        xz, w_conv, b_conv, xconv, xch, xcl);
    // 3) xproj: split-K=4 into partials, then reduce (+ dt split)
    gemm3x<<<dim3(1, 32, KSPLIT3), 256, SMEM_TOT>>>(
        xch, xcl, wxT_h, wxT_l, part,
        XPROJ_NPAD, D_INNER, 0, (D_INNER / 32) / KSPLIT3, XPROJ_NPAD,
        nullptr, 0, (size_t)NROWS * XPROJ_NPAD);
    reduce3_kernel<<<(NROWS * XPROJ_N + 255) / 256, 256>>>(part, xdbc, xdh, xdl);
    // 4) dt = softplus(xdbc[:, :64] @ w_dt + b_dt)   M=4096 N=2048 K=64
    gemm3x<<<dim3(16, 32, 1), 256, SMEM_TOT>>>(xdh, xdl, wdtT_h, wdtT_l, dtb,
                                               D_INNER, DT_RANK, 0,
                                               DT_RANK / 32, D_INNER,
                                               b_dt, 1, 0);
    // 5) transpose scan inputs to [B, D, L]
    dim3 tg(SEQ / 32, D_INNER / 32, B_SZ);
    transpose_kernel<<<tg, tb>>>(dtb,   D_INNER,     0,       dtT);
    transpose_kernel<<<tg, tb>>>(xconv, D_INNER,     0,       xcT);
    transpose_kernel<<<tg, tb>>>(xz,    2 * D_INNER, D_INNER, zT);
    // 6) chunked scan
    scanA_kernel<<<(B_SZ * D_INNER * NCH * D_STATE) / 256, 256>>>(
        dtT, xcT, xdbc, A_log, gP, gS);
    scanB_kernel<<<(B_SZ * D_INNER * D_STATE) / 256, 256>>>(gP, gS, gH);
    scanC_kernel<<<(B_SZ * D_INNER * NCH * D_STATE) / 256, 256>>>(
        dtT, xcT, zT, xdbc, A_log, Dv, gH, yh, yl);
    // 7) out = y @ w_out               M=4096 N=1024 K=2048
    gemm3x<<<dim3(8, 32, 1), 256, SMEM_TOT>>>(yh, yl, woutT_h, woutT_l, out,
                                              D_MODEL, D_INNER, 0,
                                              D_INNER / 32, D_MODEL,
                                              nullptr, 0, 0);
}

// round 7
// speedup vs baseline: 4.5367x; 1.0283x over previous
#include <cuda_runtime.h>
#include <cuda_bf16.h>
#include <math.h>
#include <cstdint>

#define B_SZ     2
#define SEQ      2048
#define D_MODEL  1024
#define D_INNER  2048
#define D_STATE  16
#define DT_RANK  64
#define D_CONV   4
#define NROWS    (B_SZ * SEQ)             // 4096
#define XPROJ_N  (DT_RANK + 2 * D_STATE)  // 96
#define XPROJ_NPAD 128
#define KSPLIT3  4
#define NCH      16                        // scan chunks
#define CHT      (SEQ / NCH)               // 128 steps per chunk

typedef __nv_bfloat16 bf16;

// ---------------- scratch (static device globals; no allocation allowed) ---
__device__ __align__(256) float g_xz[(size_t)NROWS * (2 * D_INNER)];
__device__ __align__(256) float g_xconv[(size_t)NROWS * D_INNER];
__device__ __align__(256) float g_xdbc[(size_t)NROWS * XPROJ_N];
__device__ __align__(256) float g_dt[(size_t)NROWS * D_INNER];
__device__ __align__(256) float g_part[(size_t)KSPLIT3 * NROWS * XPROJ_NPAD];
// transposed [B, D, L] scan inputs
__device__ __align__(256) float g_dtT[(size_t)B_SZ * D_INNER * SEQ];
__device__ __align__(256) float g_xcT[(size_t)B_SZ * D_INNER * SEQ];
__device__ __align__(256) float g_zT[(size_t)B_SZ * D_INNER * SEQ];
// bf16 split activations
__device__ __align__(256) bf16 g_xh[(size_t)NROWS * D_MODEL];
__device__ __align__(256) bf16 g_xl[(size_t)NROWS * D_MODEL];
__device__ __align__(256) bf16 g_xconvh[(size_t)NROWS * D_INNER];
__device__ __align__(256) bf16 g_xconvl[(size_t)NROWS * D_INNER];
__device__ __align__(256) bf16 g_xdbch[(size_t)NROWS * DT_RANK];
__device__ __align__(256) bf16 g_xdbcl[(size_t)NROWS * DT_RANK];
__device__ __align__(256) bf16 g_yh[(size_t)NROWS * D_INNER];
__device__ __align__(256) bf16 g_yl[(size_t)NROWS * D_INNER];
// bf16 split transposed weights [N, K]
__device__ __align__(256) bf16 g_winT_h[(size_t)(2 * D_INNER) * D_MODEL];
__device__ __align__(256) bf16 g_winT_l[(size_t)(2 * D_INNER) * D_MODEL];
__device__ __align__(256) bf16 g_woutT_h[(size_t)D_MODEL * D_INNER];
__device__ __align__(256) bf16 g_woutT_l[(size_t)D_MODEL * D_INNER];
__device__ __align__(256) bf16 g_wxT_h[(size_t)XPROJ_NPAD * D_INNER];
__device__ __align__(256) bf16 g_wxT_l[(size_t)XPROJ_NPAD * D_INNER];
__device__ __align__(256) bf16 g_wdtT_h[(size_t)D_INNER * DT_RANK];
__device__ __align__(256) bf16 g_wdtT_l[(size_t)D_INNER * DT_RANK];

// ======================= helpers ===========================================
__device__ __forceinline__ uint32_t smem_u32(const void* p) {
    uint32_t a;
    asm("{ .reg .u64 t; cvta.to.shared.u64 t, %1; cvt.u32.u64 %0, t; }"
        : "=r"(a) : "l"(p));
    return a;
}
__device__ __forceinline__ void cp_async16(uint32_t dst, const void* src) {
    asm volatile("cp.async.cg.shared.global [%0], [%1], 16;"
                 :: "r"(dst), "l"(src));
}
#define CP_COMMIT() asm volatile("cp.async.commit_group;")
#define CP_WAIT0()  asm volatile("cp.async.wait_group 0;")

__device__ __forceinline__ void ldsm_x4(uint32_t* r, uint32_t addr) {
    asm volatile("ldmatrix.sync.aligned.m8n8.x4.shared.b16 {%0,%1,%2,%3}, [%4];"
                 : "=r"(r[0]), "=r"(r[1]), "=r"(r[2]), "=r"(r[3]) : "r"(addr));
}

__device__ __forceinline__ void mma16816(float* c, const uint32_t* a,
                                         const uint32_t* b) {
    asm volatile(
        "mma.sync.aligned.m16n8k16.row.col.f32.bf16.bf16.f32 "
        "{%0,%1,%2,%3}, {%4,%5,%6,%7}, {%8,%9}, {%0,%1,%2,%3};\n"
        : "+f"(c[0]), "+f"(c[1]), "+f"(c[2]), "+f"(c[3])
        : "r"(a[0]), "r"(a[1]), "r"(a[2]), "r"(a[3]),
          "r"(b[0]), "r"(b[1]));
}

__device__ __forceinline__ void split_bf16(float v, bf16& h, bf16& l) {
    h = __float2bfloat16_rn(v);
    l = __float2bfloat16_rn(v - __bfloat162float(h));
}

// ===================== GEMM: C[M,N] = A * B^T, 3x bf16 split ==============
#define ROW_BYTES 80u
#define TILE_B    (128u * ROW_BYTES)    // 10240
#define STAGE_B   (4u * TILE_B)         // 40960 (Ah|Al|Bh|Bl)
#define SMEM_TOT  (2u * STAGE_B)        // 81920

__global__ void __launch_bounds__(256)
gemm3x(const bf16* __restrict__ Ah, const bf16* __restrict__ Al,
       const bf16* __restrict__ Bh, const bf16* __restrict__ Bl,
       float* __restrict__ C, int Nc, int K, int kstart_ch, int kch, int ldc,
       const float* __restrict__ bias, int act, size_t partStride)
{
    extern __shared__ __align__(16) char smem_raw[];
    const uint32_t sb = smem_u32(smem_raw);

    kstart_ch += blockIdx.z * kch;          // split-K slice

    const int tid = threadIdx.x;
    const int wid = tid >> 5, lane = tid & 31;
    const int gr = lane >> 2, q = lane & 3;
    const int row0 = blockIdx.y * 128, col0 = blockIdx.x * 128;
    const int warp_m = (wid & 1) * 64, warp_n = (wid >> 1) * 32;

    float* Cout = C + (size_t)blockIdx.z * partStride;

    const bf16* tb0 = Ah + (size_t)row0 * K;
    const bf16* tb1 = Al + (size_t)row0 * K;
    const bf16* tb2 = Bh + (size_t)col0 * K;
    const bf16* tb3 = Bl + (size_t)col0 * K;

    float acc[4][4][4];
#pragma unroll
    for (int i = 0; i < 4; i++)
#pragma unroll
        for (int j = 0; j < 4; j++)
#pragma unroll
            for (int r = 0; r < 4; r++) acc[i][j][r] = 0.f;

    auto load_stage = [&](int c, int s) {
        int koff = (kstart_ch + c) << 5;
#pragma unroll
        for (int i = 0; i < 8; i++) {
            int seg = tid + 256 * i;            // 0..2047
            int buf = seg >> 9;                 // tile id 0..3
            int w   = seg & 511;
            int row = w >> 2, s4 = w & 3;
            const bf16* base = (buf == 0) ? tb0 : (buf == 1) ? tb1
                             : (buf == 2) ? tb2 : tb3;
            const bf16* g = base + (size_t)row * K + koff + s4 * 8;
            uint32_t dst = sb + (uint32_t)s * STAGE_B + (uint32_t)buf * TILE_B
                         + (uint32_t)row * ROW_BYTES + (uint32_t)s4 * 16u;
            cp_async16(dst, g);
        }
    };

    const uint32_t a_row  = (uint32_t)(lane & 15);
    const uint32_t a_koff = (uint32_t)(lane >> 4) * 16u;
    const uint32_t b_row  = (uint32_t)(((lane >> 4) << 3) + (lane & 7));
    const uint32_t b_koff = (uint32_t)((lane >> 3) & 1) * 16u;

    load_stage(0, 0);
    CP_COMMIT();

    for (int c = 0; c < kch; c++) {
        CP_WAIT0();
        __syncthreads();        // all warps' stage-c copies visible; buffer c-1 free
        if (c + 1 < kch) { load_stage(c + 1, (c + 1) & 1); CP_COMMIT(); }

        const uint32_t st = sb + (uint32_t)(c & 1) * STAGE_B;
        const uint32_t sAh = st;
        const uint32_t sAl = st + TILE_B;
        const uint32_t sBh = st + 2 * TILE_B;
        const uint32_t sBl = st + 3 * TILE_B;

#pragma unroll
        for (int kc = 0; kc < 2; kc++) {
            uint32_t aH[4][4], aL[4][4], bH[8], bL[8];
#pragma unroll
            for (int mt = 0; mt < 4; mt++) {
                uint32_t roff = ((uint32_t)(warp_m + mt * 16) + a_row) * ROW_BYTES
                              + kc * 32u + a_koff;
                ldsm_x4(aH[mt], sAh + roff);
                ldsm_x4(aL[mt], sAl + roff);
            }
            {
                uint32_t r0 = ((uint32_t)warp_n + b_row) * ROW_BYTES
                            + kc * 32u + b_koff;
                uint32_t r1 = r0 + 16u * ROW_BYTES;
                ldsm_x4(bH + 0, sBh + r0);
                ldsm_x4(bH + 4, sBh + r1);
                ldsm_x4(bL + 0, sBl + r0);
                ldsm_x4(bL + 4, sBl + r1);
            }
#pragma unroll
            for (int mt = 0; mt < 4; mt++)
#pragma unroll
                for (int nt = 0; nt < 4; nt++)
                    mma16816(acc[mt][nt], aH[mt], bH + nt * 2);
#pragma unroll
            for (int mt = 0; mt < 4; mt++)
#pragma unroll
                for (int nt = 0; nt < 4; nt++)
                    mma16816(acc[mt][nt], aH[mt], bL + nt * 2);
#pragma unroll
            for (int mt = 0; mt < 4; mt++)
#pragma unroll
                for (int nt = 0; nt < 4; nt++)
                    mma16816(acc[mt][nt], aL[mt], bH + nt * 2);
        }
    }

    // ---------------- epilogue ----------------
#pragma unroll
    for (int mt = 0; mt < 4; mt++) {
#pragma unroll
        for (int nt = 0; nt < 4; nt++) {
            int rg = row0 + warp_m + mt * 16 + gr;
            int cg = col0 + warp_n + nt * 8 + 2 * q;
            float* cc = acc[mt][nt];
#pragma unroll
            for (int half = 0; half < 2; half++) {
                int r = rg + half * 8;
                float v0 = cc[half * 2 + 0];
                float v1 = cc[half * 2 + 1];
                if (bias) { v0 += bias[cg]; v1 += bias[cg + 1]; }
                if (act == 1) {
                    v0 = (v0 > 20.f) ? v0 : log1pf(expf(v0));
                    v1 = (v1 > 20.f) ? v1 : log1pf(expf(v1));
                }
                if (cg + 1 < Nc) {
                    *reinterpret_cast<float2*>(&Cout[(size_t)r * ldc + cg]) =
                        make_float2(v0, v1);
                } else if (cg < Nc) {
                    Cout[(size_t)r * ldc + cg] = v0;
                }
            }
        }
    }
}

// -------- split-K reduce for xproj GEMM: sum partials, write xdbc + dt split
__global__ void reduce3_kernel(const float* __restrict__ part,
                               float* __restrict__ xdbc,
                               bf16* __restrict__ xdh, bf16* __restrict__ xdl)
{
    int i = blockIdx.x * 256 + threadIdx.x;
    if (i >= NROWS * XPROJ_N) return;
    int r = i / XPROJ_N, c = i - r * XPROJ_N;
    const size_t ps = (size_t)NROWS * XPROJ_NPAD;
    float v = 0.f;
#pragma unroll
    for (int p = 0; p < KSPLIT3; p++)
        v += part[p * ps + (size_t)r * XPROJ_NPAD + c];
    xdbc[(size_t)r * XPROJ_N + c] = v;
    if (c < DT_RANK) {
        bf16 h, l;
        split_bf16(v, h, l);
        xdh[(size_t)r * DT_RANK + c] = h;
        xdl[(size_t)r * DT_RANK + c] = l;
    }
}

// ===================== weight transpose + bf16 split =======================
__global__ void wsplit_kernel(const float* __restrict__ W,
                              bf16* __restrict__ Th, bf16* __restrict__ Tl,
                              int K, int N, int Npad)
{
    __shared__ float tile[32][33];
    int kb = blockIdx.y * 32, nb = blockIdx.x * 32;
    int tx = threadIdx.x, ty = threadIdx.y;
#pragma unroll
    for (int i = ty; i < 32; i += 8) {
        int k = kb + i, n = nb + tx;
        tile[i][tx] = (k < K && n < N) ? W[(size_t)k * N + n] : 0.f;
    }
    __syncthreads();
#pragma unroll
    for (int i = ty; i < 32; i += 8) {
        int n = nb + i, k = kb + tx;
        if (n < Npad && k < K) {
            bf16 h, l;
            split_bf16(tile[tx][i], h, l);
            Th[(size_t)n * K + k] = h;
            Tl[(size_t)n * K + k] = l;
        }
    }
}

// ---------------- elementwise fp32 -> bf16 hi/lo split ---------------------
__global__ void fsplit_kernel(const float* __restrict__ X,
                              bf16* __restrict__ H, bf16* __restrict__ L,
                              int n)
{
    int i = blockIdx.x * blockDim.x + threadIdx.x;
    if (i >= n) return;
    bf16 h, l;
    split_bf16(X[i], h, l);
    H[i] = h; L[i] = l;
}

// ---------------- [B*L, stride] column slice -> [B, D, L] transpose --------
__global__ void transpose_kernel(const float* __restrict__ src, int srcStride,
                                 int coloff, float* __restrict__ dst)
{
    __shared__ float tile[32][33];
    int b  = blockIdx.z;
    int l0 = blockIdx.x * 32, d0 = blockIdx.y * 32;
    int tx = threadIdx.x, ty = threadIdx.y;
#pragma unroll
    for (int i = ty; i < 32; i += 8)
        tile[i][tx] = src[(size_t)(b * SEQ + l0 + i) * srcStride + coloff + d0 + tx];
    __syncthreads();
#pragma unroll
    for (int i = ty; i < 32; i += 8)
        dst[(size_t)(b * D_INNER + d0 + i) * SEQ + l0 + tx] = tile[tx][i];
}

// ---------------- causal depthwise conv (width 4) + SiLU + split -----------
__global__ void conv_silu_kernel(const float* __restrict__ xz,
                                 const float* __restrict__ w_conv,
                                 const float* __restrict__ b_conv,
                                 float* __restrict__ xconv,
                                 bf16* __restrict__ xch, bf16* __restrict__ xcl)
{
    int idx = blockIdx.x * blockDim.x + threadIdx.x;
    if (idx >= NROWS * D_INNER) return;
    int d = idx % D_INNER;
    int l = (idx / D_INNER) % SEQ;
    int b = idx / (D_INNER * SEQ);

    float acc = b_conv[d];
    const float* wc = w_conv + d * D_CONV;
#pragma unroll
    for (int k = 0; k < D_CONV; k++) {
        int ls = l - (D_CONV - 1) + k;
        if (ls >= 0)
            acc += xz[((size_t)(b * SEQ + ls)) * (2 * D_INNER) + d] * wc[k];
    }
    float s = 1.f / (1.f + __expf(-acc));
    float v = acc * s;
    xconv[idx] = v;
    bf16 h, lo;
    split_bf16(v, h, lo);
    xch[idx] = h; xcl[idx] = lo;
}

// ================== fused chunked selective scan (A+B+C) ===================
// block = one (b, d) channel; 256 threads = 16 chunks x 16 states.
__global__ void __launch_bounds__(256)
scan_fused_kernel(const float* __restrict__ dtT, const float* __restrict__ xcT,
                  const float* __restrict__ zT,  const float* __restrict__ xdbc,
                  const float* __restrict__ A_log, const float* __restrict__ Dv,
                  bf16* __restrict__ yh, bf16* __restrict__ yl)
{
    __shared__ float sP[NCH][D_STATE];
    __shared__ float sS[NCH][D_STATE];

    const int blk = blockIdx.x;            // b*D_INNER + d
    const int d = blk & (D_INNER - 1), b = blk >> 11;
    const int t = threadIdx.x;
    const int n = t & 15, c = t >> 4;

    const float An = -expf(A_log[d * D_STATE + n]);
    const size_t chan = (size_t)blk;
    const float* dtp = dtT + chan * SEQ + c * CHT;
    const float* xcp = xcT + chan * SEQ + c * CHT;
    const float* zp  = zT  + chan * SEQ + c * CHT;
    const float* bc0 = xdbc + ((size_t)(b * SEQ + c * CHT)) * XPROJ_N;

    // ---- Phase A: per-chunk affine coefficients ----
    {
        const float* bc = bc0;
        float P = 1.f, S = 0.f;
        for (int l0 = 0; l0 < CHT; l0 += 4) {
            float4 dt4 = *reinterpret_cast<const float4*>(dtp + l0);
            float4 xv4 = *reinterpret_cast<const float4*>(xcp + l0);
            float dtv[4] = {dt4.x, dt4.y, dt4.z, dt4.w};
            float xvv[4] = {xv4.x, xv4.y, xv4.z, xv4.w};
#pragma unroll
            for (int j = 0; j < 4; j++) {
                float Bn = bc[DT_RANK + n];
                float a  = __expf(dtv[j] * An);
                S = fmaf(a, S, dtv[j] * xvv[j] * Bn);
                P *= a;
                bc += XPROJ_N;
            }
        }
        sP[c][n] = P; sS[c][n] = S;
    }
    __syncthreads();

    // ---- Phase B: per-thread prefix over earlier chunks ----
    float h = 0.f;
    for (int cc = 0; cc < c; cc++)
        h = fmaf(sP[cc][n], h, sS[cc][n]);

    // ---- Phase C: replay with correct h_in, reduce y, gate, split-store ----
    const float Dd = Dv[d];
    const float* bc = bc0;
    size_t yrow = (size_t)(b * SEQ + c * CHT) * D_INNER + d;

    for (int l0 = 0; l0 < CHT; l0 += 4) {
        float4 dt4 = *reinterpret_cast<const float4*>(dtp + l0);
        float4 xv4 = *reinterpret_cast<const float4*>(xcp + l0);
        float4 z4  = *reinterpret_cast<const float4*>(zp + l0);
        float dtv[4] = {dt4.x, dt4.y, dt4.z, dt4.w};
        float xvv[4] = {xv4.x, xv4.y, xv4.z, xv4.w};
        float zvv[4] = {z4.x, z4.y, z4.z, z4.w};
#pragma unroll
        for (int j = 0; j < 4; j++) {
            float Bn = bc[DT_RANK + n];
            float Cn = bc[DT_RANK + D_STATE + n];
            float a  = __expf(dtv[j] * An);
            h = fmaf(a, h, dtv[j] * xvv[j] * Bn);
            float part = Cn * h;
            part += __shfl_xor_sync(0xffffffffu, part, 1);
            part += __shfl_xor_sync(0xffffffffu, part, 2);
            part += __shfl_xor_sync(0xffffffffu, part, 4);
            part += __shfl_xor_sync(0xffffffffu, part, 8);
            if (n == 0) {
                float z   = zvv[j];
                float sig = 1.f / (1.f + __expf(-z));
                float yv  = (part + xvv[j] * Dd) * (z * sig);
                bf16 hh, ll;
                split_bf16(yv, hh, ll);
                yh[yrow] = hh; yl[yrow] = ll;
            }
            bc += XPROJ_N;
            yrow += D_INNER;
        }
    }
}

// ---------------- launcher -------------------------------------------------
extern "C" void kernel_launch(void* const* d_in, const int* in_sizes, int n_in,
                              void* d_out, int out_size)
{
    const float* x       = (const float*)d_in[0];
    const float* w_in    = (const float*)d_in[1];
    const float* w_conv  = (const float*)d_in[2];
    const float* b_conv  = (const float*)d_in[3];
    const float* w_xproj = (const float*)d_in[4];
    const float* w_dt    = (const float*)d_in[5];
    const float* b_dt    = (const float*)d_in[6];
    const float* A_log   = (const float*)d_in[7];
    const float* Dv      = (const float*)d_in[8];
    const float* w_out   = (const float*)d_in[9];
    float* out = (float*)d_out;

    float *xz, *xconv, *xdbc, *dtb, *part, *dtT, *xcT, *zT;
    bf16 *xh, *xl, *xch, *xcl, *xdh, *xdl, *yh, *yl;
    bf16 *winT_h, *winT_l, *woutT_h, *woutT_l, *wxT_h, *wxT_l, *wdtT_h, *wdtT_l;
    cudaGetSymbolAddress((void**)&xz,      g_xz);
    cudaGetSymbolAddress((void**)&xconv,   g_xconv);
    cudaGetSymbolAddress((void**)&xdbc,    g_xdbc);
    cudaGetSymbolAddress((void**)&dtb,     g_dt);
    cudaGetSymbolAddress((void**)&part,    g_part);
    cudaGetSymbolAddress((void**)&dtT,     g_dtT);
    cudaGetSymbolAddress((void**)&xcT,     g_xcT);
    cudaGetSymbolAddress((void**)&zT,      g_zT);
    cudaGetSymbolAddress((void**)&xh,      g_xh);
    cudaGetSymbolAddress((void**)&xl,      g_xl);
    cudaGetSymbolAddress((void**)&xch,     g_xconvh);
    cudaGetSymbolAddress((void**)&xcl,     g_xconvl);
    cudaGetSymbolAddress((void**)&xdh,     g_xdbch);
    cudaGetSymbolAddress((void**)&xdl,     g_xdbcl);
    cudaGetSymbolAddress((void**)&yh,      g_yh);
    cudaGetSymbolAddress((void**)&yl,      g_yl);
    cudaGetSymbolAddress((void**)&winT_h,  g_winT_h);
    cudaGetSymbolAddress((void**)&winT_l,  g_winT_l);
    cudaGetSymbolAddress((void**)&woutT_h, g_woutT_h);
    cudaGetSymbolAddress((void**)&woutT_l, g_woutT_l);
    cudaGetSymbolAddress((void**)&wxT_h,   g_wxT_h);
    cudaGetSymbolAddress((void**)&wxT_l,   g_wxT_l);
    cudaGetSymbolAddress((void**)&wdtT_h,  g_wdtT_h);
    cudaGetSymbolAddress((void**)&wdtT_l,  g_wdtT_l);

    cudaFuncSetAttribute(gemm3x, cudaFuncAttributeMaxDynamicSharedMemorySize,
                         SMEM_TOT);

    dim3 tb(32, 8);
    // launch 0-2: prep needed for gemm1 (gemm1 lands at index 3 for ncu)
    fsplit_kernel<<<(NROWS * D_MODEL + 255) / 256, 256>>>(x, xh, xl, NROWS * D_MODEL);
    wsplit_kernel<<<dim3(4096 / 32, 1024 / 32), tb>>>(w_in, winT_h, winT_l,
                                                      D_MODEL, 2 * D_INNER, 2 * D_INNER);
    wsplit_kernel<<<dim3(XPROJ_NPAD / 32, 2048 / 32), tb>>>(w_xproj, wxT_h, wxT_l,
                                                            D_INNER, XPROJ_N, XPROJ_NPAD);
    // launch 3: xz = x @ w_in          M=4096 N=4096 K=1024   <-- profiled
    gemm3x<<<dim3(32, 32, 1), 256, SMEM_TOT>>>(xh, xl, winT_h, winT_l, xz,
                                               2 * D_INNER, D_MODEL, 0,
                                               D_MODEL / 32, 2 * D_INNER,
                                               nullptr, 0, 0);
    // remaining weight splits (needed later)
    wsplit_kernel<<<dim3(2048 / 32, 64 / 32), tb>>>(w_dt, wdtT_h, wdtT_l,
                                                    DT_RANK, D_INNER, D_INNER);
    wsplit_kernel<<<dim3(1024 / 32, 2048 / 32), tb>>>(w_out, woutT_h, woutT_l,
                                                      D_INNER, D_MODEL, D_MODEL);
    // causal conv + silu (+ bf16 split)
    conv_silu_kernel<<<(NROWS * D_INNER + 255) / 256, 256>>>(
        xz, w_conv, b_conv, xconv, xch, xcl);
    // xproj: split-K=4 into partials, then reduce (+ dt split)
    gemm3x<<<dim3(1, 32, KSPLIT3), 256, SMEM_TOT>>>(
        xch, xcl, wxT_h, wxT_l, part,
        XPROJ_NPAD, D_INNER, 0, (D_INNER / 32) / KSPLIT3, XPROJ_NPAD,
        nullptr, 0, (size_t)NROWS * XPROJ_NPAD);
    reduce3_kernel<<<(NROWS * XPROJ_N + 255) / 256, 256>>>(part, xdbc, xdh, xdl);
    // dt = softplus(xdbc[:, :64] @ w_dt + b_dt)   M=4096 N=2048 K=64
    gemm3x<<<dim3(16, 32, 1), 256, SMEM_TOT>>>(xdh, xdl, wdtT_h, wdtT_l, dtb,
                                               D_INNER, DT_RANK, 0,
                                               DT_RANK / 32, D_INNER,
                                               b_dt, 1, 0);
    // transpose scan inputs to [B, D, L]
    dim3 tg(SEQ / 32, D_INNER / 32, B_SZ);
    transpose_kernel<<<tg, tb>>>(dtb,   D_INNER,     0,       dtT);
    transpose_kernel<<<tg, tb>>>(xconv, D_INNER,     0,       xcT);
    transpose_kernel<<<tg, tb>>>(xz,    2 * D_INNER, D_INNER, zT);
    // fused chunked scan (A+B+C in one kernel)
    scan_fused_kernel<<<B_SZ * D_INNER, 256>>>(
        dtT, xcT, zT, xdbc, A_log, Dv, yh, yl);
    // out = y @ w_out                  M=4096 N=1024 K=2048
    gemm3x<<<dim3(8, 32, 1), 256, SMEM_TOT>>>(yh, yl, woutT_h, woutT_l, out,
                                              D_MODEL, D_INNER, 0,
                                              D_INNER / 32, D_MODEL,
                                              nullptr, 0, 0);
}

// round 9
// speedup vs baseline: 4.6680x; 1.0289x over previous
#include <cuda_runtime.h>
#include <cuda_bf16.h>
#include <math.h>
#include <cstdint>

#define B_SZ     2
#define SEQ      2048
#define D_MODEL  1024
#define D_INNER  2048
#define D_STATE  16
#define DT_RANK  64
#define D_CONV   4
#define NROWS    (B_SZ * SEQ)             // 4096
#define XPROJ_N  (DT_RANK + 2 * D_STATE)  // 96
#define XPROJ_NPAD 128
#define KSPLIT3  4
#define NCH      16                        // scan chunks
#define CHT      (SEQ / NCH)               // 128 steps per chunk

typedef __nv_bfloat16 bf16;

// ---------------- scratch (static device globals; no allocation allowed) ---
__device__ __align__(256) float g_xz[(size_t)NROWS * (2 * D_INNER)];
__device__ __align__(256) float g_xdbc[(size_t)NROWS * XPROJ_N];
__device__ __align__(256) float g_part[(size_t)KSPLIT3 * NROWS * XPROJ_NPAD];
// transposed [d][b*SEQ+l] scan inputs
__device__ __align__(256) float g_dtT[(size_t)D_INNER * NROWS];
__device__ __align__(256) float g_xcT[(size_t)D_INNER * NROWS];
__device__ __align__(256) float g_zT[(size_t)D_INNER * NROWS];
// bf16 split activations
__device__ __align__(256) bf16 g_xh[(size_t)NROWS * D_MODEL];
__device__ __align__(256) bf16 g_xl[(size_t)NROWS * D_MODEL];
__device__ __align__(256) bf16 g_xconvh[(size_t)NROWS * D_INNER];
__device__ __align__(256) bf16 g_xconvl[(size_t)NROWS * D_INNER];
__device__ __align__(256) bf16 g_xdbch[(size_t)NROWS * DT_RANK];
__device__ __align__(256) bf16 g_xdbcl[(size_t)NROWS * DT_RANK];
__device__ __align__(256) bf16 g_yh[(size_t)NROWS * D_INNER];
__device__ __align__(256) bf16 g_yl[(size_t)NROWS * D_INNER];
// bf16 split transposed weights [N, K]
__device__ __align__(256) bf16 g_winT_h[(size_t)(2 * D_INNER) * D_MODEL];
__device__ __align__(256) bf16 g_winT_l[(size_t)(2 * D_INNER) * D_MODEL];
__device__ __align__(256) bf16 g_woutT_h[(size_t)D_MODEL * D_INNER];
__device__ __align__(256) bf16 g_woutT_l[(size_t)D_MODEL * D_INNER];
__device__ __align__(256) bf16 g_wxT_h[(size_t)XPROJ_NPAD * D_INNER];
__device__ __align__(256) bf16 g_wxT_l[(size_t)XPROJ_NPAD * D_INNER];
__device__ __align__(256) bf16 g_wdtT_h[(size_t)D_INNER * DT_RANK];
__device__ __align__(256) bf16 g_wdtT_l[(size_t)D_INNER * DT_RANK];

// ======================= helpers ===========================================
__device__ __forceinline__ uint32_t smem_u32(const void* p) {
    uint32_t a;
    asm("{ .reg .u64 t; cvta.to.shared.u64 t, %1; cvt.u32.u64 %0, t; }"
        : "=r"(a) : "l"(p));
    return a;
}
__device__ __forceinline__ void cp_async16(uint32_t dst, const void* src) {
    asm volatile("cp.async.cg.shared.global [%0], [%1], 16;"
                 :: "r"(dst), "l"(src));
}
#define CP_COMMIT() asm volatile("cp.async.commit_group;")
#define CP_WAIT0()  asm volatile("cp.async.wait_group 0;")

__device__ __forceinline__ void ldsm_x4(uint32_t* r, uint32_t addr) {
    asm volatile("ldmatrix.sync.aligned.m8n8.x4.shared.b16 {%0,%1,%2,%3}, [%4];"
                 : "=r"(r[0]), "=r"(r[1]), "=r"(r[2]), "=r"(r[3]) : "r"(addr));
}

__device__ __forceinline__ void mma16816(float* c, const uint32_t* a,
                                         const uint32_t* b) {
    asm volatile(
        "mma.sync.aligned.m16n8k16.row.col.f32.bf16.bf16.f32 "
        "{%0,%1,%2,%3}, {%4,%5,%6,%7}, {%8,%9}, {%0,%1,%2,%3};\n"
        : "+f"(c[0]), "+f"(c[1]), "+f"(c[2]), "+f"(c[3])
        : "r"(a[0]), "r"(a[1]), "r"(a[2]), "r"(a[3]),
          "r"(b[0]), "r"(b[1]));
}

__device__ __forceinline__ void split_bf16(float v, bf16& h, bf16& l) {
    h = __float2bfloat16_rn(v);
    l = __float2bfloat16_rn(v - __bfloat162float(h));
}

// ===================== GEMM: C[M,N] = A * B^T, 3x bf16 split ==============
// act: 0 none; 1 softplus + column bias; 2 softplus + ROW bias.
#define ROW_BYTES 80u
#define TILE_B    (128u * ROW_BYTES)    // 10240
#define STAGE_B   (4u * TILE_B)         // 40960 (Ah|Al|Bh|Bl)
#define SMEM_TOT  (2u * STAGE_B)        // 81920

__global__ void __launch_bounds__(256)
gemm3x(const bf16* __restrict__ Ah, const bf16* __restrict__ Al,
       const bf16* __restrict__ Bh, const bf16* __restrict__ Bl,
       float* __restrict__ C, int Nc, int K, int kstart_ch, int kch, int ldc,
       const float* __restrict__ bias, int act, size_t partStride)
{
    extern __shared__ __align__(16) char smem_raw[];
    const uint32_t sb = smem_u32(smem_raw);

    kstart_ch += blockIdx.z * kch;          // split-K slice

    const int tid = threadIdx.x;
    const int wid = tid >> 5, lane = tid & 31;
    const int gr = lane >> 2, q = lane & 3;
    const int row0 = blockIdx.y * 128, col0 = blockIdx.x * 128;
    const int warp_m = (wid & 1) * 64, warp_n = (wid >> 1) * 32;

    float* Cout = C + (size_t)blockIdx.z * partStride;

    const bf16* tb0 = Ah + (size_t)row0 * K;
    const bf16* tb1 = Al + (size_t)row0 * K;
    const bf16* tb2 = Bh + (size_t)col0 * K;
    const bf16* tb3 = Bl + (size_t)col0 * K;

    float acc[4][4][4];
#pragma unroll
    for (int i = 0; i < 4; i++)
#pragma unroll
        for (int j = 0; j < 4; j++)
#pragma unroll
            for (int r = 0; r < 4; r++) acc[i][j][r] = 0.f;

    auto load_stage = [&](int c, int s) {
        int koff = (kstart_ch + c) << 5;
#pragma unroll
        for (int i = 0; i < 8; i++) {
            int seg = tid + 256 * i;            // 0..2047
            int buf = seg >> 9;                 // tile id 0..3
            int w   = seg & 511;
            int row = w >> 2, s4 = w & 3;
            const bf16* base = (buf == 0) ? tb0 : (buf == 1) ? tb1
                             : (buf == 2) ? tb2 : tb3;
            const bf16* g = base + (size_t)row * K + koff + s4 * 8;
            uint32_t dst = sb + (uint32_t)s * STAGE_B + (uint32_t)buf * TILE_B
                         + (uint32_t)row * ROW_BYTES + (uint32_t)s4 * 16u;
            cp_async16(dst, g);
        }
    };

    const uint32_t a_row  = (uint32_t)(lane & 15);
    const uint32_t a_koff = (uint32_t)(lane >> 4) * 16u;
    const uint32_t b_row  = (uint32_t)(((lane >> 4) << 3) + (lane & 7));
    const uint32_t b_koff = (uint32_t)((lane >> 3) & 1) * 16u;

    load_stage(0, 0);
    CP_COMMIT();

    for (int c = 0; c < kch; c++) {
        CP_WAIT0();
        __syncthreads();
        if (c + 1 < kch) { load_stage(c + 1, (c + 1) & 1); CP_COMMIT(); }

        const uint32_t st = sb + (uint32_t)(c & 1) * STAGE_B;
        const uint32_t sAh = st;
        const uint32_t sAl = st + TILE_B;
        const uint32_t sBh = st + 2 * TILE_B;
        const uint32_t sBl = st + 3 * TILE_B;

#pragma unroll
        for (int kc = 0; kc < 2; kc++) {
            uint32_t aH[4][4], aL[4][4], bH[8], bL[8];
#pragma unroll
            for (int mt = 0; mt < 4; mt++) {
                uint32_t roff = ((uint32_t)(warp_m + mt * 16) + a_row) * ROW_BYTES
                              + kc * 32u + a_koff;
                ldsm_x4(aH[mt], sAh + roff);
                ldsm_x4(aL[mt], sAl + roff);
            }
            {
                uint32_t r0 = ((uint32_t)warp_n + b_row) * ROW_BYTES
                            + kc * 32u + b_koff;
                uint32_t r1 = r0 + 16u * ROW_BYTES;
                ldsm_x4(bH + 0, sBh + r0);
                ldsm_x4(bH + 4, sBh + r1);
                ldsm_x4(bL + 0, sBl + r0);
                ldsm_x4(bL + 4, sBl + r1);
            }
#pragma unroll
            for (int mt = 0; mt < 4; mt++)
#pragma unroll
                for (int nt = 0; nt < 4; nt++)
                    mma16816(acc[mt][nt], aH[mt], bH + nt * 2);
#pragma unroll
            for (int mt = 0; mt < 4; mt++)
#pragma unroll
                for (int nt = 0; nt < 4; nt++)
                    mma16816(acc[mt][nt], aH[mt], bL + nt * 2);
#pragma unroll
            for (int mt = 0; mt < 4; mt++)
#pragma unroll
                for (int nt = 0; nt < 4; nt++)
                    mma16816(acc[mt][nt], aL[mt], bH + nt * 2);
        }
    }

    // ---------------- epilogue ----------------
#pragma unroll
    for (int mt = 0; mt < 4; mt++) {
#pragma unroll
        for (int nt = 0; nt < 4; nt++) {
            int rg = row0 + warp_m + mt * 16 + gr;
            int cg = col0 + warp_n + nt * 8 + 2 * q;
            float* cc = acc[mt][nt];
#pragma unroll
            for (int half = 0; half < 2; half++) {
                int r = rg + half * 8;
                float v0 = cc[half * 2 + 0];
                float v1 = cc[half * 2 + 1];
                if (bias) {
                    if (act == 2) { float bb = bias[r]; v0 += bb; v1 += bb; }
                    else          { v0 += bias[cg]; v1 += bias[cg + 1]; }
                }
                if (act) {
                    v0 = (v0 > 20.f) ? v0 : log1pf(expf(v0));
                    v1 = (v1 > 20.f) ? v1 : log1pf(expf(v1));
                }
                if (cg + 1 < Nc) {
                    *reinterpret_cast<float2*>(&Cout[(size_t)r * ldc + cg]) =
                        make_float2(v0, v1);
                } else if (cg < Nc) {
                    Cout[(size_t)r * ldc + cg] = v0;
                }
            }
        }
    }
}

// -------- split-K reduce for xproj GEMM: sum partials, write xdbc + dt split
__global__ void reduce3_kernel(const float* __restrict__ part,
                               float* __restrict__ xdbc,
                               bf16* __restrict__ xdh, bf16* __restrict__ xdl)
{
    int i = blockIdx.x * 256 + threadIdx.x;
    if (i >= NROWS * XPROJ_N) return;
    int r = i / XPROJ_N, c = i - r * XPROJ_N;
    const size_t ps = (size_t)NROWS * XPROJ_NPAD;
    float v = 0.f;
#pragma unroll
    for (int p = 0; p < KSPLIT3; p++)
        v += part[p * ps + (size_t)r * XPROJ_NPAD + c];
    xdbc[(size_t)r * XPROJ_N + c] = v;
    if (c < DT_RANK) {
        bf16 h, l;
        split_bf16(v, h, l);
        xdh[(size_t)r * DT_RANK + c] = h;
        xdl[(size_t)r * DT_RANK + c] = l;
    }
}

// ===================== weight transpose + bf16 split =======================
__global__ void wsplit_kernel(const float* __restrict__ W,
                              bf16* __restrict__ Th, bf16* __restrict__ Tl,
                              int K, int N, int Npad)
{
    __shared__ float tile[32][33];
    int kb = blockIdx.y * 32, nb = blockIdx.x * 32;
    int tx = threadIdx.x, ty = threadIdx.y;
#pragma unroll
    for (int i = ty; i < 32; i += 8) {
        int k = kb + i, n = nb + tx;
        tile[i][tx] = (k < K && n < N) ? W[(size_t)k * N + n] : 0.f;
    }
    __syncthreads();
#pragma unroll
    for (int i = ty; i < 32; i += 8) {
        int n = nb + i, k = kb + tx;
        if (n < Npad && k < K) {
            bf16 h, l;
            split_bf16(tile[tx][i], h, l);
            Th[(size_t)n * K + k] = h;
            Tl[(size_t)n * K + k] = l;
        }
    }
}

// ---------------- elementwise fp32 -> bf16 hi/lo split ---------------------
__global__ void fsplit_kernel(const float* __restrict__ X,
                              bf16* __restrict__ H, bf16* __restrict__ L,
                              int n)
{
    int i = blockIdx.x * blockDim.x + threadIdx.x;
    if (i >= n) return;
    bf16 h, l;
    split_bf16(X[i], h, l);
    H[i] = h; L[i] = l;
}

// ====== fused causal conv + SiLU + transposes (one pass over xz) ===========
// Writes: xcT [d][b*SEQ+l] fp32, zT [d][b*SEQ+l] fp32,
//         xch/xcl [b*SEQ+l][d] bf16 split (for the xproj GEMM).
__global__ void convT_kernel(const float* __restrict__ xz,
                             const float* __restrict__ w_conv,
                             const float* __restrict__ b_conv,
                             float* __restrict__ xcT, float* __restrict__ zT,
                             bf16* __restrict__ xch, bf16* __restrict__ xcl)
{
    __shared__ float tin[35][33];
    __shared__ float tout[32][33];
    __shared__ float tz[32][33];
    const int b  = blockIdx.z;
    const int l0 = blockIdx.x * 32, d0 = blockIdx.y * 32;
    const int tx = threadIdx.x, ty = threadIdx.y;     // 32 x 8

    for (int j = ty; j < 35; j += 8) {
        int l = l0 - 3 + j;
        tin[j][tx] = (l >= 0) ? xz[(size_t)(b * SEQ + l) * (2 * D_INNER) + d0 + tx]
                              : 0.f;
    }
#pragma unroll
    for (int i = ty; i < 32; i += 8)
        tz[i][tx] = xz[(size_t)(b * SEQ + l0 + i) * (2 * D_INNER) + D_INNER + d0 + tx];
    __syncthreads();

    const float w0 = w_conv[(d0 + tx) * D_CONV + 0];
    const float w1 = w_conv[(d0 + tx) * D_CONV + 1];
    const float w2 = w_conv[(d0 + tx) * D_CONV + 2];
    const float w3 = w_conv[(d0 + tx) * D_CONV + 3];
    const float bc = b_conv[d0 + tx];
#pragma unroll
    for (int i = ty; i < 32; i += 8) {
        float acc = bc + tin[i][tx] * w0 + tin[i + 1][tx] * w1
                       + tin[i + 2][tx] * w2 + tin[i + 3][tx] * w3;
        float s = 1.f / (1.f + __expf(-acc));
        float v = acc * s;
        tout[i][tx] = v;
        bf16 h, l;
        split_bf16(v, h, l);
        size_t ro = (size_t)(b * SEQ + l0 + i) * D_INNER + d0 + tx;
        xch[ro] = h; xcl[ro] = l;
    }
    __syncthreads();
#pragma unroll
    for (int i = ty; i < 32; i += 8) {
        size_t o = (size_t)(d0 + i) * NROWS + b * SEQ + l0 + tx;
        xcT[o] = tout[tx][i];
        zT[o]  = tz[tx][i];
    }
}

// ================== fused chunked selective scan (A+B+C) ===================
// block = one (b, d) channel; 256 threads = 16 chunks x 16 states.
// transposed inputs use layout [d][b*SEQ + l].
__global__ void __launch_bounds__(256)
scan_fused_kernel(const float* __restrict__ dtT, const float* __restrict__ xcT,
                  const float* __restrict__ zT,  const float* __restrict__ xdbc,
                  const float* __restrict__ A_log, const float* __restrict__ Dv,
                  bf16* __restrict__ yh, bf16* __restrict__ yl)
{
    __shared__ float sP[NCH][D_STATE];
    __shared__ float sS[NCH][D_STATE];

    const int blk = blockIdx.x;            // b*D_INNER + d
    const int d = blk & (D_INNER - 1), b = blk >> 11;
    const int t = threadIdx.x;
    const int n = t & 15, c = t >> 4;

    const float An = -expf(A_log[d * D_STATE + n]);
    const size_t chan = (size_t)d * NROWS + b * SEQ;
    const float* dtp = dtT + chan + c * CHT;
    const float* xcp = xcT + chan + c * CHT;
    const float* zp  = zT  + chan + c * CHT;
    const float* bc0 = xdbc + ((size_t)(b * SEQ + c * CHT)) * XPROJ_N;

    // ---- Phase A: per-chunk affine coefficients ----
    {
        const float* bc = bc0;
        float P = 1.f, S = 0.f;
        for (int l0 = 0; l0 < CHT; l0 += 4) {
            float4 dt4 = *reinterpret_cast<const float4*>(dtp + l0);
            float4 xv4 = *reinterpret_cast<const float4*>(xcp + l0);
            float dtv[4] = {dt4.x, dt4.y, dt4.z, dt4.w};
            float xvv[4] = {xv4.x, xv4.y, xv4.z, xv4.w};
#pragma unroll
            for (int j = 0; j < 4; j++) {
                float Bn = bc[DT_RANK + n];
                float a  = __expf(dtv[j] * An);
                S = fmaf(a, S, dtv[j] * xvv[j] * Bn);
                P *= a;
                bc += XPROJ_N;
            }
        }
        sP[c][n] = P; sS[c][n] = S;
    }
    __syncthreads();

    // ---- Phase B: per-thread prefix over earlier chunks ----
    float h = 0.f;
    for (int cc = 0; cc < c; cc++)
        h = fmaf(sP[cc][n], h, sS[cc][n]);

    // ---- Phase C: replay with correct h_in, reduce y, gate, split-store ----
    const float Dd = Dv[d];
    const float* bc = bc0;
    size_t yrow = (size_t)(b * SEQ + c * CHT) * D_INNER + d;

    for (int l0 = 0; l0 < CHT; l0 += 4) {
        float4 dt4 = *reinterpret_cast<const float4*>(dtp + l0);
        float4 xv4 = *reinterpret_cast<const float4*>(xcp + l0);
        float4 z4  = *reinterpret_cast<const float4*>(zp + l0);
        float dtv[4] = {dt4.x, dt4.y, dt4.z, dt4.w};
        float xvv[4] = {xv4.x, xv4.y, xv4.z, xv4.w};
        float zvv[4] = {z4.x, z4.y, z4.z, z4.w};
#pragma unroll
        for (int j = 0; j < 4; j++) {
            float Bn = bc[DT_RANK + n];
            float Cn = bc[DT_RANK + D_STATE + n];
            float a  = __expf(dtv[j] * An);
            h = fmaf(a, h, dtv[j] * xvv[j] * Bn);
            float part = Cn * h;
            part += __shfl_xor_sync(0xffffffffu, part, 1);
            part += __shfl_xor_sync(0xffffffffu, part, 2);
            part += __shfl_xor_sync(0xffffffffu, part, 4);
            part += __shfl_xor_sync(0xffffffffu, part, 8);
            if (n == 0) {
                float z   = zvv[j];
                float sig = 1.f / (1.f + __expf(-z));
                float yv  = (part + xvv[j] * Dd) * (z * sig);
                bf16 hh, ll;
                split_bf16(yv, hh, ll);
                yh[yrow] = hh; yl[yrow] = ll;
            }
            bc += XPROJ_N;
            yrow += D_INNER;
        }
    }
}

// ---------------- launcher -------------------------------------------------
extern "C" void kernel_launch(void* const* d_in, const int* in_sizes, int n_in,
                              void* d_out, int out_size)
{
    const float* x       = (const float*)d_in[0];
    const float* w_in    = (const float*)d_in[1];
    const float* w_conv  = (const float*)d_in[2];
    const float* b_conv  = (const float*)d_in[3];
    const float* w_xproj = (const float*)d_in[4];
    const float* w_dt    = (const float*)d_in[5];
    const float* b_dt    = (const float*)d_in[6];
    const float* A_log   = (const float*)d_in[7];
    const float* Dv      = (const float*)d_in[8];
    const float* w_out   = (const float*)d_in[9];
    float* out = (float*)d_out;

    float *xz, *xdbc, *part, *dtT, *xcT, *zT;
    bf16 *xh, *xl, *xch, *xcl, *xdh, *xdl, *yh, *yl;
    bf16 *winT_h, *winT_l, *woutT_h, *woutT_l, *wxT_h, *wxT_l, *wdtT_h, *wdtT_l;
    cudaGetSymbolAddress((void**)&xz,      g_xz);
    cudaGetSymbolAddress((void**)&xdbc,    g_xdbc);
    cudaGetSymbolAddress((void**)&part,    g_part);
    cudaGetSymbolAddress((void**)&dtT,     g_dtT);
    cudaGetSymbolAddress((void**)&xcT,     g_xcT);
    cudaGetSymbolAddress((void**)&zT,      g_zT);
    cudaGetSymbolAddress((void**)&xh,      g_xh);
    cudaGetSymbolAddress((void**)&xl,      g_xl);
    cudaGetSymbolAddress((void**)&xch,     g_xconvh);
    cudaGetSymbolAddress((void**)&xcl,     g_xconvl);
    cudaGetSymbolAddress((void**)&xdh,     g_xdbch);
    cudaGetSymbolAddress((void**)&xdl,     g_xdbcl);
    cudaGetSymbolAddress((void**)&yh,      g_yh);
    cudaGetSymbolAddress((void**)&yl,      g_yl);
    cudaGetSymbolAddress((void**)&winT_h,  g_winT_h);
    cudaGetSymbolAddress((void**)&winT_l,  g_winT_l);
    cudaGetSymbolAddress((void**)&woutT_h, g_woutT_h);
    cudaGetSymbolAddress((void**)&woutT_l, g_woutT_l);
    cudaGetSymbolAddress((void**)&wxT_h,   g_wxT_h);
    cudaGetSymbolAddress((void**)&wxT_l,   g_wxT_l);
    cudaGetSymbolAddress((void**)&wdtT_h,  g_wdtT_h);
    cudaGetSymbolAddress((void**)&wdtT_l,  g_wdtT_l);

    cudaFuncSetAttribute(gemm3x, cudaFuncAttributeMaxDynamicSharedMemorySize,
                         SMEM_TOT);

    dim3 tb(32, 8);
    // launches 0-2: prep for gemm1 (gemm1 stays at ncu index 3)
    fsplit_kernel<<<(NROWS * D_MODEL + 255) / 256, 256>>>(x, xh, xl, NROWS * D_MODEL);
    wsplit_kernel<<<dim3(4096 / 32, 1024 / 32), tb>>>(w_in, winT_h, winT_l,
                                                      D_MODEL, 2 * D_INNER, 2 * D_INNER);
    wsplit_kernel<<<dim3(XPROJ_NPAD / 32, 2048 / 32), tb>>>(w_xproj, wxT_h, wxT_l,
                                                            D_INNER, XPROJ_N, XPROJ_NPAD);
    // launch 3: xz = x @ w_in          M=4096 N=4096 K=1024   <-- profiled
    gemm3x<<<dim3(32, 32, 1), 256, SMEM_TOT>>>(xh, xl, winT_h, winT_l, xz,
                                               2 * D_INNER, D_MODEL, 0,
                                               D_MODEL / 32, 2 * D_INNER,
                                               nullptr, 0, 0);
    // remaining weight splits
    wsplit_kernel<<<dim3(2048 / 32, 64 / 32), tb>>>(w_dt, wdtT_h, wdtT_l,
                                                    DT_RANK, D_INNER, D_INNER);
    wsplit_kernel<<<dim3(1024 / 32, 2048 / 32), tb>>>(w_out, woutT_h, woutT_l,
                                                      D_INNER, D_MODEL, D_MODEL);
    // fused conv + silu + transposes (xcT, zT, xch, xcl in one pass)
    convT_kernel<<<dim3(SEQ / 32, D_INNER / 32, B_SZ), tb>>>(
        xz, w_conv, b_conv, xcT, zT, xch, xcl);
    // xproj: split-K=4 into partials, then reduce (+ dt-rank split)
    gemm3x<<<dim3(1, 32, KSPLIT3), 256, SMEM_TOT>>>(
        xch, xcl, wxT_h, wxT_l, part,
        XPROJ_NPAD, D_INNER, 0, (D_INNER / 32) / KSPLIT3, XPROJ_NPAD,
        nullptr, 0, (size_t)NROWS * XPROJ_NPAD);
    reduce3_kernel<<<(NROWS * XPROJ_N + 255) / 256, 256>>>(part, xdbc, xdh, xdl);
    // dtT[d][b*L+l] = softplus(wdtT @ xdbc_dt^T + b_dt[d])  (transposed output)
    gemm3x<<<dim3(NROWS / 128, D_INNER / 128, 1), 256, SMEM_TOT>>>(
        wdtT_h, wdtT_l, xdh, xdl, dtT,
        NROWS, DT_RANK, 0, DT_RANK / 32, NROWS,
        b_dt, 2, 0);
    // fused chunked scan (A+B+C in one kernel)
    scan_fused_kernel<<<B_SZ * D_INNER, 256>>>(
        dtT, xcT, zT, xdbc, A_log, Dv, yh, yl);
    // out = y @ w_out                  M=4096 N=1024 K=2048
    gemm3x<<<dim3(8, 32, 1), 256, SMEM_TOT>>>(yh, yl, woutT_h, woutT_l, out,
                                              D_MODEL, D_INNER, 0,
                                              D_INNER / 32, D_MODEL,
                                              nullptr, 0, 0);
}

// round 10
// speedup vs baseline: 5.5116x; 1.1807x over previous
#include <cuda_runtime.h>
#include <cuda_bf16.h>
#include <cuda_fp16.h>
#include <math.h>
#include <cstdint>

#define B_SZ     2
#define SEQ      2048
#define D_MODEL  1024
#define D_INNER  2048
#define D_STATE  16
#define DT_RANK  64
#define D_CONV   4
#define NROWS    (B_SZ * SEQ)             // 4096
#define XPROJ_N  (DT_RANK + 2 * D_STATE)  // 96
#define XPROJ_NPAD 128
#define KSPLIT3  4
#define NCH      16                        // scan chunks
#define CHT      (SEQ / NCH)               // 128 steps per chunk

typedef __half fp16;

// ---------------- scratch (static device globals; no allocation allowed) ---
__device__ __align__(256) float g_xz[(size_t)NROWS * (2 * D_INNER)];
__device__ __align__(256) float g_xdbc[(size_t)NROWS * XPROJ_N];
__device__ __align__(256) float g_part[(size_t)KSPLIT3 * NROWS * XPROJ_NPAD];
// transposed [d][b*SEQ+l] scan inputs
__device__ __align__(256) float g_dtT[(size_t)D_INNER * NROWS];
__device__ __align__(256) float g_xcT[(size_t)D_INNER * NROWS];
__device__ __align__(256) float g_zT[(size_t)D_INNER * NROWS];
// fp16 split activations (hi/lo); B-side operands are single fp16
__device__ __align__(256) fp16 g_xh[(size_t)NROWS * D_MODEL];
__device__ __align__(256) fp16 g_xl[(size_t)NROWS * D_MODEL];
__device__ __align__(256) fp16 g_xconvh[(size_t)NROWS * D_INNER];
__device__ __align__(256) fp16 g_xconvl[(size_t)NROWS * D_INNER];
__device__ __align__(256) fp16 g_xdh[(size_t)NROWS * DT_RANK];     // single
__device__ __align__(256) fp16 g_yh[(size_t)NROWS * D_INNER];
__device__ __align__(256) fp16 g_yl[(size_t)NROWS * D_INNER];
// fp16 transposed weights [N, K]
__device__ __align__(256) fp16 g_winT[(size_t)(2 * D_INNER) * D_MODEL];   // single
__device__ __align__(256) fp16 g_woutT[(size_t)D_MODEL * D_INNER];        // single
__device__ __align__(256) fp16 g_wxT[(size_t)XPROJ_NPAD * D_INNER];       // single
__device__ __align__(256) fp16 g_wdtT_h[(size_t)D_INNER * DT_RANK];       // split
__device__ __align__(256) fp16 g_wdtT_l[(size_t)D_INNER * DT_RANK];

// ======================= helpers ===========================================
__device__ __forceinline__ uint32_t smem_u32(const void* p) {
    uint32_t a;
    asm("{ .reg .u64 t; cvta.to.shared.u64 t, %1; cvt.u32.u64 %0, t; }"
        : "=r"(a) : "l"(p));
    return a;
}
__device__ __forceinline__ void cp_async16(uint32_t dst, const void* src) {
    asm volatile("cp.async.cg.shared.global [%0], [%1], 16;"
                 :: "r"(dst), "l"(src));
}
#define CP_COMMIT() asm volatile("cp.async.commit_group;")
#define CP_WAIT0()  asm volatile("cp.async.wait_group 0;")

__device__ __forceinline__ void ldsm_x4(uint32_t* r, uint32_t addr) {
    asm volatile("ldmatrix.sync.aligned.m8n8.x4.shared.b16 {%0,%1,%2,%3}, [%4];"
                 : "=r"(r[0]), "=r"(r[1]), "=r"(r[2]), "=r"(r[3]) : "r"(addr));
}

__device__ __forceinline__ void mma16816(float* c, const uint32_t* a,
                                         const uint32_t* b) {
    asm volatile(
        "mma.sync.aligned.m16n8k16.row.col.f32.f16.f16.f32 "
        "{%0,%1,%2,%3}, {%4,%5,%6,%7}, {%8,%9}, {%0,%1,%2,%3};\n"
        : "+f"(c[0]), "+f"(c[1]), "+f"(c[2]), "+f"(c[3])
        : "r"(a[0]), "r"(a[1]), "r"(a[2]), "r"(a[3]),
          "r"(b[0]), "r"(b[1]));
}

__device__ __forceinline__ void split_fp16(float v, fp16& h, fp16& l) {
    h = __float2half_rn(v);
    l = __float2half_rn(v - __half2float(h));
}

// ===== GEMM: C[M,N] = A * B^T, fp16 2-pass (Ah*Bh + Al*Bh) ================
// A split (Ah, Al) [M,K] fp16; B single (Bh) [N,K] fp16.
// act: 0 none; 1 softplus + column bias; 2 softplus + ROW bias.
#define ROW_BYTES 80u
#define TILE_B    (128u * ROW_BYTES)    // 10240
#define STAGE_B   (3u * TILE_B)         // 30720 (Ah|Al|Bh)
#define SMEM_TOT  (2u * STAGE_B)        // 61440

__global__ void __launch_bounds__(256)
gemm2p(const fp16* __restrict__ Ah, const fp16* __restrict__ Al,
       const fp16* __restrict__ Bh,
       float* __restrict__ C, int Nc, int K, int kstart_ch, int kch, int ldc,
       const float* __restrict__ bias, int act, size_t partStride)
{
    extern __shared__ __align__(16) char smem_raw[];
    const uint32_t sb = smem_u32(smem_raw);

    kstart_ch += blockIdx.z * kch;          // split-K slice

    const int tid = threadIdx.x;
    const int wid = tid >> 5, lane = tid & 31;
    const int gr = lane >> 2, q = lane & 3;
    const int row0 = blockIdx.y * 128, col0 = blockIdx.x * 128;
    const int warp_m = (wid & 1) * 64, warp_n = (wid >> 1) * 32;

    float* Cout = C + (size_t)blockIdx.z * partStride;

    const fp16* tb0 = Ah + (size_t)row0 * K;
    const fp16* tb1 = Al + (size_t)row0 * K;
    const fp16* tb2 = Bh + (size_t)col0 * K;

    float acc[4][4][4];
#pragma unroll
    for (int i = 0; i < 4; i++)
#pragma unroll
        for (int j = 0; j < 4; j++)
#pragma unroll
            for (int r = 0; r < 4; r++) acc[i][j][r] = 0.f;

    auto load_stage = [&](int c, int s) {
        int koff = (kstart_ch + c) << 5;
#pragma unroll
        for (int i = 0; i < 6; i++) {
            int seg = tid + 256 * i;            // 0..1535
            int buf = seg >> 9;                 // tile id 0..2
            int w   = seg & 511;
            int row = w >> 2, s4 = w & 3;
            const fp16* base = (buf == 0) ? tb0 : (buf == 1) ? tb1 : tb2;
            const fp16* g = base + (size_t)row * K + koff + s4 * 8;
            uint32_t dst = sb + (uint32_t)s * STAGE_B + (uint32_t)buf * TILE_B
                         + (uint32_t)row * ROW_BYTES + (uint32_t)s4 * 16u;
            cp_async16(dst, g);
        }
    };

    const uint32_t a_row  = (uint32_t)(lane & 15);
    const uint32_t a_koff = (uint32_t)(lane >> 4) * 16u;
    const uint32_t b_row  = (uint32_t)(((lane >> 4) << 3) + (lane & 7));
    const uint32_t b_koff = (uint32_t)((lane >> 3) & 1) * 16u;

    load_stage(0, 0);
    CP_COMMIT();

    for (int c = 0; c < kch; c++) {
        CP_WAIT0();
        __syncthreads();
        if (c + 1 < kch) { load_stage(c + 1, (c + 1) & 1); CP_COMMIT(); }

        const uint32_t st = sb + (uint32_t)(c & 1) * STAGE_B;
        const uint32_t sAh = st;
        const uint32_t sAl = st + TILE_B;
        const uint32_t sBh = st + 2 * TILE_B;

#pragma unroll
        for (int kc = 0; kc < 2; kc++) {
            uint32_t aH[4][4], aL[4][4], bH[8];
#pragma unroll
            for (int mt = 0; mt < 4; mt++) {
                uint32_t roff = ((uint32_t)(warp_m + mt * 16) + a_row) * ROW_BYTES
                              + kc * 32u + a_koff;
                ldsm_x4(aH[mt], sAh + roff);
                ldsm_x4(aL[mt], sAl + roff);
            }
            {
                uint32_t r0 = ((uint32_t)warp_n + b_row) * ROW_BYTES
                            + kc * 32u + b_koff;
                uint32_t r1 = r0 + 16u * ROW_BYTES;
                ldsm_x4(bH + 0, sBh + r0);
                ldsm_x4(bH + 4, sBh + r1);
            }
#pragma unroll
            for (int mt = 0; mt < 4; mt++)
#pragma unroll
                for (int nt = 0; nt < 4; nt++)
                    mma16816(acc[mt][nt], aH[mt], bH + nt * 2);
#pragma unroll
            for (int mt = 0; mt < 4; mt++)
#pragma unroll
                for (int nt = 0; nt < 4; nt++)
                    mma16816(acc[mt][nt], aL[mt], bH + nt * 2);
        }
    }

    // ---------------- epilogue ----------------
#pragma unroll
    for (int mt = 0; mt < 4; mt++) {
#pragma unroll
        for (int nt = 0; nt < 4; nt++) {
            int rg = row0 + warp_m + mt * 16 + gr;
            int cg = col0 + warp_n + nt * 8 + 2 * q;
            float* cc = acc[mt][nt];
#pragma unroll
            for (int half = 0; half < 2; half++) {
                int r = rg + half * 8;
                float v0 = cc[half * 2 + 0];
                float v1 = cc[half * 2 + 1];
                if (bias) {
                    if (act == 2) { float bb = bias[r]; v0 += bb; v1 += bb; }
                    else          { v0 += bias[cg]; v1 += bias[cg + 1]; }
                }
                if (act) {
                    v0 = (v0 > 20.f) ? v0 : log1pf(expf(v0));
                    v1 = (v1 > 20.f) ? v1 : log1pf(expf(v1));
                }
                if (cg + 1 < Nc) {
                    *reinterpret_cast<float2*>(&Cout[(size_t)r * ldc + cg]) =
                        make_float2(v0, v1);
                } else if (cg < Nc) {
                    Cout[(size_t)r * ldc + cg] = v0;
                }
            }
        }
    }
}

// -------- split-K reduce for xproj GEMM: sum partials, write xdbc + xdh ----
__global__ void reduce3_kernel(const float* __restrict__ part,
                               float* __restrict__ xdbc,
                               fp16* __restrict__ xdh)
{
    int i = blockIdx.x * 256 + threadIdx.x;
    if (i >= NROWS * XPROJ_N) return;
    int r = i / XPROJ_N, c = i - r * XPROJ_N;
    const size_t ps = (size_t)NROWS * XPROJ_NPAD;
    float v = 0.f;
#pragma unroll
    for (int p = 0; p < KSPLIT3; p++)
        v += part[p * ps + (size_t)r * XPROJ_NPAD + c];
    xdbc[(size_t)r * XPROJ_N + c] = v;
    if (c < DT_RANK)
        xdh[(size_t)r * DT_RANK + c] = __float2half_rn(v);
}

// ======= weight transpose + fp16 (single or hi/lo split if Tl) =============
__global__ void wsplit_kernel(const float* __restrict__ W,
                              fp16* __restrict__ Th, fp16* __restrict__ Tl,
                              int K, int N, int Npad)
{
    __shared__ float tile[32][33];
    int kb = blockIdx.y * 32, nb = blockIdx.x * 32;
    int tx = threadIdx.x, ty = threadIdx.y;
#pragma unroll
    for (int i = ty; i < 32; i += 8) {
        int k = kb + i, n = nb + tx;
        tile[i][tx] = (k < K && n < N) ? W[(size_t)k * N + n] : 0.f;
    }
    __syncthreads();
#pragma unroll
    for (int i = ty; i < 32; i += 8) {
        int n = nb + i, k = kb + tx;
        if (n < Npad && k < K) {
            float v = tile[tx][i];
            fp16 h = __float2half_rn(v);
            Th[(size_t)n * K + k] = h;
            if (Tl)
                Tl[(size_t)n * K + k] = __float2half_rn(v - __half2float(h));
        }
    }
}

// ---------------- elementwise fp32 -> fp16 hi/lo split ---------------------
__global__ void fsplit_kernel(const float* __restrict__ X,
                              fp16* __restrict__ H, fp16* __restrict__ L,
                              int n)
{
    int i = blockIdx.x * blockDim.x + threadIdx.x;
    if (i >= n) return;
    fp16 h, l;
    split_fp16(X[i], h, l);
    H[i] = h; L[i] = l;
}

// ====== fused causal conv + SiLU + transposes (one pass over xz) ===========
__global__ void convT_kernel(const float* __restrict__ xz,
                             const float* __restrict__ w_conv,
                             const float* __restrict__ b_conv,
                             float* __restrict__ xcT, float* __restrict__ zT,
                             fp16* __restrict__ xch, fp16* __restrict__ xcl)
{
    __shared__ float tin[35][33];
    __shared__ float tout[32][33];
    __shared__ float tz[32][33];
    const int b  = blockIdx.z;
    const int l0 = blockIdx.x * 32, d0 = blockIdx.y * 32;
    const int tx = threadIdx.x, ty = threadIdx.y;     // 32 x 8

    for (int j = ty; j < 35; j += 8) {
        int l = l0 - 3 + j;
        tin[j][tx] = (l >= 0) ? xz[(size_t)(b * SEQ + l) * (2 * D_INNER) + d0 + tx]
                              : 0.f;
    }
#pragma unroll
    for (int i = ty; i < 32; i += 8)
        tz[i][tx] = xz[(size_t)(b * SEQ + l0 + i) * (2 * D_INNER) + D_INNER + d0 + tx];
    __syncthreads();

    const float w0 = w_conv[(d0 + tx) * D_CONV + 0];
    const float w1 = w_conv[(d0 + tx) * D_CONV + 1];
    const float w2 = w_conv[(d0 + tx) * D_CONV + 2];
    const float w3 = w_conv[(d0 + tx) * D_CONV + 3];
    const float bc = b_conv[d0 + tx];
#pragma unroll
    for (int i = ty; i < 32; i += 8) {
        float acc = bc + tin[i][tx] * w0 + tin[i + 1][tx] * w1
                       + tin[i + 2][tx] * w2 + tin[i + 3][tx] * w3;
        float s = 1.f / (1.f + __expf(-acc));
        float v = acc * s;
        tout[i][tx] = v;
        fp16 h, l;
        split_fp16(v, h, l);
        size_t ro = (size_t)(b * SEQ + l0 + i) * D_INNER + d0 + tx;
        xch[ro] = h; xcl[ro] = l;
    }
    __syncthreads();
#pragma unroll
    for (int i = ty; i < 32; i += 8) {
        size_t o = (size_t)(d0 + i) * NROWS + b * SEQ + l0 + tx;
        xcT[o] = tout[tx][i];
        zT[o]  = tz[tx][i];
    }
}

// ================== fused chunked selective scan (A+B+C) ===================
__global__ void __launch_bounds__(256)
scan_fused_kernel(const float* __restrict__ dtT, const float* __restrict__ xcT,
                  const float* __restrict__ zT,  const float* __restrict__ xdbc,
                  const float* __restrict__ A_log, const float* __restrict__ Dv,
                  fp16* __restrict__ yh, fp16* __restrict__ yl)
{
    __shared__ float sP[NCH][D_STATE];
    __shared__ float sS[NCH][D_STATE];

    const int blk = blockIdx.x;            // b*D_INNER + d
    const int d = blk & (D_INNER - 1), b = blk >> 11;
    const int t = threadIdx.x;
    const int n = t & 15, c = t >> 4;

    const float An = -expf(A_log[d * D_STATE + n]);
    const size_t chan = (size_t)d * NROWS + b * SEQ;
    const float* dtp = dtT + chan + c * CHT;
    const float* xcp = xcT + chan + c * CHT;
    const float* zp  = zT  + chan + c * CHT;
    const float* bc0 = xdbc + ((size_t)(b * SEQ + c * CHT)) * XPROJ_N;

    // ---- Phase A: per-chunk affine coefficients ----
    {
        const float* bc = bc0;
        float P = 1.f, S = 0.f;
        for (int l0 = 0; l0 < CHT; l0 += 4) {
            float4 dt4 = *reinterpret_cast<const float4*>(dtp + l0);
            float4 xv4 = *reinterpret_cast<const float4*>(xcp + l0);
            float dtv[4] = {dt4.x, dt4.y, dt4.z, dt4.w};
            float xvv[4] = {xv4.x, xv4.y, xv4.z, xv4.w};
#pragma unroll
            for (int j = 0; j < 4; j++) {
                float Bn = bc[DT_RANK + n];
                float a  = __expf(dtv[j] * An);
                S = fmaf(a, S, dtv[j] * xvv[j] * Bn);
                P *= a;
                bc += XPROJ_N;
            }
        }
        sP[c][n] = P; sS[c][n] = S;
    }
    __syncthreads();

    // ---- Phase B: per-thread prefix over earlier chunks ----
    float h = 0.f;
    for (int cc = 0; cc < c; cc++)
        h = fmaf(sP[cc][n], h, sS[cc][n]);

    // ---- Phase C: replay with correct h_in, reduce y, gate, split-store ----
    const float Dd = Dv[d];
    const float* bc = bc0;
    size_t yrow = (size_t)(b * SEQ + c * CHT) * D_INNER + d;

    for (int l0 = 0; l0 < CHT; l0 += 4) {
        float4 dt4 = *reinterpret_cast<const float4*>(dtp + l0);
        float4 xv4 = *reinterpret_cast<const float4*>(xcp + l0);
        float4 z4  = *reinterpret_cast<const float4*>(zp + l0);
        float dtv[4] = {dt4.x, dt4.y, dt4.z, dt4.w};
        float xvv[4] = {xv4.x, xv4.y, xv4.z, xv4.w};
        float zvv[4] = {z4.x, z4.y, z4.z, z4.w};
#pragma unroll
        for (int j = 0; j < 4; j++) {
            float Bn = bc[DT_RANK + n];
            float Cn = bc[DT_RANK + D_STATE + n];
            float a  = __expf(dtv[j] * An);
            h = fmaf(a, h, dtv[j] * xvv[j] * Bn);
            float part = Cn * h;
            part += __shfl_xor_sync(0xffffffffu, part, 1);
            part += __shfl_xor_sync(0xffffffffu, part, 2);
            part += __shfl_xor_sync(0xffffffffu, part, 4);
            part += __shfl_xor_sync(0xffffffffu, part, 8);
            if (n == 0) {
                float z   = zvv[j];
                float sig = 1.f / (1.f + __expf(-z));
                float yv  = (part + xvv[j] * Dd) * (z * sig);
                fp16 hh, ll;
                split_fp16(yv, hh, ll);
                yh[yrow] = hh; yl[yrow] = ll;
            }
            bc += XPROJ_N;
            yrow += D_INNER;
        }
    }
}

// ---------------- launcher -------------------------------------------------
extern "C" void kernel_launch(void* const* d_in, const int* in_sizes, int n_in,
                              void* d_out, int out_size)
{
    const float* x       = (const float*)d_in[0];
    const float* w_in    = (const float*)d_in[1];
    const float* w_conv  = (const float*)d_in[2];
    const float* b_conv  = (const float*)d_in[3];
    const float* w_xproj = (const float*)d_in[4];
    const float* w_dt    = (const float*)d_in[5];
    const float* b_dt    = (const float*)d_in[6];
    const float* A_log   = (const float*)d_in[7];
    const float* Dv      = (const float*)d_in[8];
    const float* w_out   = (const float*)d_in[9];
    float* out = (float*)d_out;

    float *xz, *xdbc, *part, *dtT, *xcT, *zT;
    fp16 *xh, *xl, *xch, *xcl, *xdh, *yh, *yl;
    fp16 *winT, *woutT, *wxT, *wdtT_h, *wdtT_l;
    cudaGetSymbolAddress((void**)&xz,      g_xz);
    cudaGetSymbolAddress((void**)&xdbc,    g_xdbc);
    cudaGetSymbolAddress((void**)&part,    g_part);
    cudaGetSymbolAddress((void**)&dtT,     g_dtT);
    cudaGetSymbolAddress((void**)&xcT,     g_xcT);
    cudaGetSymbolAddress((void**)&zT,      g_zT);
    cudaGetSymbolAddress((void**)&xh,      g_xh);
    cudaGetSymbolAddress((void**)&xl,      g_xl);
    cudaGetSymbolAddress((void**)&xch,     g_xconvh);
    cudaGetSymbolAddress((void**)&xcl,     g_xconvl);
    cudaGetSymbolAddress((void**)&xdh,     g_xdh);
    cudaGetSymbolAddress((void**)&yh,      g_yh);
    cudaGetSymbolAddress((void**)&yl,      g_yl);
    cudaGetSymbolAddress((void**)&winT,    g_winT);
    cudaGetSymbolAddress((void**)&woutT,   g_woutT);
    cudaGetSymbolAddress((void**)&wxT,     g_wxT);
    cudaGetSymbolAddress((void**)&wdtT_h,  g_wdtT_h);
    cudaGetSymbolAddress((void**)&wdtT_l,  g_wdtT_l);

    cudaFuncSetAttribute(gemm2p, cudaFuncAttributeMaxDynamicSharedMemorySize,
                         SMEM_TOT);

    dim3 tb(32, 8);
    // launches 0-2: prep for gemm1 (gemm1 stays at ncu index 3)
    fsplit_kernel<<<(NROWS * D_MODEL + 255) / 256, 256>>>(x, xh, xl, NROWS * D_MODEL);
    wsplit_kernel<<<dim3(4096 / 32, 1024 / 32), tb>>>(w_in, winT, nullptr,
                                                      D_MODEL, 2 * D_INNER, 2 * D_INNER);
    wsplit_kernel<<<dim3(XPROJ_NPAD / 32, 2048 / 32), tb>>>(w_xproj, wxT, nullptr,
                                                            D_INNER, XPROJ_N, XPROJ_NPAD);
    // launch 3: xz = x @ w_in          M=4096 N=4096 K=1024   <-- profiled
    gemm2p<<<dim3(32, 32, 1), 256, SMEM_TOT>>>(xh, xl, winT, xz,
                                               2 * D_INNER, D_MODEL, 0,
                                               D_MODEL / 32, 2 * D_INNER,
                                               nullptr, 0, 0);
    // remaining weight preps
    wsplit_kernel<<<dim3(2048 / 32, 64 / 32), tb>>>(w_dt, wdtT_h, wdtT_l,
                                                    DT_RANK, D_INNER, D_INNER);
    wsplit_kernel<<<dim3(1024 / 32, 2048 / 32), tb>>>(w_out, woutT, nullptr,
                                                      D_INNER, D_MODEL, D_MODEL);
    // fused conv + silu + transposes (xcT, zT, xch, xcl in one pass)
    convT_kernel<<<dim3(SEQ / 32, D_INNER / 32, B_SZ), tb>>>(
        xz, w_conv, b_conv, xcT, zT, xch, xcl);
    // xproj: split-K=4 into partials, then reduce (+ dt-rank fp16)
    gemm2p<<<dim3(1, 32, KSPLIT3), 256, SMEM_TOT>>>(
        xch, xcl, wxT, part,
        XPROJ_NPAD, D_INNER, 0, (D_INNER / 32) / KSPLIT3, XPROJ_NPAD,
        nullptr, 0, (size_t)NROWS * XPROJ_NPAD);
    reduce3_kernel<<<(NROWS * XPROJ_N + 255) / 256, 256>>>(part, xdbc, xdh);
    // dtT[d][b*L+l] = softplus(wdtT @ xdbc_dt^T + b_dt[d])  (transposed output)
    gemm2p<<<dim3(NROWS / 128, D_INNER / 128, 1), 256, SMEM_TOT>>>(
        wdtT_h, wdtT_l, xdh, dtT,
        NROWS, DT_RANK, 0, DT_RANK / 32, NROWS,
        b_dt, 2, 0);
    // fused chunked scan (A+B+C in one kernel)
    scan_fused_kernel<<<B_SZ * D_INNER, 256>>>(
        dtT, xcT, zT, xdbc, A_log, Dv, yh, yl);
    // out = y @ w_out                  M=4096 N=1024 K=2048
    gemm2p<<<dim3(8, 32, 1), 256, SMEM_TOT>>>(yh, yl, woutT, out,
                                              D_MODEL, D_INNER, 0,
                                              D_INNER / 32, D_MODEL,
                                              nullptr, 0, 0);
}

// round 11
// speedup vs baseline: 6.8683x; 1.2462x over previous
#include <cuda_runtime.h>
#include <cuda_bf16.h>
#include <cuda_fp16.h>
#include <math.h>
#include <cstdint>

#define B_SZ     2
#define SEQ      2048
#define D_MODEL  1024
#define D_INNER  2048
#define D_STATE  16
#define DT_RANK  64
#define D_CONV   4
#define NROWS    (B_SZ * SEQ)             // 4096
#define XPROJ_N  (DT_RANK + 2 * D_STATE)  // 96
#define XPROJ_NPAD 128
#define KSPLIT3  4
#define NCH      16                        // scan chunks
#define CHT      (SEQ / NCH)               // 128 steps per chunk

typedef __half fp16;

// ---------------- scratch (static device globals; no allocation allowed) ---
__device__ __align__(256) float g_xz[(size_t)NROWS * (2 * D_INNER)];
__device__ __align__(256) float g_xdbc[(size_t)NROWS * XPROJ_N];
__device__ __align__(256) float g_part[(size_t)KSPLIT3 * NROWS * XPROJ_NPAD];
// transposed [d][b*SEQ+l] scan inputs, fp16
__device__ __align__(256) fp16 g_dtT[(size_t)D_INNER * NROWS];
__device__ __align__(256) fp16 g_xcT[(size_t)D_INNER * NROWS];
__device__ __align__(256) fp16 g_zT[(size_t)D_INNER * NROWS];
// fp16 activations (single precision-level, no lo arrays)
__device__ __align__(256) fp16 g_xh[(size_t)NROWS * D_MODEL];
__device__ __align__(256) fp16 g_xconvh[(size_t)NROWS * D_INNER];
__device__ __align__(256) fp16 g_xdh[(size_t)NROWS * DT_RANK];
__device__ __align__(256) fp16 g_yh[(size_t)NROWS * D_INNER];
// fp16 transposed weights [N, K]
__device__ __align__(256) fp16 g_winT[(size_t)(2 * D_INNER) * D_MODEL];
__device__ __align__(256) fp16 g_woutT[(size_t)D_MODEL * D_INNER];
__device__ __align__(256) fp16 g_wxT[(size_t)XPROJ_NPAD * D_INNER];
__device__ __align__(256) fp16 g_wdtT[(size_t)D_INNER * DT_RANK];

// ======================= helpers ===========================================
__device__ __forceinline__ uint32_t smem_u32(const void* p) {
    uint32_t a;
    asm("{ .reg .u64 t; cvta.to.shared.u64 t, %1; cvt.u32.u64 %0, t; }"
        : "=r"(a) : "l"(p));
    return a;
}
__device__ __forceinline__ void cp_async16(uint32_t dst, const void* src) {
    asm volatile("cp.async.cg.shared.global [%0], [%1], 16;"
                 :: "r"(dst), "l"(src));
}
#define CP_COMMIT() asm volatile("cp.async.commit_group;")
#define CP_WAIT0()  asm volatile("cp.async.wait_group 0;")

__device__ __forceinline__ void ldsm_x4(uint32_t* r, uint32_t addr) {
    asm volatile("ldmatrix.sync.aligned.m8n8.x4.shared.b16 {%0,%1,%2,%3}, [%4];"
                 : "=r"(r[0]), "=r"(r[1]), "=r"(r[2]), "=r"(r[3]) : "r"(addr));
}

__device__ __forceinline__ void mma16816(float* c, const uint32_t* a,
                                         const uint32_t* b) {
    asm volatile(
        "mma.sync.aligned.m16n8k16.row.col.f32.f16.f16.f32 "
        "{%0,%1,%2,%3}, {%4,%5,%6,%7}, {%8,%9}, {%0,%1,%2,%3};\n"
        : "+f"(c[0]), "+f"(c[1]), "+f"(c[2]), "+f"(c[3])
        : "r"(a[0]), "r"(a[1]), "r"(a[2]), "r"(a[3]),
          "r"(b[0]), "r"(b[1]));
}

// load 8 consecutive fp16 -> 8 floats (16B aligned)
__device__ __forceinline__ void load8h(const fp16* p, float* v) {
    uint4 raw = *reinterpret_cast<const uint4*>(p);
    const __half2* h2 = reinterpret_cast<const __half2*>(&raw);
#pragma unroll
    for (int i = 0; i < 4; i++) {
        float2 f = __half22float2(h2[i]);
        v[2 * i] = f.x; v[2 * i + 1] = f.y;
    }
}

// ===== GEMM: C[M,N] = A * B^T, single-pass fp16 ===========================
// act: 0 none; 1 softplus + column bias; 2 softplus + ROW bias.
// Ch != nullptr -> write fp16 output (half2 stores), else fp32 (float2).
#define ROW_BYTES 80u
#define TILE_B    (128u * ROW_BYTES)    // 10240
#define STAGE_B   (2u * TILE_B)         // 20480 (A|B)
#define SMEM_TOT  (2u * STAGE_B)        // 40960

__global__ void __launch_bounds__(256)
gemm1p(const fp16* __restrict__ A, const fp16* __restrict__ B,
       float* __restrict__ C, fp16* __restrict__ Ch,
       int Nc, int K, int kstart_ch, int kch, int ldc,
       const float* __restrict__ bias, int act, size_t partStride)
{
    extern __shared__ __align__(16) char smem_raw[];
    const uint32_t sb = smem_u32(smem_raw);

    kstart_ch += blockIdx.z * kch;          // split-K slice

    const int tid = threadIdx.x;
    const int wid = tid >> 5, lane = tid & 31;
    const int gr = lane >> 2, q = lane & 3;
    const int row0 = blockIdx.y * 128, col0 = blockIdx.x * 128;
    const int warp_m = (wid & 1) * 64, warp_n = (wid >> 1) * 32;

    float* Cout = C ? (C + (size_t)blockIdx.z * partStride) : nullptr;

    const fp16* tbA = A + (size_t)row0 * K;
    const fp16* tbB = B + (size_t)col0 * K;

    float acc[4][4][4];
#pragma unroll
    for (int i = 0; i < 4; i++)
#pragma unroll
        for (int j = 0; j < 4; j++)
#pragma unroll
            for (int r = 0; r < 4; r++) acc[i][j][r] = 0.f;

    auto load_stage = [&](int c, int s) {
        int koff = (kstart_ch + c) << 5;
#pragma unroll
        for (int i = 0; i < 4; i++) {
            int seg = tid + 256 * i;            // 0..1023
            int buf = seg >> 9;                 // 0 = A, 1 = B
            int w   = seg & 511;
            int row = w >> 2, s4 = w & 3;
            const fp16* base = buf ? tbB : tbA;
            const fp16* g = base + (size_t)row * K + koff + s4 * 8;
            uint32_t dst = sb + (uint32_t)s * STAGE_B + (uint32_t)buf * TILE_B
                         + (uint32_t)row * ROW_BYTES + (uint32_t)s4 * 16u;
            cp_async16(dst, g);
        }
    };

    const uint32_t a_row  = (uint32_t)(lane & 15);
    const uint32_t a_koff = (uint32_t)(lane >> 4) * 16u;
    const uint32_t b_row  = (uint32_t)(((lane >> 4) << 3) + (lane & 7));
    const uint32_t b_koff = (uint32_t)((lane >> 3) & 1) * 16u;

    load_stage(0, 0);
    CP_COMMIT();

    for (int c = 0; c < kch; c++) {
        CP_WAIT0();
        __syncthreads();
        if (c + 1 < kch) { load_stage(c + 1, (c + 1) & 1); CP_COMMIT(); }

        const uint32_t st = sb + (uint32_t)(c & 1) * STAGE_B;
        const uint32_t sA = st;
        const uint32_t sB = st + TILE_B;

#pragma unroll
        for (int kc = 0; kc < 2; kc++) {
            uint32_t aH[4][4], bH[8];
#pragma unroll
            for (int mt = 0; mt < 4; mt++) {
                uint32_t roff = ((uint32_t)(warp_m + mt * 16) + a_row) * ROW_BYTES
                              + kc * 32u + a_koff;
                ldsm_x4(aH[mt], sA + roff);
            }
            {
                uint32_t r0 = ((uint32_t)warp_n + b_row) * ROW_BYTES
                            + kc * 32u + b_koff;
                uint32_t r1 = r0 + 16u * ROW_BYTES;
                ldsm_x4(bH + 0, sB + r0);
                ldsm_x4(bH + 4, sB + r1);
            }
#pragma unroll
            for (int mt = 0; mt < 4; mt++)
#pragma unroll
                for (int nt = 0; nt < 4; nt++)
                    mma16816(acc[mt][nt], aH[mt], bH + nt * 2);
        }
    }

    // ---------------- epilogue ----------------
#pragma unroll
    for (int mt = 0; mt < 4; mt++) {
#pragma unroll
        for (int nt = 0; nt < 4; nt++) {
            int rg = row0 + warp_m + mt * 16 + gr;
            int cg = col0 + warp_n + nt * 8 + 2 * q;
            float* cc = acc[mt][nt];
#pragma unroll
            for (int half = 0; half < 2; half++) {
                int r = rg + half * 8;
                float v0 = cc[half * 2 + 0];
                float v1 = cc[half * 2 + 1];
                if (bias) {
                    if (act == 2) { float bb = bias[r]; v0 += bb; v1 += bb; }
                    else          { v0 += bias[cg]; v1 += bias[cg + 1]; }
                }
                if (act) {
                    v0 = (v0 > 20.f) ? v0 : log1pf(expf(v0));
                    v1 = (v1 > 20.f) ? v1 : log1pf(expf(v1));
                }
                if (cg + 1 < Nc) {
                    if (Ch) {
                        *reinterpret_cast<__half2*>(&Ch[(size_t)r * ldc + cg]) =
                            __floats2half2_rn(v0, v1);
                    } else {
                        *reinterpret_cast<float2*>(&Cout[(size_t)r * ldc + cg]) =
                            make_float2(v0, v1);
                    }
                } else if (cg < Nc) {
                    if (Ch) Ch[(size_t)r * ldc + cg] = __float2half_rn(v0);
                    else    Cout[(size_t)r * ldc + cg] = v0;
                }
            }
        }
    }
}

// -------- split-K reduce for xproj GEMM: sum partials, write xdbc + xdh ----
__global__ void reduce3_kernel(const float* __restrict__ part,
                               float* __restrict__ xdbc,
                               fp16* __restrict__ xdh)
{
    int i = blockIdx.x * 256 + threadIdx.x;
    if (i >= NROWS * XPROJ_N) return;
    int r = i / XPROJ_N, c = i - r * XPROJ_N;
    const size_t ps = (size_t)NROWS * XPROJ_NPAD;
    float v = 0.f;
#pragma unroll
    for (int p = 0; p < KSPLIT3; p++)
        v += part[p * ps + (size_t)r * XPROJ_NPAD + c];
    xdbc[(size_t)r * XPROJ_N + c] = v;
    if (c < DT_RANK)
        xdh[(size_t)r * DT_RANK + c] = __float2half_rn(v);
}

// ======= weight transpose -> fp16 [Npad, K] ================================
__global__ void wsplit_kernel(const float* __restrict__ W,
                              fp16* __restrict__ Th,
                              int K, int N, int Npad)
{
    __shared__ float tile[32][33];
    int kb = blockIdx.y * 32, nb = blockIdx.x * 32;
    int tx = threadIdx.x, ty = threadIdx.y;
#pragma unroll
    for (int i = ty; i < 32; i += 8) {
        int k = kb + i, n = nb + tx;
        tile[i][tx] = (k < K && n < N) ? W[(size_t)k * N + n] : 0.f;
    }
    __syncthreads();
#pragma unroll
    for (int i = ty; i < 32; i += 8) {
        int n = nb + i, k = kb + tx;
        if (n < Npad && k < K)
            Th[(size_t)n * K + k] = __float2half_rn(tile[tx][i]);
    }
}

// ---------------- elementwise fp32 -> fp16 convert -------------------------
__global__ void fconv_kernel(const float* __restrict__ X,
                             fp16* __restrict__ H, int n)
{
    int i = blockIdx.x * blockDim.x + threadIdx.x;
    if (i >= n) return;
    H[i] = __float2half_rn(X[i]);
}

// ====== fused causal conv + SiLU + transposes (one pass over xz) ===========
// Writes: xcT/zT [d][b*SEQ+l] fp16, xch [b*SEQ+l][d] fp16.
__global__ void convT_kernel(const float* __restrict__ xz,
                             const float* __restrict__ w_conv,
                             const float* __restrict__ b_conv,
                             fp16* __restrict__ xcT, fp16* __restrict__ zT,
                             fp16* __restrict__ xch)
{
    __shared__ float tin[35][33];
    __shared__ float tout[32][33];
    __shared__ float tz[32][33];
    const int b  = blockIdx.z;
    const int l0 = blockIdx.x * 32, d0 = blockIdx.y * 32;
    const int tx = threadIdx.x, ty = threadIdx.y;     // 32 x 8

    for (int j = ty; j < 35; j += 8) {
        int l = l0 - 3 + j;
        tin[j][tx] = (l >= 0) ? xz[(size_t)(b * SEQ + l) * (2 * D_INNER) + d0 + tx]
                              : 0.f;
    }
#pragma unroll
    for (int i = ty; i < 32; i += 8)
        tz[i][tx] = xz[(size_t)(b * SEQ + l0 + i) * (2 * D_INNER) + D_INNER + d0 + tx];
    __syncthreads();

    const float w0 = w_conv[(d0 + tx) * D_CONV + 0];
    const float w1 = w_conv[(d0 + tx) * D_CONV + 1];
    const float w2 = w_conv[(d0 + tx) * D_CONV + 2];
    const float w3 = w_conv[(d0 + tx) * D_CONV + 3];
    const float bc = b_conv[d0 + tx];
#pragma unroll
    for (int i = ty; i < 32; i += 8) {
        float acc = bc + tin[i][tx] * w0 + tin[i + 1][tx] * w1
                       + tin[i + 2][tx] * w2 + tin[i + 3][tx] * w3;
        float s = 1.f / (1.f + __expf(-acc));
        float v = acc * s;
        tout[i][tx] = v;
        xch[(size_t)(b * SEQ + l0 + i) * D_INNER + d0 + tx] = __float2half_rn(v);
    }
    __syncthreads();
#pragma unroll
    for (int i = ty; i < 32; i += 8) {
        size_t o = (size_t)(d0 + i) * NROWS + b * SEQ + l0 + tx;
        xcT[o] = __float2half_rn(tout[tx][i]);
        zT[o]  = __float2half_rn(tz[tx][i]);
    }
}

// ================== fused chunked selective scan (A+B+C) ===================
// block = one (b, d) channel; 256 threads = 16 chunks x 16 states.
// transposed fp16 inputs use layout [d][b*SEQ + l].
__global__ void __launch_bounds__(256)
scan_fused_kernel(const fp16* __restrict__ dtT, const fp16* __restrict__ xcT,
                  const fp16* __restrict__ zT,  const float* __restrict__ xdbc,
                  const float* __restrict__ A_log, const float* __restrict__ Dv,
                  fp16* __restrict__ yh)
{
    __shared__ float sP[NCH][D_STATE];
    __shared__ float sS[NCH][D_STATE];

    const int blk = blockIdx.x;            // b*D_INNER + d
    const int d = blk & (D_INNER - 1), b = blk >> 11;
    const int t = threadIdx.x;
    const int n = t & 15, c = t >> 4;

    const float An = -expf(A_log[d * D_STATE + n]);
    const size_t chan = (size_t)d * NROWS + b * SEQ;
    const fp16* dtp = dtT + chan + c * CHT;
    const fp16* xcp = xcT + chan + c * CHT;
    const fp16* zp  = zT  + chan + c * CHT;
    const float* bc0 = xdbc + ((size_t)(b * SEQ + c * CHT)) * XPROJ_N;

    // ---- Phase A: per-chunk affine coefficients ----
    {
        const float* bc = bc0;
        float P = 1.f, S = 0.f;
        for (int l0 = 0; l0 < CHT; l0 += 8) {
            float dtv[8], xvv[8];
            load8h(dtp + l0, dtv);
            load8h(xcp + l0, xvv);
#pragma unroll
            for (int j = 0; j < 8; j++) {
                float Bn = bc[DT_RANK + n];
                float a  = __expf(dtv[j] * An);
                S = fmaf(a, S, dtv[j] * xvv[j] * Bn);
                P *= a;
                bc += XPROJ_N;
            }
        }
        sP[c][n] = P; sS[c][n] = S;
    }
    __syncthreads();

    // ---- Phase B: per-thread prefix over earlier chunks ----
    float h = 0.f;
    for (int cc = 0; cc < c; cc++)
        h = fmaf(sP[cc][n], h, sS[cc][n]);

    // ---- Phase C: replay with correct h_in, reduce y, gate, store ----
    const float Dd = Dv[d];
    const float* bc = bc0;
    size_t yrow = (size_t)(b * SEQ + c * CHT) * D_INNER + d;

    for (int l0 = 0; l0 < CHT; l0 += 8) {
        float dtv[8], xvv[8], zvv[8];
        load8h(dtp + l0, dtv);
        load8h(xcp + l0, xvv);
        load8h(zp + l0, zvv);
#pragma unroll
        for (int j = 0; j < 8; j++) {
            float Bn = bc[DT_RANK + n];
            float Cn = bc[DT_RANK + D_STATE + n];
            float a  = __expf(dtv[j] * An);
            h = fmaf(a, h, dtv[j] * xvv[j] * Bn);
            float part = Cn * h;
            part += __shfl_xor_sync(0xffffffffu, part, 1);
            part += __shfl_xor_sync(0xffffffffu, part, 2);
            part += __shfl_xor_sync(0xffffffffu, part, 4);
            part += __shfl_xor_sync(0xffffffffu, part, 8);
            if (n == 0) {
                float z   = zvv[j];
                float sig = 1.f / (1.f + __expf(-z));
                float yv  = (part + xvv[j] * Dd) * (z * sig);
                yh[yrow] = __float2half_rn(yv);
            }
            bc += XPROJ_N;
            yrow += D_INNER;
        }
    }
}

// ---------------- launcher -------------------------------------------------
extern "C" void kernel_launch(void* const* d_in, const int* in_sizes, int n_in,
                              void* d_out, int out_size)
{
    const float* x       = (const float*)d_in[0];
    const float* w_in    = (const float*)d_in[1];
    const float* w_conv  = (const float*)d_in[2];
    const float* b_conv  = (const float*)d_in[3];
    const float* w_xproj = (const float*)d_in[4];
    const float* w_dt    = (const float*)d_in[5];
    const float* b_dt    = (const float*)d_in[6];
    const float* A_log   = (const float*)d_in[7];
    const float* Dv      = (const float*)d_in[8];
    const float* w_out   = (const float*)d_in[9];
    float* out = (float*)d_out;

    float *xz, *xdbc, *part;
    fp16 *dtT, *xcT, *zT;
    fp16 *xh, *xch, *xdh, *yh;
    fp16 *winT, *woutT, *wxT, *wdtT;
    cudaGetSymbolAddress((void**)&xz,    g_xz);
    cudaGetSymbolAddress((void**)&xdbc,  g_xdbc);
    cudaGetSymbolAddress((void**)&part,  g_part);
    cudaGetSymbolAddress((void**)&dtT,   g_dtT);
    cudaGetSymbolAddress((void**)&xcT,   g_xcT);
    cudaGetSymbolAddress((void**)&zT,    g_zT);
    cudaGetSymbolAddress((void**)&xh,    g_xh);
    cudaGetSymbolAddress((void**)&xch,   g_xconvh);
    cudaGetSymbolAddress((void**)&xdh,   g_xdh);
    cudaGetSymbolAddress((void**)&yh,    g_yh);
    cudaGetSymbolAddress((void**)&winT,  g_winT);
    cudaGetSymbolAddress((void**)&woutT, g_woutT);
    cudaGetSymbolAddress((void**)&wxT,   g_wxT);
    cudaGetSymbolAddress((void**)&wdtT,  g_wdtT);

    cudaFuncSetAttribute(gemm1p, cudaFuncAttributeMaxDynamicSharedMemorySize,
                         SMEM_TOT);

    dim3 tb(32, 8);
    // launches 0-2: prep for gemm1 (gemm1 stays at ncu index 3)
    fconv_kernel<<<(NROWS * D_MODEL + 255) / 256, 256>>>(x, xh, NROWS * D_MODEL);
    wsplit_kernel<<<dim3(4096 / 32, 1024 / 32), tb>>>(w_in, winT,
                                                      D_MODEL, 2 * D_INNER, 2 * D_INNER);
    wsplit_kernel<<<dim3(XPROJ_NPAD / 32, 2048 / 32), tb>>>(w_xproj, wxT,
                                                            D_INNER, XPROJ_N, XPROJ_NPAD);
    // launch 3: xz = x @ w_in          M=4096 N=4096 K=1024   <-- profiled
    gemm1p<<<dim3(32, 32, 1), 256, SMEM_TOT>>>(xh, winT, xz, nullptr,
                                               2 * D_INNER, D_MODEL, 0,
                                               D_MODEL / 32, 2 * D_INNER,
                                               nullptr, 0, 0);
    // remaining weight preps
    wsplit_kernel<<<dim3(2048 / 32, 64 / 32), tb>>>(w_dt, wdtT,
                                                    DT_RANK, D_INNER, D_INNER);
    wsplit_kernel<<<dim3(1024 / 32, 2048 / 32), tb>>>(w_out, woutT,
                                                      D_INNER, D_MODEL, D_MODEL);
    // fused conv + silu + transposes (xcT, zT fp16 + xch fp16 in one pass)
    convT_kernel<<<dim3(SEQ / 32, D_INNER / 32, B_SZ), tb>>>(
        xz, w_conv, b_conv, xcT, zT, xch);
    // xproj: split-K=4 into partials, then reduce (+ dt-rank fp16)
    gemm1p<<<dim3(1, 32, KSPLIT3), 256, SMEM_TOT>>>(
        xch, wxT, part, nullptr,
        XPROJ_NPAD, D_INNER, 0, (D_INNER / 32) / KSPLIT3, XPROJ_NPAD,
        nullptr, 0, (size_t)NROWS * XPROJ_NPAD);
    reduce3_kernel<<<(NROWS * XPROJ_N + 255) / 256, 256>>>(part, xdbc, xdh);
    // dtT[d][b*L+l] = softplus(wdtT @ xdbc_dt^T + b_dt[d])  (fp16 output)
    gemm1p<<<dim3(NROWS / 128, D_INNER / 128, 1), 256, SMEM_TOT>>>(
        wdtT, xdh, nullptr, dtT,
        NROWS, DT_RANK, 0, DT_RANK / 32, NROWS,
        b_dt, 2, 0);
    // fused chunked scan (A+B+C in one kernel)
    scan_fused_kernel<<<B_SZ * D_INNER, 256>>>(
        dtT, xcT, zT, xdbc, A_log, Dv, yh);
    // out = y @ w_out                  M=4096 N=1024 K=2048
    gemm1p<<<dim3(8, 32, 1), 256, SMEM_TOT>>>(yh, woutT, out, nullptr,
                                              D_MODEL, D_INNER, 0,
                                              D_INNER / 32, D_MODEL,
                                              nullptr, 0, 0);
}

// round 12
// speedup vs baseline: 6.9284x; 1.0087x over previous
#include <cuda_runtime.h>
#include <cuda_bf16.h>
#include <cuda_fp16.h>
#include <math.h>
#include <cstdint>

#define B_SZ     2
#define SEQ      2048
#define D_MODEL  1024
#define D_INNER  2048
#define D_STATE  16
#define DT_RANK  64
#define D_CONV   4
#define NROWS    (B_SZ * SEQ)             // 4096
#define XPROJ_N  (DT_RANK + 2 * D_STATE)  // 96
#define XPROJ_NPAD 128
#define KSPLIT3  4
#define NCH      16                        // scan chunks
#define CHT      (SEQ / NCH)               // 128 steps per chunk

typedef __half fp16;

// ---------------- scratch (static device globals; no allocation allowed) ---
__device__ __align__(256) float g_xz[(size_t)NROWS * (2 * D_INNER)];
__device__ __align__(256) float g_xdbc[(size_t)NROWS * XPROJ_N];
__device__ __align__(256) float g_part[(size_t)KSPLIT3 * NROWS * XPROJ_NPAD];
// transposed [d][b*SEQ+l] scan inputs, fp16
__device__ __align__(256) fp16 g_dtT[(size_t)D_INNER * NROWS];
__device__ __align__(256) fp16 g_xcT[(size_t)D_INNER * NROWS];
__device__ __align__(256) fp16 g_zT[(size_t)D_INNER * NROWS];
// fp16 activations
__device__ __align__(256) fp16 g_xh[(size_t)NROWS * D_MODEL];
__device__ __align__(256) fp16 g_xconvh[(size_t)NROWS * D_INNER];
__device__ __align__(256) fp16 g_xdh[(size_t)NROWS * DT_RANK];
__device__ __align__(256) fp16 g_yh[(size_t)NROWS * D_INNER];
// fp16 transposed weights [N, K]
__device__ __align__(256) fp16 g_winT[(size_t)(2 * D_INNER) * D_MODEL];
__device__ __align__(256) fp16 g_woutT[(size_t)D_MODEL * D_INNER];
__device__ __align__(256) fp16 g_wxT[(size_t)XPROJ_NPAD * D_INNER];
__device__ __align__(256) fp16 g_wdtT[(size_t)D_INNER * DT_RANK];

// ======================= helpers ===========================================
__device__ __forceinline__ uint32_t smem_u32(const void* p) {
    uint32_t a;
    asm("{ .reg .u64 t; cvta.to.shared.u64 t, %1; cvt.u32.u64 %0, t; }"
        : "=r"(a) : "l"(p));
    return a;
}
__device__ __forceinline__ void cp_async16(uint32_t dst, const void* src) {
    asm volatile("cp.async.cg.shared.global [%0], [%1], 16;"
                 :: "r"(dst), "l"(src));
}
#define CP_COMMIT() asm volatile("cp.async.commit_group;")
#define CP_WAIT0()  asm volatile("cp.async.wait_group 0;")
#define CP_WAIT1()  asm volatile("cp.async.wait_group 1;")

__device__ __forceinline__ void ldsm_x4(uint32_t* r, uint32_t addr) {
    asm volatile("ldmatrix.sync.aligned.m8n8.x4.shared.b16 {%0,%1,%2,%3}, [%4];"
                 : "=r"(r[0]), "=r"(r[1]), "=r"(r[2]), "=r"(r[3]) : "r"(addr));
}

__device__ __forceinline__ void mma16816(float* c, const uint32_t* a,
                                         const uint32_t* b) {
    asm volatile(
        "mma.sync.aligned.m16n8k16.row.col.f32.f16.f16.f32 "
        "{%0,%1,%2,%3}, {%4,%5,%6,%7}, {%8,%9}, {%0,%1,%2,%3};\n"
        : "+f"(c[0]), "+f"(c[1]), "+f"(c[2]), "+f"(c[3])
        : "r"(a[0]), "r"(a[1]), "r"(a[2]), "r"(a[3]),
          "r"(b[0]), "r"(b[1]));
}

// load 8 consecutive fp16 -> 8 floats (16B aligned)
__device__ __forceinline__ void load8h(const fp16* p, float* v) {
    uint4 raw = *reinterpret_cast<const uint4*>(p);
    const __half2* h2 = reinterpret_cast<const __half2*>(&raw);
#pragma unroll
    for (int i = 0; i < 4; i++) {
        float2 f = __half22float2(h2[i]);
        v[2 * i] = f.x; v[2 * i + 1] = f.y;
    }
}

// ===== GEMM: C[M,N] = A * B^T, single-pass fp16, 3-stage cp.async =========
// act: 0 none; 1 softplus + column bias; 2 softplus + ROW bias.
// Ch != nullptr -> write fp16 output (half2 stores), else fp32 (float2).
#define ROW_BYTES 80u
#define TILE_B    (128u * ROW_BYTES)    // 10240
#define STAGE_B   (2u * TILE_B)         // 20480 (A|B)
#define NSTAGE    3
#define SMEM_TOT  (NSTAGE * STAGE_B)    // 61440

__global__ void __launch_bounds__(256)
gemm1p(const fp16* __restrict__ A, const fp16* __restrict__ B,
       float* __restrict__ C, fp16* __restrict__ Ch,
       int Nc, int K, int kstart_ch, int kch, int ldc,
       const float* __restrict__ bias, int act, size_t partStride)
{
    extern __shared__ __align__(16) char smem_raw[];
    const uint32_t sb = smem_u32(smem_raw);

    kstart_ch += blockIdx.z * kch;          // split-K slice

    const int tid = threadIdx.x;
    const int wid = tid >> 5, lane = tid & 31;
    const int gr = lane >> 2, q = lane & 3;
    const int row0 = blockIdx.y * 128, col0 = blockIdx.x * 128;
    const int warp_m = (wid & 1) * 64, warp_n = (wid >> 1) * 32;

    float* Cout = C ? (C + (size_t)blockIdx.z * partStride) : nullptr;

    const fp16* tbA = A + (size_t)row0 * K;
    const fp16* tbB = B + (size_t)col0 * K;

    float acc[4][4][4];
#pragma unroll
    for (int i = 0; i < 4; i++)
#pragma unroll
        for (int j = 0; j < 4; j++)
#pragma unroll
            for (int r = 0; r < 4; r++) acc[i][j][r] = 0.f;

    auto load_stage = [&](int c, int s) {
        int koff = (kstart_ch + c) << 5;
#pragma unroll
        for (int i = 0; i < 4; i++) {
            int seg = tid + 256 * i;            // 0..1023
            int buf = seg >> 9;                 // 0 = A, 1 = B
            int w   = seg & 511;
            int row = w >> 2, s4 = w & 3;
            const fp16* base = buf ? tbB : tbA;
            const fp16* g = base + (size_t)row * K + koff + s4 * 8;
            uint32_t dst = sb + (uint32_t)s * STAGE_B + (uint32_t)buf * TILE_B
                         + (uint32_t)row * ROW_BYTES + (uint32_t)s4 * 16u;
            cp_async16(dst, g);
        }
    };

    const uint32_t a_row  = (uint32_t)(lane & 15);
    const uint32_t a_koff = (uint32_t)(lane >> 4) * 16u;
    const uint32_t b_row  = (uint32_t)(((lane >> 4) << 3) + (lane & 7));
    const uint32_t b_koff = (uint32_t)((lane >> 3) & 1) * 16u;

    // prologue: fill 2 of 3 stages
    load_stage(0, 0);
    CP_COMMIT();
    if (kch > 1) { load_stage(1, 1); CP_COMMIT(); }

    int snext = 2;                       // stage slot for chunk c+2
    for (int c = 0; c < kch; c++) {
        if (c + 1 < kch) CP_WAIT1();     // keep newest group in flight
        else             CP_WAIT0();     // tail: need everything
        __syncthreads();
        if (c + 2 < kch) {
            load_stage(c + 2, snext);
            CP_COMMIT();
        }

        const int scur = (c < NSTAGE) ? c : snext;  // c mod 3, cheap form
        const uint32_t st = sb + (uint32_t)(c - (c / NSTAGE) * NSTAGE) * STAGE_B;
        (void)scur;
        const uint32_t sA = st;
        const uint32_t sB = st + TILE_B;
        snext = snext + 1 == NSTAGE ? 0 : snext + 1;

#pragma unroll
        for (int kc = 0; kc < 2; kc++) {
            uint32_t aH[4][4], bH[8];
#pragma unroll
            for (int mt = 0; mt < 4; mt++) {
                uint32_t roff = ((uint32_t)(warp_m + mt * 16) + a_row) * ROW_BYTES
                              + kc * 32u + a_koff;
                ldsm_x4(aH[mt], sA + roff);
            }
            {
                uint32_t r0 = ((uint32_t)warp_n + b_row) * ROW_BYTES
                            + kc * 32u + b_koff;
                uint32_t r1 = r0 + 16u * ROW_BYTES;
                ldsm_x4(bH + 0, sB + r0);
                ldsm_x4(bH + 4, sB + r1);
            }
#pragma unroll
            for (int mt = 0; mt < 4; mt++)
#pragma unroll
                for (int nt = 0; nt < 4; nt++)
                    mma16816(acc[mt][nt], aH[mt], bH + nt * 2);
        }
    }

    // ---------------- epilogue ----------------
#pragma unroll
    for (int mt = 0; mt < 4; mt++) {
#pragma unroll
        for (int nt = 0; nt < 4; nt++) {
            int rg = row0 + warp_m + mt * 16 + gr;
            int cg = col0 + warp_n + nt * 8 + 2 * q;
            float* cc = acc[mt][nt];
#pragma unroll
            for (int half = 0; half < 2; half++) {
                int r = rg + half * 8;
                float v0 = cc[half * 2 + 0];
                float v1 = cc[half * 2 + 1];
                if (bias) {
                    if (act == 2) { float bb = bias[r]; v0 += bb; v1 += bb; }
                    else          { v0 += bias[cg]; v1 += bias[cg + 1]; }
                }
                if (act) {
                    v0 = (v0 > 20.f) ? v0 : log1pf(expf(v0));
                    v1 = (v1 > 20.f) ? v1 : log1pf(expf(v1));
                }
                if (cg + 1 < Nc) {
                    if (Ch) {
                        *reinterpret_cast<__half2*>(&Ch[(size_t)r * ldc + cg]) =
                            __floats2half2_rn(v0, v1);
                    } else {
                        *reinterpret_cast<float2*>(&Cout[(size_t)r * ldc + cg]) =
                            make_float2(v0, v1);
                    }
                } else if (cg < Nc) {
                    if (Ch) Ch[(size_t)r * ldc + cg] = __float2half_rn(v0);
                    else    Cout[(size_t)r * ldc + cg] = v0;
                }
            }
        }
    }
}

// -------- split-K reduce for xproj GEMM: sum partials, write xdbc + xdh ----
__global__ void reduce3_kernel(const float* __restrict__ part,
                               float* __restrict__ xdbc,
                               fp16* __restrict__ xdh)
{
    int i = blockIdx.x * 256 + threadIdx.x;
    if (i >= NROWS * XPROJ_N) return;
    int r = i / XPROJ_N, c = i - r * XPROJ_N;
    const size_t ps = (size_t)NROWS * XPROJ_NPAD;
    float v = 0.f;
#pragma unroll
    for (int p = 0; p < KSPLIT3; p++)
        v += part[p * ps + (size_t)r * XPROJ_NPAD + c];
    xdbc[(size_t)r * XPROJ_N + c] = v;
    if (c < DT_RANK)
        xdh[(size_t)r * DT_RANK + c] = __float2half_rn(v);
}

// ======= weight transpose -> fp16 [Npad, K] ================================
__global__ void wsplit_kernel(const float* __restrict__ W,
                              fp16* __restrict__ Th,
                              int K, int N, int Npad)
{
    __shared__ float tile[32][33];
    int kb = blockIdx.y * 32, nb = blockIdx.x * 32;
    int tx = threadIdx.x, ty = threadIdx.y;
#pragma unroll
    for (int i = ty; i < 32; i += 8) {
        int k = kb + i, n = nb + tx;
        tile[i][tx] = (k < K && n < N) ? W[(size_t)k * N + n] : 0.f;
    }
    __syncthreads();
#pragma unroll
    for (int i = ty; i < 32; i += 8) {
        int n = nb + i, k = kb + tx;
        if (n < Npad && k < K)
            Th[(size_t)n * K + k] = __float2half_rn(tile[tx][i]);
    }
}

// ---------------- elementwise fp32 -> fp16 convert -------------------------
__global__ void fconv_kernel(const float* __restrict__ X,
                             fp16* __restrict__ H, int n)
{
    int i = blockIdx.x * blockDim.x + threadIdx.x;
    if (i >= n) return;
    H[i] = __float2half_rn(X[i]);
}

// ====== fused causal conv + SiLU + transposes (one pass over xz) ===========
__global__ void convT_kernel(const float* __restrict__ xz,
                             const float* __restrict__ w_conv,
                             const float* __restrict__ b_conv,
                             fp16* __restrict__ xcT, fp16* __restrict__ zT,
                             fp16* __restrict__ xch)
{
    __shared__ float tin[35][33];
    __shared__ float tout[32][33];
    __shared__ float tz[32][33];
    const int b  = blockIdx.z;
    const int l0 = blockIdx.x * 32, d0 = blockIdx.y * 32;
    const int tx = threadIdx.x, ty = threadIdx.y;     // 32 x 8

    for (int j = ty; j < 35; j += 8) {
        int l = l0 - 3 + j;
        tin[j][tx] = (l >= 0) ? xz[(size_t)(b * SEQ + l) * (2 * D_INNER) + d0 + tx]
                              : 0.f;
    }
#pragma unroll
    for (int i = ty; i < 32; i += 8)
        tz[i][tx] = xz[(size_t)(b * SEQ + l0 + i) * (2 * D_INNER) + D_INNER + d0 + tx];
    __syncthreads();

    const float w0 = w_conv[(d0 + tx) * D_CONV + 0];
    const float w1 = w_conv[(d0 + tx) * D_CONV + 1];
    const float w2 = w_conv[(d0 + tx) * D_CONV + 2];
    const float w3 = w_conv[(d0 + tx) * D_CONV + 3];
    const float bc = b_conv[d0 + tx];
#pragma unroll
    for (int i = ty; i < 32; i += 8) {
        float acc = bc + tin[i][tx] * w0 + tin[i + 1][tx] * w1
                       + tin[i + 2][tx] * w2 + tin[i + 3][tx] * w3;
        float s = 1.f / (1.f + __expf(-acc));
        float v = acc * s;
        tout[i][tx] = v;
        xch[(size_t)(b * SEQ + l0 + i) * D_INNER + d0 + tx] = __float2half_rn(v);
    }
    __syncthreads();
#pragma unroll
    for (int i = ty; i < 32; i += 8) {
        size_t o = (size_t)(d0 + i) * NROWS + b * SEQ + l0 + tx;
        xcT[o] = __float2half_rn(tout[tx][i]);
        zT[o]  = __float2half_rn(tz[tx][i]);
    }
}

// ================== fused chunked selective scan (A+B+C) ===================
__global__ void __launch_bounds__(256)
scan_fused_kernel(const fp16* __restrict__ dtT, const fp16* __restrict__ xcT,
                  const fp16* __restrict__ zT,  const float* __restrict__ xdbc,
                  const float* __restrict__ A_log, const float* __restrict__ Dv,
                  fp16* __restrict__ yh)
{
    __shared__ float sP[NCH][D_STATE];
    __shared__ float sS[NCH][D_STATE];

    const int blk = blockIdx.x;            // b*D_INNER + d
    const int d = blk & (D_INNER - 1), b = blk >> 11;
    const int t = threadIdx.x;
    const int n = t & 15, c = t >> 4;

    const float An = -expf(A_log[d * D_STATE + n]);
    const size_t chan = (size_t)d * NROWS + b * SEQ;
    const fp16* dtp = dtT + chan + c * CHT;
    const fp16* xcp = xcT + chan + c * CHT;
    const fp16* zp  = zT  + chan + c * CHT;
    const float* bc0 = xdbc + ((size_t)(b * SEQ + c * CHT)) * XPROJ_N;

    // ---- Phase A: per-chunk affine coefficients ----
    {
        const float* bc = bc0;
        float P = 1.f, S = 0.f;
        for (int l0 = 0; l0 < CHT; l0 += 8) {
            float dtv[8], xvv[8];
            load8h(dtp + l0, dtv);
            load8h(xcp + l0, xvv);
#pragma unroll
            for (int j = 0; j < 8; j++) {
                float Bn = bc[DT_RANK + n];
                float a  = __expf(dtv[j] * An);
                S = fmaf(a, S, dtv[j] * xvv[j] * Bn);
                P *= a;
                bc += XPROJ_N;
            }
        }
        sP[c][n] = P; sS[c][n] = S;
    }
    __syncthreads();

    // ---- Phase B: per-thread prefix over earlier chunks ----
    float h = 0.f;
    for (int cc = 0; cc < c; cc++)
        h = fmaf(sP[cc][n], h, sS[cc][n]);

    // ---- Phase C: replay with correct h_in, reduce y, gate, store ----
    const float Dd = Dv[d];
    const float* bc = bc0;
    size_t yrow = (size_t)(b * SEQ + c * CHT) * D_INNER + d;

    for (int l0 = 0; l0 < CHT; l0 += 8) {
        float dtv[8], xvv[8], zvv[8];
        load8h(dtp + l0, dtv);
        load8h(xcp + l0, xvv);
        load8h(zp + l0, zvv);
#pragma unroll
        for (int j = 0; j < 8; j++) {
            float Bn = bc[DT_RANK + n];
            float Cn = bc[DT_RANK + D_STATE + n];
            float a  = __expf(dtv[j] * An);
            h = fmaf(a, h, dtv[j] * xvv[j] * Bn);
            float part = Cn * h;
            part += __shfl_xor_sync(0xffffffffu, part, 1);
            part += __shfl_xor_sync(0xffffffffu, part, 2);
            part += __shfl_xor_sync(0xffffffffu, part, 4);
            part += __shfl_xor_sync(0xffffffffu, part, 8);
            if (n == 0) {
                float z   = zvv[j];
                float sig = 1.f / (1.f + __expf(-z));
                float yv  = (part + xvv[j] * Dd) * (z * sig);
                yh[yrow] = __float2half_rn(yv);
            }
            bc += XPROJ_N;
            yrow += D_INNER;
        }
    }
}

// ---------------- launcher -------------------------------------------------
extern "C" void kernel_launch(void* const* d_in, const int* in_sizes, int n_in,
                              void* d_out, int out_size)
{
    const float* x       = (const float*)d_in[0];
    const float* w_in    = (const float*)d_in[1];
    const float* w_conv  = (const float*)d_in[2];
    const float* b_conv  = (const float*)d_in[3];
    const float* w_xproj = (const float*)d_in[4];
    const float* w_dt    = (const float*)d_in[5];
    const float* b_dt    = (const float*)d_in[6];
    const float* A_log   = (const float*)d_in[7];
    const float* Dv      = (const float*)d_in[8];
    const float* w_out   = (const float*)d_in[9];
    float* out = (float*)d_out;

    float *xz, *xdbc, *part;
    fp16 *dtT, *xcT, *zT;
    fp16 *xh, *xch, *xdh, *yh;
    fp16 *winT, *woutT, *wxT, *wdtT;
    cudaGetSymbolAddress((void**)&xz,    g_xz);
    cudaGetSymbolAddress((void**)&xdbc,  g_xdbc);
    cudaGetSymbolAddress((void**)&part,  g_part);
    cudaGetSymbolAddress((void**)&dtT,   g_dtT);
    cudaGetSymbolAddress((void**)&xcT,   g_xcT);
    cudaGetSymbolAddress((void**)&zT,    g_zT);
    cudaGetSymbolAddress((void**)&xh,    g_xh);
    cudaGetSymbolAddress((void**)&xch,   g_xconvh);
    cudaGetSymbolAddress((void**)&xdh,   g_xdh);
    cudaGetSymbolAddress((void**)&yh,    g_yh);
    cudaGetSymbolAddress((void**)&winT,  g_winT);
    cudaGetSymbolAddress((void**)&woutT, g_woutT);
    cudaGetSymbolAddress((void**)&wxT,   g_wxT);
    cudaGetSymbolAddress((void**)&wdtT,  g_wdtT);

    cudaFuncSetAttribute(gemm1p, cudaFuncAttributeMaxDynamicSharedMemorySize,
                         SMEM_TOT);

    dim3 tb(32, 8);
    // launches 0-2: prep for gemm1 (gemm1 stays at ncu index 3)
    fconv_kernel<<<(NROWS * D_MODEL + 255) / 256, 256>>>(x, xh, NROWS * D_MODEL);
    wsplit_kernel<<<dim3(4096 / 32, 1024 / 32), tb>>>(w_in, winT,
                                                      D_MODEL, 2 * D_INNER, 2 * D_INNER);
    wsplit_kernel<<<dim3(XPROJ_NPAD / 32, 2048 / 32), tb>>>(w_xproj, wxT,
                                                            D_INNER, XPROJ_N, XPROJ_NPAD);
    // launch 3: xz = x @ w_in          M=4096 N=4096 K=1024   <-- profiled
    gemm1p<<<dim3(32, 32, 1), 256, SMEM_TOT>>>(xh, winT, xz, nullptr,
                                               2 * D_INNER, D_MODEL, 0,
                                               D_MODEL / 32, 2 * D_INNER,
                                               nullptr, 0, 0);
    // remaining weight preps
    wsplit_kernel<<<dim3(2048 / 32, 64 / 32), tb>>>(w_dt, wdtT,
                                                    DT_RANK, D_INNER, D_INNER);
    wsplit_kernel<<<dim3(1024 / 32, 2048 / 32), tb>>>(w_out, woutT,
                                                      D_INNER, D_MODEL, D_MODEL);
    // fused conv + silu + transposes (xcT, zT fp16 + xch fp16 in one pass)
    convT_kernel<<<dim3(SEQ / 32, D_INNER / 32, B_SZ), tb>>>(
        xz, w_conv, b_conv, xcT, zT, xch);
    // xproj: split-K=4 into partials, then reduce (+ dt-rank fp16)
    gemm1p<<<dim3(1, 32, KSPLIT3), 256, SMEM_TOT>>>(
        xch, wxT, part, nullptr,
        XPROJ_NPAD, D_INNER, 0, (D_INNER / 32) / KSPLIT3, XPROJ_NPAD,
        nullptr, 0, (size_t)NROWS * XPROJ_NPAD);
    reduce3_kernel<<<(NROWS * XPROJ_N + 255) / 256, 256>>>(part, xdbc, xdh);
    // dtT[d][b*L+l] = softplus(wdtT @ xdbc_dt^T + b_dt[d])  (fp16 output)
    gemm1p<<<dim3(NROWS / 128, D_INNER / 128, 1), 256, SMEM_TOT>>>(
        wdtT, xdh, nullptr, dtT,
        NROWS, DT_RANK, 0, DT_RANK / 32, NROWS,
        b_dt, 2, 0);
    // fused chunked scan (A+B+C in one kernel)
    scan_fused_kernel<<<B_SZ * D_INNER, 256>>>(
        dtT, xcT, zT, xdbc, A_log, Dv, yh);
    // out = y @ w_out                  M=4096 N=1024 K=2048
    gemm1p<<<dim3(8, 32, 1), 256, SMEM_TOT>>>(yh, woutT, out, nullptr,
                                              D_MODEL, D_INNER, 0,
                                              D_INNER / 32, D_MODEL,
                                              nullptr, 0, 0);
}

// round 13
// speedup vs baseline: 7.0265x; 1.0142x over previous
#include <cuda_runtime.h>
#include <cuda_bf16.h>
#include <cuda_fp16.h>
#include <math.h>
#include <cstdint>

#define B_SZ     2
#define SEQ      2048
#define D_MODEL  1024
#define D_INNER  2048
#define D_STATE  16
#define DT_RANK  64
#define D_CONV   4
#define NROWS    (B_SZ * SEQ)             // 4096
#define XPROJ_N  (DT_RANK + 2 * D_STATE)  // 96
#define XPROJ_NPAD 128
#define KSPLIT3  8
#define NCH      16                        // scan chunks
#define CHT      (SEQ / NCH)               // 128 steps per chunk

typedef __half fp16;

// ---------------- scratch (static device globals; no allocation allowed) ---
__device__ __align__(256) float g_xz[(size_t)NROWS * (2 * D_INNER)];
__device__ __align__(256) float g_xdbc[(size_t)NROWS * XPROJ_N];
__device__ __align__(256) float g_part[(size_t)KSPLIT3 * NROWS * XPROJ_NPAD];
// transposed [d][b*SEQ+l] scan inputs, fp16
__device__ __align__(256) fp16 g_dtT[(size_t)D_INNER * NROWS];
__device__ __align__(256) fp16 g_xcT[(size_t)D_INNER * NROWS];
__device__ __align__(256) fp16 g_zT[(size_t)D_INNER * NROWS];
// fp16 activations
__device__ __align__(256) fp16 g_xh[(size_t)NROWS * D_MODEL];
__device__ __align__(256) fp16 g_xconvh[(size_t)NROWS * D_INNER];
__device__ __align__(256) fp16 g_xdh[(size_t)NROWS * DT_RANK];
__device__ __align__(256) fp16 g_yh[(size_t)NROWS * D_INNER];
// fp16 transposed weights [N, K]
__device__ __align__(256) fp16 g_winT[(size_t)(2 * D_INNER) * D_MODEL];
__device__ __align__(256) fp16 g_woutT[(size_t)D_MODEL * D_INNER];
__device__ __align__(256) fp16 g_wxT[(size_t)XPROJ_NPAD * D_INNER];
__device__ __align__(256) fp16 g_wdtT[(size_t)D_INNER * DT_RANK];

// ======================= helpers ===========================================
__device__ __forceinline__ uint32_t smem_u32(const void* p) {
    uint32_t a;
    asm("{ .reg .u64 t; cvta.to.shared.u64 t, %1; cvt.u32.u64 %0, t; }"
        : "=r"(a) : "l"(p));
    return a;
}
__device__ __forceinline__ void cp_async16(uint32_t dst, const void* src) {
    asm volatile("cp.async.cg.shared.global [%0], [%1], 16;"
                 :: "r"(dst), "l"(src));
}
#define CP_COMMIT() asm volatile("cp.async.commit_group;")
#define CP_WAIT0()  asm volatile("cp.async.wait_group 0;")
#define CP_WAIT1()  asm volatile("cp.async.wait_group 1;")

__device__ __forceinline__ void ldsm_x4(uint32_t* r, uint32_t addr) {
    asm volatile("ldmatrix.sync.aligned.m8n8.x4.shared.b16 {%0,%1,%2,%3}, [%4];"
                 : "=r"(r[0]), "=r"(r[1]), "=r"(r[2]), "=r"(r[3]) : "r"(addr));
}

__device__ __forceinline__ void mma16816(float* c, const uint32_t* a,
                                         const uint32_t* b) {
    asm volatile(
        "mma.sync.aligned.m16n8k16.row.col.f32.f16.f16.f32 "
        "{%0,%1,%2,%3}, {%4,%5,%6,%7}, {%8,%9}, {%0,%1,%2,%3};\n"
        : "+f"(c[0]), "+f"(c[1]), "+f"(c[2]), "+f"(c[3])
        : "r"(a[0]), "r"(a[1]), "r"(a[2]), "r"(a[3]),
          "r"(b[0]), "r"(b[1]));
}

// load 8 consecutive fp16 -> 8 floats (16B aligned)
__device__ __forceinline__ void load8h(const fp16* p, float* v) {
    uint4 raw = *reinterpret_cast<const uint4*>(p);
    const __half2* h2 = reinterpret_cast<const __half2*>(&raw);
#pragma unroll
    for (int i = 0; i < 4; i++) {
        float2 f = __half22float2(h2[i]);
        v[2 * i] = f.x; v[2 * i + 1] = f.y;
    }
}

// ===== GEMM: C[M,N] = A * B^T, single-pass fp16, 3-stage cp.async =========
// act: 0 none; 1 softplus + column bias; 2 softplus + ROW bias.
// Ch != nullptr -> write fp16 output (half2 stores), else fp32 (float2).
#define ROW_BYTES 80u
#define TILE_B    (128u * ROW_BYTES)    // 10240
#define STAGE_B   (2u * TILE_B)         // 20480 (A|B)
#define NSTAGE    3
#define SMEM_TOT  (NSTAGE * STAGE_B)    // 61440

__global__ void __launch_bounds__(256)
gemm1p(const fp16* __restrict__ A, const fp16* __restrict__ B,
       float* __restrict__ C, fp16* __restrict__ Ch,
       int Nc, int K, int kstart_ch, int kch, int ldc,
       const float* __restrict__ bias, int act, size_t partStride)
{
    extern __shared__ __align__(16) char smem_raw[];
    const uint32_t sb = smem_u32(smem_raw);

    kstart_ch += blockIdx.z * kch;          // split-K slice

    const int tid = threadIdx.x;
    const int wid = tid >> 5, lane = tid & 31;
    const int gr = lane >> 2, q = lane & 3;
    const int row0 = blockIdx.y * 128, col0 = blockIdx.x * 128;
    const int warp_m = (wid & 1) * 64, warp_n = (wid >> 1) * 32;

    float* Cout = C ? (C + (size_t)blockIdx.z * partStride) : nullptr;

    const fp16* tbA = A + (size_t)row0 * K;
    const fp16* tbB = B + (size_t)col0 * K;

    float acc[4][4][4];
#pragma unroll
    for (int i = 0; i < 4; i++)
#pragma unroll
        for (int j = 0; j < 4; j++)
#pragma unroll
            for (int r = 0; r < 4; r++) acc[i][j][r] = 0.f;

    auto load_stage = [&](int c, int s) {
        int koff = (kstart_ch + c) << 5;
#pragma unroll
        for (int i = 0; i < 4; i++) {
            int seg = tid + 256 * i;            // 0..1023
            int buf = seg >> 9;                 // 0 = A, 1 = B
            int w   = seg & 511;
            int row = w >> 2, s4 = w & 3;
            const fp16* base = buf ? tbB : tbA;
            const fp16* g = base + (size_t)row * K + koff + s4 * 8;
            uint32_t dst = sb + (uint32_t)s * STAGE_B + (uint32_t)buf * TILE_B
                         + (uint32_t)row * ROW_BYTES + (uint32_t)s4 * 16u;
            cp_async16(dst, g);
        }
    };

    const uint32_t a_row  = (uint32_t)(lane & 15);
    const uint32_t a_koff = (uint32_t)(lane >> 4) * 16u;
    const uint32_t b_row  = (uint32_t)(((lane >> 4) << 3) + (lane & 7));
    const uint32_t b_koff = (uint32_t)((lane >> 3) & 1) * 16u;

    // prologue: fill 2 of 3 stages
    load_stage(0, 0);
    CP_COMMIT();
    if (kch > 1) { load_stage(1, 1); CP_COMMIT(); }

    int snext = 2;                       // stage slot for chunk c+2
    for (int c = 0; c < kch; c++) {
        if (c + 1 < kch) CP_WAIT1();     // keep newest group in flight
        else             CP_WAIT0();     // tail: need everything
        __syncthreads();
        if (c + 2 < kch) {
            load_stage(c + 2, snext);
            CP_COMMIT();
        }

        const uint32_t st = sb + (uint32_t)(c - (c / NSTAGE) * NSTAGE) * STAGE_B;
        const uint32_t sA = st;
        const uint32_t sB = st + TILE_B;
        snext = snext + 1 == NSTAGE ? 0 : snext + 1;

#pragma unroll
        for (int kc = 0; kc < 2; kc++) {
            uint32_t aH[4][4], bH[8];
#pragma unroll
            for (int mt = 0; mt < 4; mt++) {
                uint32_t roff = ((uint32_t)(warp_m + mt * 16) + a_row) * ROW_BYTES
                              + kc * 32u + a_koff;
                ldsm_x4(aH[mt], sA + roff);
            }
            {
                uint32_t r0 = ((uint32_t)warp_n + b_row) * ROW_BYTES
                            + kc * 32u + b_koff;
                uint32_t r1 = r0 + 16u * ROW_BYTES;
                ldsm_x4(bH + 0, sB + r0);
                ldsm_x4(bH + 4, sB + r1);
            }
#pragma unroll
            for (int mt = 0; mt < 4; mt++)
#pragma unroll
                for (int nt = 0; nt < 4; nt++)
                    mma16816(acc[mt][nt], aH[mt], bH + nt * 2);
        }
    }

    // ---------------- epilogue ----------------
#pragma unroll
    for (int mt = 0; mt < 4; mt++) {
#pragma unroll
        for (int nt = 0; nt < 4; nt++) {
            int rg = row0 + warp_m + mt * 16 + gr;
            int cg = col0 + warp_n + nt * 8 + 2 * q;
            float* cc = acc[mt][nt];
#pragma unroll
            for (int half = 0; half < 2; half++) {
                int r = rg + half * 8;
                float v0 = cc[half * 2 + 0];
                float v1 = cc[half * 2 + 1];
                if (bias) {
                    if (act == 2) { float bb = bias[r]; v0 += bb; v1 += bb; }
                    else          { v0 += bias[cg]; v1 += bias[cg + 1]; }
                }
                if (act) {
                    v0 = (v0 > 20.f) ? v0 : log1pf(expf(v0));
                    v1 = (v1 > 20.f) ? v1 : log1pf(expf(v1));
                }
                if (cg + 1 < Nc) {
                    if (Ch) {
                        *reinterpret_cast<__half2*>(&Ch[(size_t)r * ldc + cg]) =
                            __floats2half2_rn(v0, v1);
                    } else {
                        *reinterpret_cast<float2*>(&Cout[(size_t)r * ldc + cg]) =
                            make_float2(v0, v1);
                    }
                } else if (cg < Nc) {
                    if (Ch) Ch[(size_t)r * ldc + cg] = __float2half_rn(v0);
                    else    Cout[(size_t)r * ldc + cg] = v0;
                }
            }
        }
    }
}

// -------- split-K reduce for xproj GEMM: sum partials, write xdbc + xdh ----
__global__ void reduce3_kernel(const float* __restrict__ part,
                               float* __restrict__ xdbc,
                               fp16* __restrict__ xdh)
{
    int i = blockIdx.x * 256 + threadIdx.x;
    if (i >= NROWS * XPROJ_N) return;
    int r = i / XPROJ_N, c = i - r * XPROJ_N;
    const size_t ps = (size_t)NROWS * XPROJ_NPAD;
    float v = 0.f;
#pragma unroll
    for (int p = 0; p < KSPLIT3; p++)
        v += part[p * ps + (size_t)r * XPROJ_NPAD + c];
    xdbc[(size_t)r * XPROJ_N + c] = v;
    if (c < DT_RANK)
        xdh[(size_t)r * DT_RANK + c] = __float2half_rn(v);
}

// ======= weight transpose -> fp16 [Npad, K] ================================
__global__ void wsplit_kernel(const float* __restrict__ W,
                              fp16* __restrict__ Th,
                              int K, int N, int Npad)
{
    __shared__ float tile[32][33];
    int kb = blockIdx.y * 32, nb = blockIdx.x * 32;
    int tx = threadIdx.x, ty = threadIdx.y;
#pragma unroll
    for (int i = ty; i < 32; i += 8) {
        int k = kb + i, n = nb + tx;
        tile[i][tx] = (k < K && n < N) ? W[(size_t)k * N + n] : 0.f;
    }
    __syncthreads();
#pragma unroll
    for (int i = ty; i < 32; i += 8) {
        int n = nb + i, k = kb + tx;
        if (n < Npad && k < K)
            Th[(size_t)n * K + k] = __float2half_rn(tile[tx][i]);
    }
}

// ---------------- elementwise fp32 -> fp16 convert (8 per thread) ----------
__global__ void fconv_kernel(const float* __restrict__ X,
                             fp16* __restrict__ H, int n)
{
    int i = (blockIdx.x * blockDim.x + threadIdx.x) * 8;
    if (i >= n) return;
    float4 a = *reinterpret_cast<const float4*>(X + i);
    float4 b = *reinterpret_cast<const float4*>(X + i + 4);
    __half2 h0 = __floats2half2_rn(a.x, a.y);
    __half2 h1 = __floats2half2_rn(a.z, a.w);
    __half2 h2 = __floats2half2_rn(b.x, b.y);
    __half2 h3 = __floats2half2_rn(b.z, b.w);
    uint4 out;
    out.x = *reinterpret_cast<uint32_t*>(&h0);
    out.y = *reinterpret_cast<uint32_t*>(&h1);
    out.z = *reinterpret_cast<uint32_t*>(&h2);
    out.w = *reinterpret_cast<uint32_t*>(&h3);
    *reinterpret_cast<uint4*>(H + i) = out;
}

// ====== fused causal conv + SiLU + transposes (one pass over xz) ===========
__global__ void convT_kernel(const float* __restrict__ xz,
                             const float* __restrict__ w_conv,
                             const float* __restrict__ b_conv,
                             fp16* __restrict__ xcT, fp16* __restrict__ zT,
                             fp16* __restrict__ xch)
{
    __shared__ float tin[35][33];
    __shared__ float tout[32][33];
    __shared__ float tz[32][33];
    const int b  = blockIdx.z;
    const int l0 = blockIdx.x * 32, d0 = blockIdx.y * 32;
    const int tx = threadIdx.x, ty = threadIdx.y;     // 32 x 8

    for (int j = ty; j < 35; j += 8) {
        int l = l0 - 3 + j;
        tin[j][tx] = (l >= 0) ? xz[(size_t)(b * SEQ + l) * (2 * D_INNER) + d0 + tx]
                              : 0.f;
    }
#pragma unroll
    for (int i = ty; i < 32; i += 8)
        tz[i][tx] = xz[(size_t)(b * SEQ + l0 + i) * (2 * D_INNER) + D_INNER + d0 + tx];
    __syncthreads();

    const float w0 = w_conv[(d0 + tx) * D_CONV + 0];
    const float w1 = w_conv[(d0 + tx) * D_CONV + 1];
    const float w2 = w_conv[(d0 + tx) * D_CONV + 2];
    const float w3 = w_conv[(d0 + tx) * D_CONV + 3];
    const float bc = b_conv[d0 + tx];
#pragma unroll
    for (int i = ty; i < 32; i += 8) {
        float acc = bc + tin[i][tx] * w0 + tin[i + 1][tx] * w1
                       + tin[i + 2][tx] * w2 + tin[i + 3][tx] * w3;
        float s = 1.f / (1.f + __expf(-acc));
        float v = acc * s;
        tout[i][tx] = v;
        xch[(size_t)(b * SEQ + l0 + i) * D_INNER + d0 + tx] = __float2half_rn(v);
    }
    __syncthreads();
#pragma unroll
    for (int i = ty; i < 32; i += 8) {
        size_t o = (size_t)(d0 + i) * NROWS + b * SEQ + l0 + tx;
        xcT[o] = __float2half_rn(tout[tx][i]);
        zT[o]  = __float2half_rn(tz[tx][i]);
    }
}

// ================== fused chunked selective scan (A+B+C) ===================
__global__ void __launch_bounds__(256)
scan_fused_kernel(const fp16* __restrict__ dtT, const fp16* __restrict__ xcT,
                  const fp16* __restrict__ zT,  const float* __restrict__ xdbc,
                  const float* __restrict__ A_log, const float* __restrict__ Dv,
                  fp16* __restrict__ yh)
{
    __shared__ float sP[NCH][D_STATE];
    __shared__ float sS[NCH][D_STATE];

    const int blk = blockIdx.x;            // b*D_INNER + d
    const int d = blk & (D_INNER - 1), b = blk >> 11;
    const int t = threadIdx.x;
    const int n = t & 15, c = t >> 4;

    const float An = -expf(A_log[d * D_STATE + n]);
    const size_t chan = (size_t)d * NROWS + b * SEQ;
    const fp16* dtp = dtT + chan + c * CHT;
    const fp16* xcp = xcT + chan + c * CHT;
    const fp16* zp  = zT  + chan + c * CHT;
    const float* bc0 = xdbc + ((size_t)(b * SEQ + c * CHT)) * XPROJ_N;

    // ---- Phase A: per-chunk affine coefficients ----
    {
        const float* bc = bc0;
        float P = 1.f, S = 0.f;
        for (int l0 = 0; l0 < CHT; l0 += 8) {
            float dtv[8], xvv[8];
            load8h(dtp + l0, dtv);
            load8h(xcp + l0, xvv);
#pragma unroll
            for (int j = 0; j < 8; j++) {
                float Bn = bc[DT_RANK + n];
                float a  = __expf(dtv[j] * An);
                S = fmaf(a, S, dtv[j] * xvv[j] * Bn);
                P *= a;
                bc += XPROJ_N;
            }
        }
        sP[c][n] = P; sS[c][n] = S;
    }
    __syncthreads();

    // ---- Phase B: per-thread prefix over earlier chunks ----
    float h = 0.f;
    for (int cc = 0; cc < c; cc++)
        h = fmaf(sP[cc][n], h, sS[cc][n]);

    // ---- Phase C: replay with correct h_in, reduce y, gate, store ----
    const float Dd = Dv[d];
    const float* bc = bc0;
    size_t yrow = (size_t)(b * SEQ + c * CHT) * D_INNER + d;

    for (int l0 = 0; l0 < CHT; l0 += 8) {
        float dtv[8], xvv[8], zvv[8];
        load8h(dtp + l0, dtv);
        load8h(xcp + l0, xvv);
        load8h(zp + l0, zvv);
#pragma unroll
        for (int j = 0; j < 8; j++) {
            float Bn = bc[DT_RANK + n];
            float Cn = bc[DT_RANK + D_STATE + n];
            float a  = __expf(dtv[j] * An);
            h = fmaf(a, h, dtv[j] * xvv[j] * Bn);
            float part = Cn * h;
            part += __shfl_xor_sync(0xffffffffu, part, 1);
            part += __shfl_xor_sync(0xffffffffu, part, 2);
            part += __shfl_xor_sync(0xffffffffu, part, 4);
            part += __shfl_xor_sync(0xffffffffu, part, 8);
            if (n == 0) {
                float z   = zvv[j];
                float sig = 1.f / (1.f + __expf(-z));
                float yv  = (part + xvv[j] * Dd) * (z * sig);
                yh[yrow] = __float2half_rn(yv);
            }
            bc += XPROJ_N;
            yrow += D_INNER;
        }
    }
}

// ---------------- launcher -------------------------------------------------
extern "C" void kernel_launch(void* const* d_in, const int* in_sizes, int n_in,
                              void* d_out, int out_size)
{
    const float* x       = (const float*)d_in[0];
    const float* w_in    = (const float*)d_in[1];
    const float* w_conv  = (const float*)d_in[2];
    const float* b_conv  = (const float*)d_in[3];
    const float* w_xproj = (const float*)d_in[4];
    const float* w_dt    = (const float*)d_in[5];
    const float* b_dt    = (const float*)d_in[6];
    const float* A_log   = (const float*)d_in[7];
    const float* Dv      = (const float*)d_in[8];
    const float* w_out   = (const float*)d_in[9];
    float* out = (float*)d_out;

    float *xz, *xdbc, *part;
    fp16 *dtT, *xcT, *zT;
    fp16 *xh, *xch, *xdh, *yh;
    fp16 *winT, *woutT, *wxT, *wdtT;
    cudaGetSymbolAddress((void**)&xz,    g_xz);
    cudaGetSymbolAddress((void**)&xdbc,  g_xdbc);
    cudaGetSymbolAddress((void**)&part,  g_part);
    cudaGetSymbolAddress((void**)&dtT,   g_dtT);
    cudaGetSymbolAddress((void**)&xcT,   g_xcT);
    cudaGetSymbolAddress((void**)&zT,    g_zT);
    cudaGetSymbolAddress((void**)&xh,    g_xh);
    cudaGetSymbolAddress((void**)&xch,   g_xconvh);
    cudaGetSymbolAddress((void**)&xdh,   g_xdh);
    cudaGetSymbolAddress((void**)&yh,    g_yh);
    cudaGetSymbolAddress((void**)&winT,  g_winT);
    cudaGetSymbolAddress((void**)&woutT, g_woutT);
    cudaGetSymbolAddress((void**)&wxT,   g_wxT);
    cudaGetSymbolAddress((void**)&wdtT,  g_wdtT);

    cudaFuncSetAttribute(gemm1p, cudaFuncAttributeMaxDynamicSharedMemorySize,
                         SMEM_TOT);

    dim3 tb(32, 8);
    // 0-2: prep for gemm1; convT lands at profiled index 3
    fconv_kernel<<<(NROWS * D_MODEL / 8 + 255) / 256, 256>>>(x, xh, NROWS * D_MODEL);
    wsplit_kernel<<<dim3(4096 / 32, 1024 / 32), tb>>>(w_in, winT,
                                                      D_MODEL, 2 * D_INNER, 2 * D_INNER);
    // 2: xz = x @ w_in          M=4096 N=4096 K=1024
    gemm1p<<<dim3(32, 32, 1), 256, SMEM_TOT>>>(xh, winT, xz, nullptr,
                                               2 * D_INNER, D_MODEL, 0,
                                               D_MODEL / 32, 2 * D_INNER,
                                               nullptr, 0, 0);
    // 3: fused conv + silu + transposes        <-- profiled this round
    convT_kernel<<<dim3(SEQ / 32, D_INNER / 32, B_SZ), tb>>>(
        xz, w_conv, b_conv, xcT, zT, xch);
    // remaining weight preps
    wsplit_kernel<<<dim3(XPROJ_NPAD / 32, 2048 / 32), tb>>>(w_xproj, wxT,
                                                            D_INNER, XPROJ_N, XPROJ_NPAD);
    wsplit_kernel<<<dim3(2048 / 32, 64 / 32), tb>>>(w_dt, wdtT,
                                                    DT_RANK, D_INNER, D_INNER);
    wsplit_kernel<<<dim3(1024 / 32, 2048 / 32), tb>>>(w_out, woutT,
                                                      D_INNER, D_MODEL, D_MODEL);
    // xproj: split-K=8 into partials, then reduce (+ dt-rank fp16)
    gemm1p<<<dim3(1, 32, KSPLIT3), 256, SMEM_TOT>>>(
        xch, wxT, part, nullptr,
        XPROJ_NPAD, D_INNER, 0, (D_INNER / 32) / KSPLIT3, XPROJ_NPAD,
        nullptr, 0, (size_t)NROWS * XPROJ_NPAD);
    reduce3_kernel<<<(NROWS * XPROJ_N + 255) / 256, 256>>>(part, xdbc, xdh);
    // dtT[d][b*L+l] = softplus(wdtT @ xdbc_dt^T + b_dt[d])  (fp16 output)
    gemm1p<<<dim3(NROWS / 128, D_INNER / 128, 1), 256, SMEM_TOT>>>(
        wdtT, xdh, nullptr, dtT,
        NROWS, DT_RANK, 0, DT_RANK / 32, NROWS,
        b_dt, 2, 0);
    // fused chunked scan (A+B+C in one kernel)
    scan_fused_kernel<<<B_SZ * D_INNER, 256>>>(
        dtT, xcT, zT, xdbc, A_log, Dv, yh);
    // out = y @ w_out                  M=4096 N=1024 K=2048
    gemm1p<<<dim3(8, 32, 1), 256, SMEM_TOT>>>(yh, woutT, out, nullptr,
                                              D_MODEL, D_INNER, 0,
                                              D_INNER / 32, D_MODEL,
                                              nullptr, 0, 0);
}

// round 14
// speedup vs baseline: 7.0287x; 1.0003x over previous
#include <cuda_runtime.h>
#include <cuda_bf16.h>
#include <cuda_fp16.h>
#include <math.h>
#include <cstdint>

#define B_SZ     2
#define SEQ      2048
#define D_MODEL  1024
#define D_INNER  2048
#define D_STATE  16
#define DT_RANK  64
#define D_CONV   4
#define NROWS    (B_SZ * SEQ)             // 4096
#define XPROJ_N  (DT_RANK + 2 * D_STATE)  // 96
#define XPROJ_NPAD 128
#define KSPLIT3  8
#define NCH      16                        // scan chunks
#define CHT      (SEQ / NCH)               // 128 steps per chunk
#define SCH      4                         // d-channels per scan block

typedef __half fp16;

// ---------------- scratch (static device globals; no allocation allowed) ---
__device__ __align__(256) float g_xz[(size_t)NROWS * (2 * D_INNER)];
__device__ __align__(256) float g_xdbc[(size_t)NROWS * XPROJ_N];
__device__ __align__(256) float g_part[(size_t)KSPLIT3 * NROWS * XPROJ_NPAD];
// transposed [d][b*SEQ+l] scan inputs, fp16
__device__ __align__(256) fp16 g_dtT[(size_t)D_INNER * NROWS];
__device__ __align__(256) fp16 g_xcT[(size_t)D_INNER * NROWS];
__device__ __align__(256) fp16 g_zT[(size_t)D_INNER * NROWS];
// fp16 activations
__device__ __align__(256) fp16 g_xh[(size_t)NROWS * D_MODEL];
__device__ __align__(256) fp16 g_xconvh[(size_t)NROWS * D_INNER];
__device__ __align__(256) fp16 g_xdh[(size_t)NROWS * DT_RANK];
__device__ __align__(256) fp16 g_yh[(size_t)NROWS * D_INNER];
// fp16 transposed weights [N, K]
__device__ __align__(256) fp16 g_winT[(size_t)(2 * D_INNER) * D_MODEL];
__device__ __align__(256) fp16 g_woutT[(size_t)D_MODEL * D_INNER];
__device__ __align__(256) fp16 g_wxT[(size_t)XPROJ_NPAD * D_INNER];
__device__ __align__(256) fp16 g_wdtT[(size_t)D_INNER * DT_RANK];

// ======================= helpers ===========================================
__device__ __forceinline__ uint32_t smem_u32(const void* p) {
    uint32_t a;
    asm("{ .reg .u64 t; cvta.to.shared.u64 t, %1; cvt.u32.u64 %0, t; }"
        : "=r"(a) : "l"(p));
    return a;
}
__device__ __forceinline__ void cp_async16(uint32_t dst, const void* src) {
    asm volatile("cp.async.cg.shared.global [%0], [%1], 16;"
                 :: "r"(dst), "l"(src));
}
#define CP_COMMIT() asm volatile("cp.async.commit_group;")
#define CP_WAIT0()  asm volatile("cp.async.wait_group 0;")
#define CP_WAIT1()  asm volatile("cp.async.wait_group 1;")

__device__ __forceinline__ void ldsm_x4(uint32_t* r, uint32_t addr) {
    asm volatile("ldmatrix.sync.aligned.m8n8.x4.shared.b16 {%0,%1,%2,%3}, [%4];"
                 : "=r"(r[0]), "=r"(r[1]), "=r"(r[2]), "=r"(r[3]) : "r"(addr));
}

__device__ __forceinline__ void mma16816(float* c, const uint32_t* a,
                                         const uint32_t* b) {
    asm volatile(
        "mma.sync.aligned.m16n8k16.row.col.f32.f16.f16.f32 "
        "{%0,%1,%2,%3}, {%4,%5,%6,%7}, {%8,%9}, {%0,%1,%2,%3};\n"
        : "+f"(c[0]), "+f"(c[1]), "+f"(c[2]), "+f"(c[3])
        : "r"(a[0]), "r"(a[1]), "r"(a[2]), "r"(a[3]),
          "r"(b[0]), "r"(b[1]));
}

// load 4 consecutive fp16 -> 4 floats (8B aligned)
__device__ __forceinline__ void load4h(const fp16* p, float* v) {
    uint2 raw = *reinterpret_cast<const uint2*>(p);
    const __half2* h2 = reinterpret_cast<const __half2*>(&raw);
    float2 f0 = __half22float2(h2[0]);
    float2 f1 = __half22float2(h2[1]);
    v[0] = f0.x; v[1] = f0.y; v[2] = f1.x; v[3] = f1.y;
}

// ===== GEMM: C[M,N] = A * B^T, single-pass fp16, 3-stage cp.async =========
#define ROW_BYTES 80u
#define TILE_B    (128u * ROW_BYTES)    // 10240
#define STAGE_B   (2u * TILE_B)         // 20480 (A|B)
#define NSTAGE    3
#define SMEM_TOT  (NSTAGE * STAGE_B)    // 61440

__global__ void __launch_bounds__(256)
gemm1p(const fp16* __restrict__ A, const fp16* __restrict__ B,
       float* __restrict__ C, fp16* __restrict__ Ch,
       int Nc, int K, int kstart_ch, int kch, int ldc,
       const float* __restrict__ bias, int act, size_t partStride)
{
    extern __shared__ __align__(16) char smem_raw[];
    const uint32_t sb = smem_u32(smem_raw);

    kstart_ch += blockIdx.z * kch;          // split-K slice

    const int tid = threadIdx.x;
    const int wid = tid >> 5, lane = tid & 31;
    const int gr = lane >> 2, q = lane & 3;
    const int row0 = blockIdx.y * 128, col0 = blockIdx.x * 128;
    const int warp_m = (wid & 1) * 64, warp_n = (wid >> 1) * 32;

    float* Cout = C ? (C + (size_t)blockIdx.z * partStride) : nullptr;

    const fp16* tbA = A + (size_t)row0 * K;
    const fp16* tbB = B + (size_t)col0 * K;

    float acc[4][4][4];
#pragma unroll
    for (int i = 0; i < 4; i++)
#pragma unroll
        for (int j = 0; j < 4; j++)
#pragma unroll
            for (int r = 0; r < 4; r++) acc[i][j][r] = 0.f;

    auto load_stage = [&](int c, int s) {
        int koff = (kstart_ch + c) << 5;
#pragma unroll
        for (int i = 0; i < 4; i++) {
            int seg = tid + 256 * i;            // 0..1023
            int buf = seg >> 9;                 // 0 = A, 1 = B
            int w   = seg & 511;
            int row = w >> 2, s4 = w & 3;
            const fp16* base = buf ? tbB : tbA;
            const fp16* g = base + (size_t)row * K + koff + s4 * 8;
            uint32_t dst = sb + (uint32_t)s * STAGE_B + (uint32_t)buf * TILE_B
                         + (uint32_t)row * ROW_BYTES + (uint32_t)s4 * 16u;
            cp_async16(dst, g);
        }
    };

    const uint32_t a_row  = (uint32_t)(lane & 15);
    const uint32_t a_koff = (uint32_t)(lane >> 4) * 16u;
    const uint32_t b_row  = (uint32_t)(((lane >> 4) << 3) + (lane & 7));
    const uint32_t b_koff = (uint32_t)((lane >> 3) & 1) * 16u;

    load_stage(0, 0);
    CP_COMMIT();
    if (kch > 1) { load_stage(1, 1); CP_COMMIT(); }

    int snext = 2;
    for (int c = 0; c < kch; c++) {
        if (c + 1 < kch) CP_WAIT1();
        else             CP_WAIT0();
        __syncthreads();
        if (c + 2 < kch) {
            load_stage(c + 2, snext);
            CP_COMMIT();
        }

        const uint32_t st = sb + (uint32_t)(c - (c / NSTAGE) * NSTAGE) * STAGE_B;
        const uint32_t sA = st;
        const uint32_t sB = st + TILE_B;
        snext = snext + 1 == NSTAGE ? 0 : snext + 1;

#pragma unroll
        for (int kc = 0; kc < 2; kc++) {
            uint32_t aH[4][4], bH[8];
#pragma unroll
            for (int mt = 0; mt < 4; mt++) {
                uint32_t roff = ((uint32_t)(warp_m + mt * 16) + a_row) * ROW_BYTES
                              + kc * 32u + a_koff;
                ldsm_x4(aH[mt], sA + roff);
            }
            {
                uint32_t r0 = ((uint32_t)warp_n + b_row) * ROW_BYTES
                            + kc * 32u + b_koff;
                uint32_t r1 = r0 + 16u * ROW_BYTES;
                ldsm_x4(bH + 0, sB + r0);
                ldsm_x4(bH + 4, sB + r1);
            }
#pragma unroll
            for (int mt = 0; mt < 4; mt++)
#pragma unroll
                for (int nt = 0; nt < 4; nt++)
                    mma16816(acc[mt][nt], aH[mt], bH + nt * 2);
        }
    }

    // ---------------- epilogue ----------------
#pragma unroll
    for (int mt = 0; mt < 4; mt++) {
#pragma unroll
        for (int nt = 0; nt < 4; nt++) {
            int rg = row0 + warp_m + mt * 16 + gr;
            int cg = col0 + warp_n + nt * 8 + 2 * q;
            float* cc = acc[mt][nt];
#pragma unroll
            for (int half = 0; half < 2; half++) {
                int r = rg + half * 8;
                float v0 = cc[half * 2 + 0];
                float v1 = cc[half * 2 + 1];
                if (bias) {
                    if (act == 2) { float bb = bias[r]; v0 += bb; v1 += bb; }
                    else          { v0 += bias[cg]; v1 += bias[cg + 1]; }
                }
                if (act) {
                    v0 = (v0 > 20.f) ? v0 : log1pf(expf(v0));
                    v1 = (v1 > 20.f) ? v1 : log1pf(expf(v1));
                }
                if (cg + 1 < Nc) {
                    if (Ch) {
                        *reinterpret_cast<__half2*>(&Ch[(size_t)r * ldc + cg]) =
                            __floats2half2_rn(v0, v1);
                    } else {
                        *reinterpret_cast<float2*>(&Cout[(size_t)r * ldc + cg]) =
                            make_float2(v0, v1);
                    }
                } else if (cg < Nc) {
                    if (Ch) Ch[(size_t)r * ldc + cg] = __float2half_rn(v0);
                    else    Cout[(size_t)r * ldc + cg] = v0;
                }
            }
        }
    }
}

// -------- split-K reduce for xproj GEMM: sum partials, write xdbc + xdh ----
__global__ void reduce3_kernel(const float* __restrict__ part,
                               float* __restrict__ xdbc,
                               fp16* __restrict__ xdh)
{
    int i = blockIdx.x * 256 + threadIdx.x;
    if (i >= NROWS * XPROJ_N) return;
    int r = i / XPROJ_N, c = i - r * XPROJ_N;
    const size_t ps = (size_t)NROWS * XPROJ_NPAD;
    float v = 0.f;
#pragma unroll
    for (int p = 0; p < KSPLIT3; p++)
        v += part[p * ps + (size_t)r * XPROJ_NPAD + c];
    xdbc[(size_t)r * XPROJ_N + c] = v;
    if (c < DT_RANK)
        xdh[(size_t)r * DT_RANK + c] = __float2half_rn(v);
}

// ======= weight transpose -> fp16 [Npad, K] ================================
__global__ void wsplit_kernel(const float* __restrict__ W,
                              fp16* __restrict__ Th,
                              int K, int N, int Npad)
{
    __shared__ float tile[32][33];
    int kb = blockIdx.y * 32, nb = blockIdx.x * 32;
    int tx = threadIdx.x, ty = threadIdx.y;
#pragma unroll
    for (int i = ty; i < 32; i += 8) {
        int k = kb + i, n = nb + tx;
        tile[i][tx] = (k < K && n < N) ? W[(size_t)k * N + n] : 0.f;
    }
    __syncthreads();
#pragma unroll
    for (int i = ty; i < 32; i += 8) {
        int n = nb + i, k = kb + tx;
        if (n < Npad && k < K)
            Th[(size_t)n * K + k] = __float2half_rn(tile[tx][i]);
    }
}

// ---------------- elementwise fp32 -> fp16 convert (8 per thread) ----------
__global__ void fconv_kernel(const float* __restrict__ X,
                             fp16* __restrict__ H, int n)
{
    int i = (blockIdx.x * blockDim.x + threadIdx.x) * 8;
    if (i >= n) return;
    float4 a = *reinterpret_cast<const float4*>(X + i);
    float4 b = *reinterpret_cast<const float4*>(X + i + 4);
    __half2 h0 = __floats2half2_rn(a.x, a.y);
    __half2 h1 = __floats2half2_rn(a.z, a.w);
    __half2 h2 = __floats2half2_rn(b.x, b.y);
    __half2 h3 = __floats2half2_rn(b.z, b.w);
    uint4 out;
    out.x = *reinterpret_cast<uint32_t*>(&h0);
    out.y = *reinterpret_cast<uint32_t*>(&h1);
    out.z = *reinterpret_cast<uint32_t*>(&h2);
    out.w = *reinterpret_cast<uint32_t*>(&h3);
    *reinterpret_cast<uint4*>(H + i) = out;
}

// ====== fused causal conv + SiLU + transposes (one pass over xz) ===========
__global__ void convT_kernel(const float* __restrict__ xz,
                             const float* __restrict__ w_conv,
                             const float* __restrict__ b_conv,
                             fp16* __restrict__ xcT, fp16* __restrict__ zT,
                             fp16* __restrict__ xch)
{
    __shared__ float tin[35][33];
    __shared__ float tout[32][33];
    __shared__ float tz[32][33];
    const int b  = blockIdx.z;
    const int l0 = blockIdx.x * 32, d0 = blockIdx.y * 32;
    const int tx = threadIdx.x, ty = threadIdx.y;     // 32 x 8

    for (int j = ty; j < 35; j += 8) {
        int l = l0 - 3 + j;
        tin[j][tx] = (l >= 0) ? xz[(size_t)(b * SEQ + l) * (2 * D_INNER) + d0 + tx]
                              : 0.f;
    }
#pragma unroll
    for (int i = ty; i < 32; i += 8)
        tz[i][tx] = xz[(size_t)(b * SEQ + l0 + i) * (2 * D_INNER) + D_INNER + d0 + tx];
    __syncthreads();

    const float w0 = w_conv[(d0 + tx) * D_CONV + 0];
    const float w1 = w_conv[(d0 + tx) * D_CONV + 1];
    const float w2 = w_conv[(d0 + tx) * D_CONV + 2];
    const float w3 = w_conv[(d0 + tx) * D_CONV + 3];
    const float bc = b_conv[d0 + tx];
#pragma unroll
    for (int i = ty; i < 32; i += 8) {
        float acc = bc + tin[i][tx] * w0 + tin[i + 1][tx] * w1
                       + tin[i + 2][tx] * w2 + tin[i + 3][tx] * w3;
        float s = 1.f / (1.f + __expf(-acc));
        float v = acc * s;
        tout[i][tx] = v;
        xch[(size_t)(b * SEQ + l0 + i) * D_INNER + d0 + tx] = __float2half_rn(v);
    }
    __syncthreads();
#pragma unroll
    for (int i = ty; i < 32; i += 8) {
        size_t o = (size_t)(d0 + i) * NROWS + b * SEQ + l0 + tx;
        xcT[o] = __float2half_rn(tout[tx][i]);
        zT[o]  = __float2half_rn(tz[tx][i]);
    }
}

// ========== fused chunked selective scan, SCH=4 channels per block =========
// block = (b, d0..d0+3); 256 threads = 16 chunks x 16 states.
// Bn/Cn loads from xdbc shared across the 4 channels.
__global__ void __launch_bounds__(256)
scan_fused_kernel(const fp16* __restrict__ dtT, const fp16* __restrict__ xcT,
                  const fp16* __restrict__ zT,  const float* __restrict__ xdbc,
                  const float* __restrict__ A_log, const float* __restrict__ Dv,
                  fp16* __restrict__ yh)
{
    __shared__ float sP[NCH][SCH][D_STATE];
    __shared__ float sS[NCH][SCH][D_STATE];

    const int blk = blockIdx.x;            // b * (D_INNER/SCH) + dgrp
    const int dgrp = blk & (D_INNER / SCH - 1);
    const int b    = blk >> 9;             // / (D_INNER/SCH) = 512
    const int d0   = dgrp * SCH;
    const int t = threadIdx.x;
    const int n = t & 15, c = t >> 4;

    float An[SCH], Dd[SCH];
#pragma unroll
    for (int ch = 0; ch < SCH; ch++) {
        An[ch] = -expf(A_log[(d0 + ch) * D_STATE + n]);
        Dd[ch] = Dv[d0 + ch];
    }

    const size_t base = (size_t)d0 * NROWS + b * SEQ + c * CHT;
    const fp16* dtp = dtT + base;
    const fp16* xcp = xcT + base;
    const fp16* zp  = zT  + base;
    const float* bc0 = xdbc + ((size_t)(b * SEQ + c * CHT)) * XPROJ_N;

    // ---- Phase A: per-chunk affine coefficients (4 channels) ----
    {
        const float* bc = bc0;
        float P[SCH], S[SCH];
#pragma unroll
        for (int ch = 0; ch < SCH; ch++) { P[ch] = 1.f; S[ch] = 0.f; }
        for (int l0 = 0; l0 < CHT; l0 += 4) {
            float dt4[SCH][4], xc4[SCH][4];
#pragma unroll
            for (int ch = 0; ch < SCH; ch++) {
                load4h(dtp + (size_t)ch * NROWS + l0, dt4[ch]);
                load4h(xcp + (size_t)ch * NROWS + l0, xc4[ch]);
            }
#pragma unroll
            for (int j = 0; j < 4; j++) {
                float Bn = bc[DT_RANK + n];
#pragma unroll
                for (int ch = 0; ch < SCH; ch++) {
                    float a = __expf(dt4[ch][j] * An[ch]);
                    S[ch] = fmaf(a, S[ch], dt4[ch][j] * xc4[ch][j] * Bn);
                    P[ch] *= a;
                }
                bc += XPROJ_N;
            }
        }
#pragma unroll
        for (int ch = 0; ch < SCH; ch++) { sP[c][ch][n] = P[ch]; sS[c][ch][n] = S[ch]; }
    }
    __syncthreads();

    // ---- Phase B: per-thread prefix over earlier chunks ----
    float h[SCH];
#pragma unroll
    for (int ch = 0; ch < SCH; ch++) h[ch] = 0.f;
    for (int cc = 0; cc < c; cc++)
#pragma unroll
        for (int ch = 0; ch < SCH; ch++)
            h[ch] = fmaf(sP[cc][ch][n], h[ch], sS[cc][ch][n]);

    // ---- Phase C: replay, reduce y (4 channels), gate, vector store ----
    const float* bc = bc0;
    size_t yrow = (size_t)(b * SEQ + c * CHT) * D_INNER + d0;

    for (int l0 = 0; l0 < CHT; l0 += 4) {
        float dt4[SCH][4], xc4[SCH][4];
#pragma unroll
        for (int ch = 0; ch < SCH; ch++) {
            load4h(dtp + (size_t)ch * NROWS + l0, dt4[ch]);
            load4h(xcp + (size_t)ch * NROWS + l0, xc4[ch]);
        }
#pragma unroll
        for (int j = 0; j < 4; j++) {
            float Bn = bc[DT_RANK + n];
            float Cn = bc[DT_RANK + D_STATE + n];
            float part[SCH];
#pragma unroll
            for (int ch = 0; ch < SCH; ch++) {
                float a = __expf(dt4[ch][j] * An[ch]);
                h[ch] = fmaf(a, h[ch], dt4[ch][j] * xc4[ch][j] * Bn);
                part[ch] = Cn * h[ch];
            }
#pragma unroll
            for (int ch = 0; ch < SCH; ch++) {
                part[ch] += __shfl_xor_sync(0xffffffffu, part[ch], 1);
                part[ch] += __shfl_xor_sync(0xffffffffu, part[ch], 2);
                part[ch] += __shfl_xor_sync(0xffffffffu, part[ch], 4);
                part[ch] += __shfl_xor_sync(0xffffffffu, part[ch], 8);
            }
            if (n == 0) {
                __half2 o01, o23;
                {
                    float z0 = __half2float(zp[l0 + j]);
                    float z1 = __half2float(zp[(size_t)1 * NROWS + l0 + j]);
                    float g0 = z0 / (1.f + __expf(-z0));
                    float g1 = z1 / (1.f + __expf(-z1));
                    o01 = __floats2half2_rn(
                        (part[0] + xc4[0][j] * Dd[0]) * g0,
                        (part[1] + xc4[1][j] * Dd[1]) * g1);
                    float z2 = __half2float(zp[(size_t)2 * NROWS + l0 + j]);
                    float z3 = __half2float(zp[(size_t)3 * NROWS + l0 + j]);
                    float g2 = z2 / (1.f + __expf(-z2));
                    float g3 = z3 / (1.f + __expf(-z3));
                    o23 = __floats2half2_rn(
                        (part[2] + xc4[2][j] * Dd[2]) * g2,
                        (part[3] + xc4[3][j] * Dd[3]) * g3);
                }
                uint2 ov;
                ov.x = *reinterpret_cast<uint32_t*>(&o01);
                ov.y = *reinterpret_cast<uint32_t*>(&o23);
                *reinterpret_cast<uint2*>(&yh[yrow]) = ov;
            }
            bc += XPROJ_N;
            yrow += D_INNER;
        }
    }
}

// ---------------- launcher -------------------------------------------------
extern "C" void kernel_launch(void* const* d_in, const int* in_sizes, int n_in,
                              void* d_out, int out_size)
{
    const float* x       = (const float*)d_in[0];
    const float* w_in    = (const float*)d_in[1];
    const float* w_conv  = (const float*)d_in[2];
    const float* b_conv  = (const float*)d_in[3];
    const float* w_xproj = (const float*)d_in[4];
    const float* w_dt    = (const float*)d_in[5];
    const float* b_dt    = (const float*)d_in[6];
    const float* A_log   = (const float*)d_in[7];
    const float* Dv      = (const float*)d_in[8];
    const float* w_out   = (const float*)d_in[9];
    float* out = (float*)d_out;

    float *xz, *xdbc, *part;
    fp16 *dtT, *xcT, *zT;
    fp16 *xh, *xch, *xdh, *yh;
    fp16 *winT, *woutT, *wxT, *wdtT;
    cudaGetSymbolAddress((void**)&xz,    g_xz);
    cudaGetSymbolAddress((void**)&xdbc,  g_xdbc);
    cudaGetSymbolAddress((void**)&part,  g_part);
    cudaGetSymbolAddress((void**)&dtT,   g_dtT);
    cudaGetSymbolAddress((void**)&xcT,   g_xcT);
    cudaGetSymbolAddress((void**)&zT,    g_zT);
    cudaGetSymbolAddress((void**)&xh,    g_xh);
    cudaGetSymbolAddress((void**)&xch,   g_xconvh);
    cudaGetSymbolAddress((void**)&xdh,   g_xdh);
    cudaGetSymbolAddress((void**)&yh,    g_yh);
    cudaGetSymbolAddress((void**)&winT,  g_winT);
    cudaGetSymbolAddress((void**)&woutT, g_woutT);
    cudaGetSymbolAddress((void**)&wxT,   g_wxT);
    cudaGetSymbolAddress((void**)&wdtT,  g_wdtT);

    cudaFuncSetAttribute(gemm1p, cudaFuncAttributeMaxDynamicSharedMemorySize,
                         SMEM_TOT);

    dim3 tb(32, 8);
    fconv_kernel<<<(NROWS * D_MODEL / 8 + 255) / 256, 256>>>(x, xh, NROWS * D_MODEL);
    wsplit_kernel<<<dim3(4096 / 32, 1024 / 32), tb>>>(w_in, winT,
                                                      D_MODEL, 2 * D_INNER, 2 * D_INNER);
    // 2: xz = x @ w_in          M=4096 N=4096 K=1024
    gemm1p<<<dim3(32, 32, 1), 256, SMEM_TOT>>>(xh, winT, xz, nullptr,
                                               2 * D_INNER, D_MODEL, 0,
                                               D_MODEL / 32, 2 * D_INNER,
                                               nullptr, 0, 0);
    // 3: fused conv + silu + transposes
    convT_kernel<<<dim3(SEQ / 32, D_INNER / 32, B_SZ), tb>>>(
        xz, w_conv, b_conv, xcT, zT, xch);
    // remaining weight preps
    wsplit_kernel<<<dim3(XPROJ_NPAD / 32, 2048 / 32), tb>>>(w_xproj, wxT,
                                                            D_INNER, XPROJ_N, XPROJ_NPAD);
    wsplit_kernel<<<dim3(2048 / 32, 64 / 32), tb>>>(w_dt, wdtT,
                                                    DT_RANK, D_INNER, D_INNER);
    wsplit_kernel<<<dim3(1024 / 32, 2048 / 32), tb>>>(w_out, woutT,
                                                      D_INNER, D_MODEL, D_MODEL);
    // xproj: split-K=8 into partials, then reduce (+ dt-rank fp16)
    gemm1p<<<dim3(1, 32, KSPLIT3), 256, SMEM_TOT>>>(
        xch, wxT, part, nullptr,
        XPROJ_NPAD, D_INNER, 0, (D_INNER / 32) / KSPLIT3, XPROJ_NPAD,
        nullptr, 0, (size_t)NROWS * XPROJ_NPAD);
    reduce3_kernel<<<(NROWS * XPROJ_N + 255) / 256, 256>>>(part, xdbc, xdh);
    // dtT[d][b*L+l] = softplus(wdtT @ xdbc_dt^T + b_dt[d])  (fp16 output)
    gemm1p<<<dim3(NROWS / 128, D_INNER / 128, 1), 256, SMEM_TOT>>>(
        wdtT, xdh, nullptr, dtT,
        NROWS, DT_RANK, 0, DT_RANK / 32, NROWS,
        b_dt, 2, 0);
    // fused chunked scan, 4 channels per block
    scan_fused_kernel<<<B_SZ * D_INNER / SCH, 256>>>(
        dtT, xcT, zT, xdbc, A_log, Dv, yh);
    // out = y @ w_out                  M=4096 N=1024 K=2048
    gemm1p<<<dim3(8, 32, 1), 256, SMEM_TOT>>>(yh, woutT, out, nullptr,
                                              D_MODEL, D_INNER, 0,
                                              D_INNER / 32, D_MODEL,
                                              nullptr, 0, 0);
}